// round 1
// baseline (speedup 1.0000x reference)
#include <cuda_runtime.h>
#include <cuda_bf16.h>
#include <math.h>

// Problem constants (fixed by setup_inputs)
#define NN 50000
#define EE 400000
#define RR 1000
#define FF 128
#define K1 1000
#define PX 64      // proxy rows
#define CC 256     // concat dim = F*(DEPTH+1)

// ---------------- scratch (device globals; no allocation allowed) ----------------
__device__ float g_nf0[(size_t)NN * FF];
__device__ float g_nf1[(size_t)NN * FF];
__device__ float g_relnsq[RR];
__device__ float g_reldot[RR * 2];
__device__ float g_invp[PX];
__device__ int   g_rb[NN];
__device__ int   g_re[NN];

__inline__ __device__ float warp_sum(float v) {
    #pragma unroll
    for (int o = 16; o; o >>= 1) v += __shfl_xor_sync(0xffffffffu, v, o);
    return v;
}
__inline__ __device__ float warp_max(float v) {
    #pragma unroll
    for (int o = 16; o; o >>= 1) v = fmaxf(v, __shfl_xor_sync(0xffffffffu, v, o));
    return v;
}

// ---------------- Kernel A: per-relation norms & attn dots, proxy inv-norms ----------------
// grid = RR + PX blocks, 128 threads
__global__ void prep_kernel(const float* __restrict__ rel_emb,
                            const float* __restrict__ attn,
                            const float* __restrict__ proxy) {
    int b = blockIdx.x;
    int t = threadIdx.x;
    int lane = t & 31, w = t >> 5;
    __shared__ float sh[3][4];

    if (b < RR) {
        float v  = rel_emb[b * FF + t];
        float a0 = attn[t];
        float a1 = attn[FF + t];
        float nsq = warp_sum(v * v);
        float d0  = warp_sum(v * a0);
        float d1  = warp_sum(v * a1);
        if (lane == 0) { sh[0][w] = nsq; sh[1][w] = d0; sh[2][w] = d1; }
        __syncthreads();
        if (t == 0) {
            g_relnsq[b]       = sh[0][0] + sh[0][1] + sh[0][2] + sh[0][3];
            g_reldot[2*b]     = sh[1][0] + sh[1][1] + sh[1][2] + sh[1][3];
            g_reldot[2*b + 1] = sh[2][0] + sh[2][1] + sh[2][2] + sh[2][3];
        }
    } else {
        int k = b - RR;
        float p0 = proxy[k * CC + t];
        float p1 = proxy[k * CC + 128 + t];
        float s = warp_sum(p0 * p0 + p1 * p1);
        if (lane == 0) sh[0][w] = s;
        __syncthreads();
        if (t == 0) {
            float tot = sh[0][0] + sh[0][1] + sh[0][2] + sh[0][3];
            g_invp[k] = 1.0f / sqrtf(fmaxf(tot, 1e-12f));
        }
    }
}

// ---------------- Kernel B: row segment bounds (adj sorted by row) ----------------
__global__ void zero_bounds_kernel() {
    int i = blockIdx.x * blockDim.x + threadIdx.x;
    if (i < NN) { g_rb[i] = 0; g_re[i] = 0; }
}
__global__ void detect_bounds_kernel(const int* __restrict__ adj) {
    int e = blockIdx.x * blockDim.x + threadIdx.x;
    if (e >= EE) return;
    int r = adj[2 * e];
    if (e == 0 || adj[2 * (e - 1)] != r) g_rb[r] = e;
    if (e == EE - 1 || adj[2 * (e + 1)] != r) g_re[r] = e + 1;
}

// ---------------- Kernel C: per-row softmax + reflected-neighbor aggregation ----------------
// one warp per row; 256 threads/block
__global__ void agg_kernel(const float* __restrict__ feats,
                           const float* __restrict__ rel_emb,
                           const float* __restrict__ sv,
                           const int* __restrict__ adj,
                           const int* __restrict__ si) {
    int gw = (blockIdx.x * blockDim.x + threadIdx.x) >> 5;
    int lane = threadIdx.x & 31;
    if (gw >= NN) return;

    int e0 = g_rb[gw], e1 = g_re[gw];
    float4* o0 = reinterpret_cast<float4*>(g_nf0 + (size_t)gw * FF);
    float4* o1 = reinterpret_cast<float4*>(g_nf1 + (size_t)gw * FF);

    if (e0 >= e1) {
        float4 z = make_float4(0.f, 0.f, 0.f, 0.f);
        o0[lane] = z; o1[lane] = z;
        return;
    }

    const float2* rd2 = reinterpret_cast<const float2*>(g_reldot);

    // pass 1: per-head max logit over the segment
    float m0 = -1e30f, m1 = -1e30f;
    for (int e = e0; e < e1; e++) {
        float s = sv[e];
        int r = si[2 * e + 1];
        float2 rd = rd2[r];
        m0 = fmaxf(m0, s * rd.x);
        m1 = fmaxf(m1, s * rd.y);
    }

    // pass 2: accumulate exp-weighted reflected neighbors
    float4 a0 = make_float4(0.f, 0.f, 0.f, 0.f);
    float4 a1 = make_float4(0.f, 0.f, 0.f, 0.f);
    float s0 = 0.f, s1 = 0.f;
    for (int e = e0; e < e1; e++) {
        int   col = adj[2 * e + 1];
        int   r   = si[2 * e + 1];
        float s   = sv[e];
        float2 rd = rd2[r];
        float f = s / sqrtf(fmaxf(s * s * g_relnsq[r], 1e-12f));

        float4 u = reinterpret_cast<const float4*>(rel_emb + (size_t)r * FF)[lane];
        u.x *= f; u.y *= f; u.z *= f; u.w *= f;
        float4 x = __ldg(reinterpret_cast<const float4*>(feats + (size_t)col * FF) + lane);

        float d = x.x * u.x + x.y * u.y + x.z * u.z + x.w * u.w;
        d = warp_sum(d);
        float t2 = 2.f * d;
        float4 y;
        y.x = x.x - t2 * u.x; y.y = x.y - t2 * u.y;
        y.z = x.z - t2 * u.z; y.w = x.w - t2 * u.w;

        float w0 = expf(s * rd.x - m0);
        float w1 = expf(s * rd.y - m1);
        s0 += w0; s1 += w1;
        a0.x += w0 * y.x; a0.y += w0 * y.y; a0.z += w0 * y.z; a0.w += w0 * y.w;
        a1.x += w1 * y.x; a1.y += w1 * y.y; a1.z += w1 * y.z; a1.w += w1 * y.w;
    }
    float i0 = 1.f / s0, i1 = 1.f / s1;
    a0.x *= i0; a0.y *= i0; a0.z *= i0; a0.w *= i0;
    a1.x *= i1; a1.y *= i1; a1.z *= i1; a1.w *= i1;
    o0[lane] = a0;
    o1[lane] = a1;
}

// ---------------- Kernel E: fused concat + l2norm + proxy softmax + pf + gate + blend --------
#define TILE 32
#define PP 257  // proxy shared pitch (bank-conflict-free)
#define SMEM_FLOATS (PX * PP + TILE * CC + TILE * CC + TILE * PX + TILE)

__global__ __launch_bounds__(256) void final_kernel(const float* __restrict__ feats,
                                                    const float* __restrict__ proxy,
                                                    const float* __restrict__ W,
                                                    const int* __restrict__ neigh,
                                                    float* __restrict__ out) {
    extern __shared__ float sm[];
    float* Psh  = sm;                       // 64 x 257
    float* Osh  = Psh + PX * PP;            // 32 x 256
    float* PFsh = Osh + TILE * CC;          // 32 x 256
    float* ATT  = PFsh + TILE * CC;         // 32 x 64
    float* INVN = ATT + TILE * PX;          // 32

    int tid = threadIdx.x;
    int lane = tid & 31, w = tid >> 5;
    int base = blockIdx.x * TILE;

    // load proxy (raw) into padded shared
    for (int idx = tid; idx < PX * CC; idx += 256) {
        Psh[(idx >> 8) * PP + (idx & 255)] = proxy[idx];
    }
    // build O tile: concat(features, 0.5*(nf0 + nf1-swapped))
    for (int rr = 0; rr < TILE; rr++) {
        int n = base + rr;
        float v = 0.f;
        if (n < NN) {
            if (tid < 128) {
                v = feats[(size_t)n * FF + tid];
            } else {
                int m = (n < K1) ? neigh[n] : n;
                int jj = tid - 128;
                v = 0.5f * (g_nf0[(size_t)n * FF + jj] + g_nf1[(size_t)m * FF + jj]);
            }
        }
        Osh[rr * CC + tid] = v;
    }
    __syncthreads();

    // row inverse norms (warp w owns rows 4w..4w+3)
    for (int q = 0; q < 4; q++) {
        int r = w * 4 + q;
        float s = 0.f;
        #pragma unroll
        for (int m = 0; m < 8; m++) {
            float v = Osh[r * CC + lane + 32 * m];
            s += v * v;
        }
        s = warp_sum(s);
        if (lane == 0) INVN[r] = 1.f / sqrtf(fmaxf(s, 1e-12f));
    }
    __syncthreads();

    // proxy attention logits + softmax (lane handles k=lane and k=lane+32)
    float ipa = g_invp[lane];
    float ipb = g_invp[lane + 32];
    for (int q = 0; q < 4; q++) {
        int r = w * 4 + q;
        const float* orow = Osh + r * CC;
        const float* p0 = Psh + lane * PP;
        const float* p1 = Psh + (lane + 32) * PP;
        float d0 = 0.f, d1 = 0.f;
        #pragma unroll 4
        for (int j = 0; j < CC; j++) {
            float o = orow[j];
            d0 += o * p0[j];
            d1 += o * p1[j];
        }
        float invn = INVN[r];
        float l0 = d0 * invn * ipa;
        float l1 = d1 * invn * ipb;
        float mx = warp_max(fmaxf(l0, l1));
        float e0v = expf(l0 - mx);
        float e1v = expf(l1 - mx);
        float s = warp_sum(e0v + e1v);
        float inv = 1.f / s;
        ATT[r * PX + lane]      = e0v * inv;
        ATT[r * PX + lane + 32] = e1v * inv;
    }
    __syncthreads();

    // proxy_feature = O - ATT @ proxy
    for (int rr = 0; rr < TILE; rr++) {
        float acc = Osh[rr * CC + tid];
        const float* arow = ATT + rr * PX;
        #pragma unroll 8
        for (int k = 0; k < PX; k++) acc -= arow[k] * Psh[k * PP + tid];
        PFsh[rr * CC + tid] = acc;
    }
    __syncthreads();

    // gate = sigmoid(PF @ W); result = g*O + (1-g)*PF
    // thread tile: 4 rows (r0..r0+3) x 8 cols (j0..j0+7)
    int j0 = lane * 8;
    int r0 = w * 4;
    float acc[4][8];
    #pragma unroll
    for (int q = 0; q < 4; q++)
        #pragma unroll
        for (int c = 0; c < 8; c++) acc[q][c] = 0.f;

    for (int i = 0; i < CC; i++) {
        float4 wa = __ldg(reinterpret_cast<const float4*>(W + (size_t)i * CC + j0));
        float4 wb = __ldg(reinterpret_cast<const float4*>(W + (size_t)i * CC + j0 + 4));
        float p[4];
        #pragma unroll
        for (int q = 0; q < 4; q++) p[q] = PFsh[(r0 + q) * CC + i];
        #pragma unroll
        for (int q = 0; q < 4; q++) {
            acc[q][0] += p[q] * wa.x; acc[q][1] += p[q] * wa.y;
            acc[q][2] += p[q] * wa.z; acc[q][3] += p[q] * wa.w;
            acc[q][4] += p[q] * wb.x; acc[q][5] += p[q] * wb.y;
            acc[q][6] += p[q] * wb.z; acc[q][7] += p[q] * wb.w;
        }
    }

    #pragma unroll
    for (int q = 0; q < 4; q++) {
        int r = r0 + q;
        int n = base + r;
        if (n >= NN) continue;
        float res[8];
        #pragma unroll
        for (int c = 0; c < 8; c++) {
            float z = acc[q][c];
            float g = 1.f / (1.f + expf(-z));
            float o  = Osh[r * CC + j0 + c];
            float pf = PFsh[r * CC + j0 + c];
            res[c] = g * o + (1.f - g) * pf;
        }
        float4* dst = reinterpret_cast<float4*>(out + (size_t)n * CC + j0);
        dst[0] = make_float4(res[0], res[1], res[2], res[3]);
        dst[1] = make_float4(res[4], res[5], res[6], res[7]);
    }
}

// ---------------- launch ----------------
extern "C" void kernel_launch(void* const* d_in, const int* in_sizes, int n_in,
                              void* d_out, int out_size) {
    const float* features  = (const float*)d_in[0];
    const float* rel_emb   = (const float*)d_in[1];
    const float* sparse_v  = (const float*)d_in[2];
    const float* attn_k    = (const float*)d_in[3];
    const float* proxy     = (const float*)d_in[4];
    const float* gate_k    = (const float*)d_in[5];
    const int*   adj       = (const int*)d_in[6];
    const int*   sparse_i  = (const int*)d_in[7];
    const int*   neigh     = (const int*)d_in[9];
    float* out = (float*)d_out;

    // A: per-relation + proxy precompute
    prep_kernel<<<RR + PX, 128>>>(rel_emb, attn_k, proxy);

    // B: segment bounds
    zero_bounds_kernel<<<(NN + 255) / 256, 256>>>();
    detect_bounds_kernel<<<(EE + 255) / 256, 256>>>(adj);

    // C: edge aggregation (1 warp / row)
    agg_kernel<<<(NN * 32 + 255) / 256, 256>>>(features, rel_emb, sparse_v, adj, sparse_i);

    // E: fused tail
    size_t smem = (size_t)SMEM_FLOATS * sizeof(float);
    cudaFuncSetAttribute(final_kernel, cudaFuncAttributeMaxDynamicSharedMemorySize, (int)smem);
    final_kernel<<<(NN + TILE - 1) / TILE, 256, smem>>>(features, proxy, gate_k, neigh, out);
}

// round 2
// speedup vs baseline: 1.4126x; 1.4126x over previous
#include <cuda_runtime.h>
#include <cuda_bf16.h>
#include <math.h>

// Problem constants (fixed by setup_inputs)
#define NN 50000
#define EE 400000
#define RR 1000
#define FF 128
#define K1 1000
#define PX 64      // proxy rows
#define CC 256     // concat dim = F*(DEPTH+1)

// ---------------- scratch (device globals; no allocation allowed) ----------------
__device__ float g_nf0[(size_t)NN * FF];
__device__ float g_nf1[(size_t)NN * FF];
__device__ float g_relnsq[RR];
__device__ float g_reldot[RR * 2];
__device__ float g_invp[PX];
__device__ int   g_rb[NN];
__device__ int   g_re[NN];

__inline__ __device__ float warp_sum(float v) {
    #pragma unroll
    for (int o = 16; o; o >>= 1) v += __shfl_xor_sync(0xffffffffu, v, o);
    return v;
}
__inline__ __device__ float warp_max(float v) {
    #pragma unroll
    for (int o = 16; o; o >>= 1) v = fmaxf(v, __shfl_xor_sync(0xffffffffu, v, o));
    return v;
}

// ---------------- Kernel A: per-relation norms & attn dots, proxy inv-norms ----------------
__global__ void prep_kernel(const float* __restrict__ rel_emb,
                            const float* __restrict__ attn,
                            const float* __restrict__ proxy) {
    int b = blockIdx.x;
    int t = threadIdx.x;
    int lane = t & 31, w = t >> 5;
    __shared__ float sh[3][4];

    if (b < RR) {
        float v  = rel_emb[b * FF + t];
        float a0 = attn[t];
        float a1 = attn[FF + t];
        float nsq = warp_sum(v * v);
        float d0  = warp_sum(v * a0);
        float d1  = warp_sum(v * a1);
        if (lane == 0) { sh[0][w] = nsq; sh[1][w] = d0; sh[2][w] = d1; }
        __syncthreads();
        if (t == 0) {
            g_relnsq[b]       = sh[0][0] + sh[0][1] + sh[0][2] + sh[0][3];
            g_reldot[2*b]     = sh[1][0] + sh[1][1] + sh[1][2] + sh[1][3];
            g_reldot[2*b + 1] = sh[2][0] + sh[2][1] + sh[2][2] + sh[2][3];
        }
    } else {
        int k = b - RR;
        float p0 = proxy[k * CC + t];
        float p1 = proxy[k * CC + 128 + t];
        float s = warp_sum(p0 * p0 + p1 * p1);
        if (lane == 0) sh[0][w] = s;
        __syncthreads();
        if (t == 0) {
            float tot = sh[0][0] + sh[0][1] + sh[0][2] + sh[0][3];
            g_invp[k] = 1.0f / sqrtf(fmaxf(tot, 1e-12f));
        }
    }
}

// ---------------- Kernel B: row segment bounds (adj sorted by row) ----------------
__global__ void zero_bounds_kernel() {
    int i = blockIdx.x * blockDim.x + threadIdx.x;
    if (i < NN) { g_rb[i] = 0; g_re[i] = 0; }
}
__global__ void detect_bounds_kernel(const int* __restrict__ adj) {
    int e = blockIdx.x * blockDim.x + threadIdx.x;
    if (e >= EE) return;
    int r = adj[2 * e];
    if (e == 0 || adj[2 * (e - 1)] != r) g_rb[r] = e;
    if (e == EE - 1 || adj[2 * (e + 1)] != r) g_re[r] = e + 1;
}

// ---------------- Kernel C: per-row softmax + reflected-neighbor aggregation ----------------
__global__ void agg_kernel(const float* __restrict__ feats,
                           const float* __restrict__ rel_emb,
                           const float* __restrict__ sv,
                           const int* __restrict__ adj,
                           const int* __restrict__ si) {
    int gw = (blockIdx.x * blockDim.x + threadIdx.x) >> 5;
    int lane = threadIdx.x & 31;
    if (gw >= NN) return;

    int e0 = g_rb[gw], e1 = g_re[gw];
    float4* o0 = reinterpret_cast<float4*>(g_nf0 + (size_t)gw * FF);
    float4* o1 = reinterpret_cast<float4*>(g_nf1 + (size_t)gw * FF);

    if (e0 >= e1) {
        float4 z = make_float4(0.f, 0.f, 0.f, 0.f);
        o0[lane] = z; o1[lane] = z;
        return;
    }

    const float2* rd2 = reinterpret_cast<const float2*>(g_reldot);

    // pass 1: per-head max logit over the segment
    float m0 = -1e30f, m1 = -1e30f;
    #pragma unroll 4
    for (int e = e0; e < e1; e++) {
        float s = sv[e];
        int r = si[2 * e + 1];
        float2 rd = rd2[r];
        m0 = fmaxf(m0, s * rd.x);
        m1 = fmaxf(m1, s * rd.y);
    }

    // pass 2: accumulate exp-weighted reflected neighbors
    float4 a0 = make_float4(0.f, 0.f, 0.f, 0.f);
    float4 a1 = make_float4(0.f, 0.f, 0.f, 0.f);
    float s0 = 0.f, s1 = 0.f;
    #pragma unroll 2
    for (int e = e0; e < e1; e++) {
        int   col = adj[2 * e + 1];
        int   r   = si[2 * e + 1];
        float s   = sv[e];
        float2 rd = rd2[r];
        float f = s / sqrtf(fmaxf(s * s * g_relnsq[r], 1e-12f));

        float4 u = reinterpret_cast<const float4*>(rel_emb + (size_t)r * FF)[lane];
        u.x *= f; u.y *= f; u.z *= f; u.w *= f;
        float4 x = __ldg(reinterpret_cast<const float4*>(feats + (size_t)col * FF) + lane);

        float d = x.x * u.x + x.y * u.y + x.z * u.z + x.w * u.w;
        d = warp_sum(d);
        float t2 = 2.f * d;
        float4 y;
        y.x = x.x - t2 * u.x; y.y = x.y - t2 * u.y;
        y.z = x.z - t2 * u.z; y.w = x.w - t2 * u.w;

        float w0 = expf(s * rd.x - m0);
        float w1 = expf(s * rd.y - m1);
        s0 += w0; s1 += w1;
        a0.x += w0 * y.x; a0.y += w0 * y.y; a0.z += w0 * y.z; a0.w += w0 * y.w;
        a1.x += w1 * y.x; a1.y += w1 * y.y; a1.z += w1 * y.z; a1.w += w1 * y.w;
    }
    float i0 = 1.f / s0, i1 = 1.f / s1;
    a0.x *= i0; a0.y *= i0; a0.z *= i0; a0.w *= i0;
    a1.x *= i1; a1.y *= i1; a1.z *= i1; a1.w *= i1;
    o0[lane] = a0;
    o1[lane] = a1;
}

// ---------------- Kernel E: fused tail, register-tiled ----------------
#define TILE 32
#define PP 257  // proxy shared pitch (bank-conflict-free for k-row scalar access)
#define SMEM_FLOATS (PX * PP + TILE * CC + TILE * CC + TILE * PX + TILE)

__global__ __launch_bounds__(256) void final_kernel(const float* __restrict__ feats,
                                                    const float* __restrict__ proxy,
                                                    const float* __restrict__ W,
                                                    const int* __restrict__ neigh,
                                                    float* __restrict__ out) {
    extern __shared__ float sm[];
    float* Psh  = sm;                       // 64 x 257
    float* Osh  = Psh + PX * PP;            // 32 x 256
    float* PFsh = Osh + TILE * CC;          // 32 x 256
    float* ATT  = PFsh + TILE * CC;         // 32 x 64
    float* INVN = ATT + TILE * PX;          // 32

    int tid = threadIdx.x;
    int lane = tid & 31, w = tid >> 5;
    int r0 = w * 4;
    int base = blockIdx.x * TILE;

    // load proxy (raw) into padded shared
    #pragma unroll 4
    for (int idx = tid; idx < PX * CC; idx += 256) {
        Psh[(idx >> 8) * PP + (idx & 255)] = proxy[idx];
    }
    // build O tile: concat(features, 0.5*(nf0 + nf1-swapped))
    #pragma unroll 4
    for (int rr = 0; rr < TILE; rr++) {
        int n = base + rr;
        float v = 0.f;
        if (n < NN) {
            if (tid < 128) {
                v = feats[(size_t)n * FF + tid];
            } else {
                int m = (n < K1) ? neigh[n] : n;
                int jj = tid - 128;
                v = 0.5f * (g_nf0[(size_t)n * FF + jj] + g_nf1[(size_t)m * FF + jj]);
            }
        }
        Osh[rr * CC + tid] = v;
    }
    __syncthreads();

    // row inverse norms (warp w owns rows 4w..4w+3)
    #pragma unroll
    for (int q = 0; q < 4; q++) {
        int r = r0 + q;
        float s = 0.f;
        #pragma unroll
        for (int m = 0; m < 8; m++) {
            float v = Osh[r * CC + lane + 32 * m];
            s += v * v;
        }
        s = warp_sum(s);
        if (lane == 0) INVN[r] = 1.f / sqrtf(fmaxf(s, 1e-12f));
    }
    __syncthreads();

    // ---- logits GEMM: 4 rows x 2 proxy cols per thread (k = lane, lane+32) ----
    {
        float acc0[4], acc1[4];
        #pragma unroll
        for (int q = 0; q < 4; q++) { acc0[q] = 0.f; acc1[q] = 0.f; }
        const float* p0 = Psh + lane * PP;
        const float* p1 = Psh + (lane + 32) * PP;
        #pragma unroll 4
        for (int j = 0; j < CC; j++) {
            float v0 = p0[j];
            float v1 = p1[j];
            #pragma unroll
            for (int q = 0; q < 4; q++) {
                float o = Osh[(r0 + q) * CC + j];   // broadcast
                acc0[q] += o * v0;
                acc1[q] += o * v1;
            }
        }
        float ipa = g_invp[lane];
        float ipb = g_invp[lane + 32];
        #pragma unroll
        for (int q = 0; q < 4; q++) {
            int r = r0 + q;
            float invn = INVN[r];
            float l0 = acc0[q] * invn * ipa;
            float l1 = acc1[q] * invn * ipb;
            float mx = warp_max(fmaxf(l0, l1));
            float e0v = expf(l0 - mx);
            float e1v = expf(l1 - mx);
            float s = warp_sum(e0v + e1v);
            float inv = 1.f / s;
            ATT[r * PX + lane]      = e0v * inv;
            ATT[r * PX + lane + 32] = e1v * inv;
        }
    }
    __syncthreads();

    // ---- PF GEMM: proxy_feature = O - ATT @ proxy ; 4 rows x 8 cols (j = lane+32c) ----
    {
        float acc[4][8];
        #pragma unroll
        for (int q = 0; q < 4; q++)
            #pragma unroll
            for (int c = 0; c < 8; c++) acc[q][c] = 0.f;

        #pragma unroll 2
        for (int k = 0; k < PX; k++) {
            float a[4];
            #pragma unroll
            for (int q = 0; q < 4; q++) a[q] = ATT[(r0 + q) * PX + k];  // broadcast
            float pv[8];
            #pragma unroll
            for (int c = 0; c < 8; c++) pv[c] = Psh[k * PP + lane + 32 * c];
            #pragma unroll
            for (int q = 0; q < 4; q++)
                #pragma unroll
                for (int c = 0; c < 8; c++) acc[q][c] += a[q] * pv[c];
        }
        #pragma unroll
        for (int q = 0; q < 4; q++)
            #pragma unroll
            for (int c = 0; c < 8; c++) {
                int idx = (r0 + q) * CC + lane + 32 * c;
                PFsh[idx] = Osh[idx] - acc[q][c];
            }
    }
    __syncthreads();

    // ---- gate GEMM: Z = PF @ W ; 4 rows x 8 cols (j = lane*4 + 128c), vectorized W loads ----
    {
        float acc[4][8];
        #pragma unroll
        for (int q = 0; q < 4; q++)
            #pragma unroll
            for (int c = 0; c < 8; c++) acc[q][c] = 0.f;

        #pragma unroll 2
        for (int i = 0; i < CC; i++) {
            const float4* Wv = reinterpret_cast<const float4*>(W + (size_t)i * CC);
            float4 wa = __ldg(Wv + lane);
            float4 wb = __ldg(Wv + lane + 32);
            float p[4];
            #pragma unroll
            for (int q = 0; q < 4; q++) p[q] = PFsh[(r0 + q) * CC + i];  // broadcast
            #pragma unroll
            for (int q = 0; q < 4; q++) {
                acc[q][0] += p[q] * wa.x; acc[q][1] += p[q] * wa.y;
                acc[q][2] += p[q] * wa.z; acc[q][3] += p[q] * wa.w;
                acc[q][4] += p[q] * wb.x; acc[q][5] += p[q] * wb.y;
                acc[q][6] += p[q] * wb.z; acc[q][7] += p[q] * wb.w;
            }
        }

        // blend + store: cols lane*4..+3 and lane*4+128..+131
        #pragma unroll
        for (int q = 0; q < 4; q++) {
            int r = r0 + q;
            int n = base + r;
            if (n >= NN) continue;
            const float4* Orow  = reinterpret_cast<const float4*>(Osh + r * CC);
            const float4* PFrow = reinterpret_cast<const float4*>(PFsh + r * CC);
            float4 oa = Orow[lane],      ob = Orow[lane + 32];
            float4 fa = PFrow[lane],     fb = PFrow[lane + 32];
            float4 ra, rb;
            {
                float g;
                g = 1.f / (1.f + expf(-acc[q][0])); ra.x = g * oa.x + (1.f - g) * fa.x;
                g = 1.f / (1.f + expf(-acc[q][1])); ra.y = g * oa.y + (1.f - g) * fa.y;
                g = 1.f / (1.f + expf(-acc[q][2])); ra.z = g * oa.z + (1.f - g) * fa.z;
                g = 1.f / (1.f + expf(-acc[q][3])); ra.w = g * oa.w + (1.f - g) * fa.w;
                g = 1.f / (1.f + expf(-acc[q][4])); rb.x = g * ob.x + (1.f - g) * fb.x;
                g = 1.f / (1.f + expf(-acc[q][5])); rb.y = g * ob.y + (1.f - g) * fb.y;
                g = 1.f / (1.f + expf(-acc[q][6])); rb.z = g * ob.z + (1.f - g) * fb.z;
                g = 1.f / (1.f + expf(-acc[q][7])); rb.w = g * ob.w + (1.f - g) * fb.w;
            }
            float4* dst = reinterpret_cast<float4*>(out + (size_t)n * CC);
            dst[lane]      = ra;
            dst[lane + 32] = rb;
        }
    }
}

// ---------------- launch ----------------
extern "C" void kernel_launch(void* const* d_in, const int* in_sizes, int n_in,
                              void* d_out, int out_size) {
    const float* features  = (const float*)d_in[0];
    const float* rel_emb   = (const float*)d_in[1];
    const float* sparse_v  = (const float*)d_in[2];
    const float* attn_k    = (const float*)d_in[3];
    const float* proxy     = (const float*)d_in[4];
    const float* gate_k    = (const float*)d_in[5];
    const int*   adj       = (const int*)d_in[6];
    const int*   sparse_i  = (const int*)d_in[7];
    const int*   neigh     = (const int*)d_in[9];
    float* out = (float*)d_out;

    prep_kernel<<<RR + PX, 128>>>(rel_emb, attn_k, proxy);
    zero_bounds_kernel<<<(NN + 255) / 256, 256>>>();
    detect_bounds_kernel<<<(EE + 255) / 256, 256>>>(adj);
    agg_kernel<<<(NN * 32 + 255) / 256, 256>>>(features, rel_emb, sparse_v, adj, sparse_i);

    size_t smem = (size_t)SMEM_FLOATS * sizeof(float);
    cudaFuncSetAttribute(final_kernel, cudaFuncAttributeMaxDynamicSharedMemorySize, (int)smem);
    final_kernel<<<(NN + TILE - 1) / TILE, 256, smem>>>(features, proxy, gate_k, neigh, out);
}

// round 3
// speedup vs baseline: 2.2942x; 1.6242x over previous
#include <cuda_runtime.h>
#include <cuda_bf16.h>
#include <math.h>

// Problem constants (fixed by setup_inputs)
#define NN 50000
#define EE 400000
#define RR 1000
#define FF 128
#define K1 1000
#define PX 64      // proxy rows
#define CC 256     // concat dim = F*(DEPTH+1)

// ---------------- scratch (device globals; no allocation allowed) ----------------
__device__ float g_nf0[(size_t)NN * FF];
__device__ float g_nf1[(size_t)NN * FF];
__device__ float g_relnsq[RR];
__device__ float g_reldot[RR * 2];
__device__ float g_invp[PX];
__device__ int   g_rb[NN];
__device__ int   g_re[NN];

__inline__ __device__ float warp_sum(float v) {
    #pragma unroll
    for (int o = 16; o; o >>= 1) v += __shfl_xor_sync(0xffffffffu, v, o);
    return v;
}
__inline__ __device__ float warp_max(float v) {
    #pragma unroll
    for (int o = 16; o; o >>= 1) v = fmaxf(v, __shfl_xor_sync(0xffffffffu, v, o));
    return v;
}

// ---------------- Kernel A: per-relation norms & attn dots, proxy inv-norms ----------------
__global__ void prep_kernel(const float* __restrict__ rel_emb,
                            const float* __restrict__ attn,
                            const float* __restrict__ proxy) {
    int b = blockIdx.x;
    int t = threadIdx.x;
    int lane = t & 31, w = t >> 5;
    __shared__ float sh[3][4];

    if (b < RR) {
        float v  = rel_emb[b * FF + t];
        float a0 = attn[t];
        float a1 = attn[FF + t];
        float nsq = warp_sum(v * v);
        float d0  = warp_sum(v * a0);
        float d1  = warp_sum(v * a1);
        if (lane == 0) { sh[0][w] = nsq; sh[1][w] = d0; sh[2][w] = d1; }
        __syncthreads();
        if (t == 0) {
            g_relnsq[b]       = sh[0][0] + sh[0][1] + sh[0][2] + sh[0][3];
            g_reldot[2*b]     = sh[1][0] + sh[1][1] + sh[1][2] + sh[1][3];
            g_reldot[2*b + 1] = sh[2][0] + sh[2][1] + sh[2][2] + sh[2][3];
        }
    } else {
        int k = b - RR;
        float p0 = proxy[k * CC + t];
        float p1 = proxy[k * CC + 128 + t];
        float s = warp_sum(p0 * p0 + p1 * p1);
        if (lane == 0) sh[0][w] = s;
        __syncthreads();
        if (t == 0) {
            float tot = sh[0][0] + sh[0][1] + sh[0][2] + sh[0][3];
            g_invp[k] = 1.0f / sqrtf(fmaxf(tot, 1e-12f));
        }
    }
}

// ---------------- Kernel B: row segment bounds (adj sorted by row) ----------------
__global__ void zero_bounds_kernel() {
    int i = blockIdx.x * blockDim.x + threadIdx.x;
    if (i < NN) { g_rb[i] = 0; g_re[i] = 0; }
}
__global__ void detect_bounds_kernel(const int* __restrict__ adj) {
    int e = blockIdx.x * blockDim.x + threadIdx.x;
    if (e >= EE) return;
    int r = adj[2 * e];
    if (e == 0 || adj[2 * (e - 1)] != r) g_rb[r] = e;
    if (e == EE - 1 || adj[2 * (e + 1)] != r) g_re[r] = e + 1;
}

// ---------------- Kernel C: per-row softmax + reflected-neighbor aggregation ----------------
__global__ void agg_kernel(const float* __restrict__ feats,
                           const float* __restrict__ rel_emb,
                           const float* __restrict__ sv,
                           const int* __restrict__ adj,
                           const int* __restrict__ si) {
    int gw = (blockIdx.x * blockDim.x + threadIdx.x) >> 5;
    int lane = threadIdx.x & 31;
    if (gw >= NN) return;

    int e0 = g_rb[gw], e1 = g_re[gw];
    float4* o0 = reinterpret_cast<float4*>(g_nf0 + (size_t)gw * FF);
    float4* o1 = reinterpret_cast<float4*>(g_nf1 + (size_t)gw * FF);

    if (e0 >= e1) {
        float4 z = make_float4(0.f, 0.f, 0.f, 0.f);
        o0[lane] = z; o1[lane] = z;
        return;
    }

    const float2* rd2 = reinterpret_cast<const float2*>(g_reldot);

    // pass 1: per-head max logit over the segment
    float m0 = -1e30f, m1 = -1e30f;
    #pragma unroll 4
    for (int e = e0; e < e1; e++) {
        float s = sv[e];
        int r = si[2 * e + 1];
        float2 rd = rd2[r];
        m0 = fmaxf(m0, s * rd.x);
        m1 = fmaxf(m1, s * rd.y);
    }

    // pass 2: accumulate exp-weighted reflected neighbors
    float4 a0 = make_float4(0.f, 0.f, 0.f, 0.f);
    float4 a1 = make_float4(0.f, 0.f, 0.f, 0.f);
    float s0 = 0.f, s1 = 0.f;
    #pragma unroll 2
    for (int e = e0; e < e1; e++) {
        int   col = adj[2 * e + 1];
        int   r   = si[2 * e + 1];
        float s   = sv[e];
        float2 rd = rd2[r];
        float f = s / sqrtf(fmaxf(s * s * g_relnsq[r], 1e-12f));

        float4 u = reinterpret_cast<const float4*>(rel_emb + (size_t)r * FF)[lane];
        u.x *= f; u.y *= f; u.z *= f; u.w *= f;
        float4 x = __ldg(reinterpret_cast<const float4*>(feats + (size_t)col * FF) + lane);

        float d = x.x * u.x + x.y * u.y + x.z * u.z + x.w * u.w;
        d = warp_sum(d);
        float t2 = 2.f * d;
        float4 y;
        y.x = x.x - t2 * u.x; y.y = x.y - t2 * u.y;
        y.z = x.z - t2 * u.z; y.w = x.w - t2 * u.w;

        float w0 = expf(s * rd.x - m0);
        float w1 = expf(s * rd.y - m1);
        s0 += w0; s1 += w1;
        a0.x += w0 * y.x; a0.y += w0 * y.y; a0.z += w0 * y.z; a0.w += w0 * y.w;
        a1.x += w1 * y.x; a1.y += w1 * y.y; a1.z += w1 * y.z; a1.w += w1 * y.w;
    }
    float i0 = 1.f / s0, i1 = 1.f / s1;
    a0.x *= i0; a0.y *= i0; a0.z *= i0; a0.w *= i0;
    a1.x *= i1; a1.y *= i1; a1.z *= i1; a1.w *= i1;
    o0[lane] = a0;
    o1[lane] = a1;
}

// ---------------- Kernel E: fused tail, 64-row tile, 512 threads, W staged in smem ----------
#define TILE 64
#define NTHR 512
#define PP 257  // proxy shared pitch
// Psh region (64 x 257) is reused for W chunks (64 x 256) during the gate GEMM.
#define SMEM_FLOATS (PX * PP + TILE * CC + TILE * CC + TILE * PX + TILE)

__global__ __launch_bounds__(NTHR) void final_kernel(const float* __restrict__ feats,
                                                     const float* __restrict__ proxy,
                                                     const float* __restrict__ W,
                                                     const int* __restrict__ neigh,
                                                     float* __restrict__ out) {
    extern __shared__ float sm[];
    float* Psh  = sm;                       // 64 x 257  (later: W chunk 64 x 256)
    float* Osh  = Psh + PX * PP;            // 64 x 256
    float* PFsh = Osh + TILE * CC;          // 64 x 256
    float* ATT  = PFsh + TILE * CC;         // 64 x 64
    float* INVN = ATT + TILE * PX;          // 64

    int tid = threadIdx.x;
    int lane = tid & 31, w = tid >> 5;       // 16 warps
    int r0 = w * 4;                          // each warp owns 4 rows
    int base = blockIdx.x * TILE;

    // load proxy (raw) into padded shared
    #pragma unroll
    for (int idx = tid; idx < PX * CC; idx += NTHR) {
        Psh[(idx >> 8) * PP + (idx & 255)] = proxy[idx];
    }
    // build O tile: concat(features, 0.5*(nf0 + nf1-swapped)); 2 rows per pass
    {
        int col = tid & 255;
        for (int rr = tid >> 8; rr < TILE; rr += 2) {
            int n = base + rr;
            float v = 0.f;
            if (n < NN) {
                if (col < 128) {
                    v = feats[(size_t)n * FF + col];
                } else {
                    int m = (n < K1) ? neigh[n] : n;
                    int jj = col - 128;
                    v = 0.5f * (g_nf0[(size_t)n * FF + jj] + g_nf1[(size_t)m * FF + jj]);
                }
            }
            Osh[rr * CC + col] = v;
        }
    }
    __syncthreads();

    // row inverse norms (warp w owns rows r0..r0+3)
    #pragma unroll
    for (int q = 0; q < 4; q++) {
        int r = r0 + q;
        float s = 0.f;
        #pragma unroll
        for (int m = 0; m < 8; m++) {
            float v = Osh[r * CC + lane + 32 * m];
            s += v * v;
        }
        s = warp_sum(s);
        if (lane == 0) INVN[r] = 1.f / sqrtf(fmaxf(s, 1e-12f));
    }
    __syncthreads();

    // ---- logits GEMM: 4 rows x 2 proxy cols per thread (k = lane, lane+32) ----
    {
        float acc0[4], acc1[4];
        #pragma unroll
        for (int q = 0; q < 4; q++) { acc0[q] = 0.f; acc1[q] = 0.f; }
        const float* p0 = Psh + lane * PP;
        const float* p1 = Psh + (lane + 32) * PP;
        #pragma unroll 2
        for (int j = 0; j < CC; j += 4) {
            float4 ov[4];
            #pragma unroll
            for (int q = 0; q < 4; q++)
                ov[q] = *reinterpret_cast<const float4*>(Osh + (r0 + q) * CC + j); // broadcast
            float a0 = p0[j], a1 = p0[j+1], a2 = p0[j+2], a3 = p0[j+3];
            float b0 = p1[j], b1 = p1[j+1], b2 = p1[j+2], b3 = p1[j+3];
            #pragma unroll
            for (int q = 0; q < 4; q++) {
                acc0[q] += ov[q].x * a0 + ov[q].y * a1 + ov[q].z * a2 + ov[q].w * a3;
                acc1[q] += ov[q].x * b0 + ov[q].y * b1 + ov[q].z * b2 + ov[q].w * b3;
            }
        }
        float ipa = g_invp[lane];
        float ipb = g_invp[lane + 32];
        #pragma unroll
        for (int q = 0; q < 4; q++) {
            int r = r0 + q;
            float invn = INVN[r];
            float l0 = acc0[q] * invn * ipa;
            float l1 = acc1[q] * invn * ipb;
            float mx = warp_max(fmaxf(l0, l1));
            float e0v = expf(l0 - mx);
            float e1v = expf(l1 - mx);
            float s = warp_sum(e0v + e1v);
            float inv = 1.f / s;
            ATT[r * PX + lane]      = e0v * inv;
            ATT[r * PX + lane + 32] = e1v * inv;
        }
    }
    __syncthreads();

    // ---- PF GEMM: proxy_feature = O - ATT @ proxy ; 4 rows x 8 cols (j = lane+32c) ----
    {
        float acc[4][8];
        #pragma unroll
        for (int q = 0; q < 4; q++)
            #pragma unroll
            for (int c = 0; c < 8; c++) acc[q][c] = 0.f;

        #pragma unroll 2
        for (int k = 0; k < PX; k++) {
            float a[4];
            #pragma unroll
            for (int q = 0; q < 4; q++) a[q] = ATT[(r0 + q) * PX + k];  // broadcast
            float pv[8];
            #pragma unroll
            for (int c = 0; c < 8; c++) pv[c] = Psh[k * PP + lane + 32 * c];
            #pragma unroll
            for (int q = 0; q < 4; q++)
                #pragma unroll
                for (int c = 0; c < 8; c++) acc[q][c] += a[q] * pv[c];
        }
        #pragma unroll
        for (int q = 0; q < 4; q++)
            #pragma unroll
            for (int c = 0; c < 8; c++) {
                int idx = (r0 + q) * CC + lane + 32 * c;
                PFsh[idx] = Osh[idx] - acc[q][c];
            }
    }

    // ---- gate GEMM: Z = PF @ W, W staged through smem (overlays Psh) in 4 chunks ----
    {
        float acc[4][8];
        #pragma unroll
        for (int q = 0; q < 4; q++)
            #pragma unroll
            for (int c = 0; c < 8; c++) acc[q][c] = 0.f;

        float4* Wsh4 = reinterpret_cast<float4*>(Psh);  // 64 x 64 float4
        const float4* Wg4 = reinterpret_cast<const float4*>(W);

        #pragma unroll
        for (int chunk = 0; chunk < 4; chunk++) {
            __syncthreads();  // prior consumers of Psh/Wsh done
            // load W rows [chunk*64, chunk*64+64) : 4096 float4, 8 per thread
            #pragma unroll
            for (int idx = tid; idx < 64 * 64; idx += NTHR)
                Wsh4[idx] = __ldg(Wg4 + chunk * 64 * 64 + idx);
            __syncthreads();

            #pragma unroll 2
            for (int ii = 0; ii < 64; ii++) {
                int i = chunk * 64 + ii;
                float4 wa = Wsh4[ii * 64 + lane];        // cols lane*4 .. +3
                float4 wb = Wsh4[ii * 64 + lane + 32];   // cols lane*4+128 .. +131
                float p[4];
                #pragma unroll
                for (int q = 0; q < 4; q++) p[q] = PFsh[(r0 + q) * CC + i]; // broadcast
                #pragma unroll
                for (int q = 0; q < 4; q++) {
                    acc[q][0] += p[q] * wa.x; acc[q][1] += p[q] * wa.y;
                    acc[q][2] += p[q] * wa.z; acc[q][3] += p[q] * wa.w;
                    acc[q][4] += p[q] * wb.x; acc[q][5] += p[q] * wb.y;
                    acc[q][6] += p[q] * wb.z; acc[q][7] += p[q] * wb.w;
                }
            }
        }

        // blend + store: cols lane*4..+3 and lane*4+128..+131
        #pragma unroll
        for (int q = 0; q < 4; q++) {
            int r = r0 + q;
            int n = base + r;
            if (n >= NN) continue;
            const float4* Orow  = reinterpret_cast<const float4*>(Osh + r * CC);
            const float4* PFrow = reinterpret_cast<const float4*>(PFsh + r * CC);
            float4 oa = Orow[lane],      ob = Orow[lane + 32];
            float4 fa = PFrow[lane],     fb = PFrow[lane + 32];
            float4 ra, rb;
            {
                float g;
                g = 1.f / (1.f + expf(-acc[q][0])); ra.x = g * oa.x + (1.f - g) * fa.x;
                g = 1.f / (1.f + expf(-acc[q][1])); ra.y = g * oa.y + (1.f - g) * fa.y;
                g = 1.f / (1.f + expf(-acc[q][2])); ra.z = g * oa.z + (1.f - g) * fa.z;
                g = 1.f / (1.f + expf(-acc[q][3])); ra.w = g * oa.w + (1.f - g) * fa.w;
                g = 1.f / (1.f + expf(-acc[q][4])); rb.x = g * ob.x + (1.f - g) * fb.x;
                g = 1.f / (1.f + expf(-acc[q][5])); rb.y = g * ob.y + (1.f - g) * fb.y;
                g = 1.f / (1.f + expf(-acc[q][6])); rb.z = g * ob.z + (1.f - g) * fb.z;
                g = 1.f / (1.f + expf(-acc[q][7])); rb.w = g * ob.w + (1.f - g) * fb.w;
            }
            float4* dst = reinterpret_cast<float4*>(out + (size_t)n * CC);
            dst[lane]      = ra;
            dst[lane + 32] = rb;
        }
    }
}

// ---------------- launch ----------------
extern "C" void kernel_launch(void* const* d_in, const int* in_sizes, int n_in,
                              void* d_out, int out_size) {
    const float* features  = (const float*)d_in[0];
    const float* rel_emb   = (const float*)d_in[1];
    const float* sparse_v  = (const float*)d_in[2];
    const float* attn_k    = (const float*)d_in[3];
    const float* proxy     = (const float*)d_in[4];
    const float* gate_k    = (const float*)d_in[5];
    const int*   adj       = (const int*)d_in[6];
    const int*   sparse_i  = (const int*)d_in[7];
    const int*   neigh     = (const int*)d_in[9];
    float* out = (float*)d_out;

    prep_kernel<<<RR + PX, 128>>>(rel_emb, attn_k, proxy);
    zero_bounds_kernel<<<(NN + 255) / 256, 256>>>();
    detect_bounds_kernel<<<(EE + 255) / 256, 256>>>(adj);
    agg_kernel<<<(NN * 32 + 255) / 256, 256>>>(features, rel_emb, sparse_v, adj, sparse_i);

    size_t smem = (size_t)SMEM_FLOATS * sizeof(float);
    cudaFuncSetAttribute(final_kernel, cudaFuncAttributeMaxDynamicSharedMemorySize, (int)smem);
    final_kernel<<<(NN + TILE - 1) / TILE, NTHR, smem>>>(features, proxy, gate_k, neigh, out);
}

// round 4
// speedup vs baseline: 2.8285x; 1.2329x over previous
#include <cuda_runtime.h>
#include <cuda_bf16.h>
#include <math.h>

// Problem constants (fixed by setup_inputs)
#define NN 50000
#define EE 400000
#define RR 1000
#define FF 128
#define K1 1000
#define PX 64      // proxy rows
#define CC 256     // concat dim = F*(DEPTH+1)

// ---------------- scratch (device globals; no allocation allowed) ----------------
__device__ float g_nf0[(size_t)NN * FF];
__device__ float g_nf1[(size_t)NN * FF];
__device__ float g_relnsq[RR];
__device__ float g_reldot[RR * 2];
__device__ float g_invp[PX];
__device__ int   g_rb[NN];
__device__ int   g_re[NN];

// W^T in split bf16, packed per 64-k chunk:
// layout: [chunk c][hi(9216 words) | lo(9216 words)], word = n*36 + (k_local>>1)
// (pitch 36 words = 72 bf16 per n-row; only words 0..31 carry data)
#define WT_CHUNK_WORDS 18432              // hi+lo per chunk
__device__ __align__(16) unsigned int g_Wt[4 * WT_CHUNK_WORDS];

__inline__ __device__ float warp_sum(float v) {
    #pragma unroll
    for (int o = 16; o; o >>= 1) v += __shfl_xor_sync(0xffffffffu, v, o);
    return v;
}
__inline__ __device__ float warp_max(float v) {
    #pragma unroll
    for (int o = 16; o; o >>= 1) v = fmaxf(v, __shfl_xor_sync(0xffffffffu, v, o));
    return v;
}

__inline__ __device__ unsigned int pack_bf16x2(__nv_bfloat16 lo, __nv_bfloat16 hi) {
    __nv_bfloat162 v(lo, hi);
    return *reinterpret_cast<unsigned int*>(&v);
}

__inline__ __device__ void mma_bf16(float* d, const unsigned int* a,
                                    unsigned int b0, unsigned int b1) {
    asm volatile(
        "mma.sync.aligned.m16n8k16.row.col.f32.bf16.bf16.f32 "
        "{%0,%1,%2,%3}, {%4,%5,%6,%7}, {%8,%9}, {%0,%1,%2,%3};"
        : "+f"(d[0]), "+f"(d[1]), "+f"(d[2]), "+f"(d[3])
        : "r"(a[0]), "r"(a[1]), "r"(a[2]), "r"(a[3]), "r"(b0), "r"(b1));
}

// ---------------- Kernel A: per-relation norms & attn dots, proxy inv-norms ----------------
__global__ void prep_kernel(const float* __restrict__ rel_emb,
                            const float* __restrict__ attn,
                            const float* __restrict__ proxy) {
    int b = blockIdx.x;
    int t = threadIdx.x;
    int lane = t & 31, w = t >> 5;
    __shared__ float sh[3][4];

    if (b < RR) {
        float v  = rel_emb[b * FF + t];
        float a0 = attn[t];
        float a1 = attn[FF + t];
        float nsq = warp_sum(v * v);
        float d0  = warp_sum(v * a0);
        float d1  = warp_sum(v * a1);
        if (lane == 0) { sh[0][w] = nsq; sh[1][w] = d0; sh[2][w] = d1; }
        __syncthreads();
        if (t == 0) {
            g_relnsq[b]       = sh[0][0] + sh[0][1] + sh[0][2] + sh[0][3];
            g_reldot[2*b]     = sh[1][0] + sh[1][1] + sh[1][2] + sh[1][3];
            g_reldot[2*b + 1] = sh[2][0] + sh[2][1] + sh[2][2] + sh[2][3];
        }
    } else {
        int k = b - RR;
        float p0 = proxy[k * CC + t];
        float p1 = proxy[k * CC + 128 + t];
        float s = warp_sum(p0 * p0 + p1 * p1);
        if (lane == 0) sh[0][w] = s;
        __syncthreads();
        if (t == 0) {
            float tot = sh[0][0] + sh[0][1] + sh[0][2] + sh[0][3];
            g_invp[k] = 1.0f / sqrtf(fmaxf(tot, 1e-12f));
        }
    }
}

// ---------------- Kernel A2: W -> transposed split-bf16 packed chunks ----------------
__global__ void wconv_kernel(const float* __restrict__ W) {
    int tid = blockIdx.x * blockDim.x + threadIdx.x;  // 256*128 threads
    if (tid >= 256 * 128) return;
    int n  = tid >> 7;
    int kp = tid & 127;
    int k  = kp * 2;
    float w0 = W[(size_t)k * CC + n];
    float w1 = W[(size_t)(k + 1) * CC + n];
    __nv_bfloat16 h0 = __float2bfloat16(w0);
    __nv_bfloat16 h1 = __float2bfloat16(w1);
    __nv_bfloat16 l0 = __float2bfloat16(w0 - __bfloat162float(h0));
    __nv_bfloat16 l1 = __float2bfloat16(w1 - __bfloat162float(h1));
    int c  = k >> 6;
    int lw = (k & 63) >> 1;
    int idx = c * WT_CHUNK_WORDS + n * 36 + lw;
    g_Wt[idx]        = pack_bf16x2(h0, h1);
    g_Wt[idx + 9216] = pack_bf16x2(l0, l1);
}

// ---------------- Kernel B: row segment bounds (adj sorted by row) ----------------
__global__ void zero_bounds_kernel() {
    int i = blockIdx.x * blockDim.x + threadIdx.x;
    if (i < NN) { g_rb[i] = 0; g_re[i] = 0; }
}
__global__ void detect_bounds_kernel(const int* __restrict__ adj) {
    int e = blockIdx.x * blockDim.x + threadIdx.x;
    if (e >= EE) return;
    int r = adj[2 * e];
    if (e == 0 || adj[2 * (e - 1)] != r) g_rb[r] = e;
    if (e == EE - 1 || adj[2 * (e + 1)] != r) g_re[r] = e + 1;
}

// ---------------- Kernel C: per-row softmax + reflected-neighbor aggregation ----------------
__global__ void agg_kernel(const float* __restrict__ feats,
                           const float* __restrict__ rel_emb,
                           const float* __restrict__ sv,
                           const int* __restrict__ adj,
                           const int* __restrict__ si) {
    int gw = (blockIdx.x * blockDim.x + threadIdx.x) >> 5;
    int lane = threadIdx.x & 31;
    if (gw >= NN) return;

    int e0 = g_rb[gw], e1 = g_re[gw];
    float4* o0 = reinterpret_cast<float4*>(g_nf0 + (size_t)gw * FF);
    float4* o1 = reinterpret_cast<float4*>(g_nf1 + (size_t)gw * FF);

    if (e0 >= e1) {
        float4 z = make_float4(0.f, 0.f, 0.f, 0.f);
        o0[lane] = z; o1[lane] = z;
        return;
    }

    const float2* rd2 = reinterpret_cast<const float2*>(g_reldot);

    float m0 = -1e30f, m1 = -1e30f;
    #pragma unroll 4
    for (int e = e0; e < e1; e++) {
        float s = sv[e];
        int r = si[2 * e + 1];
        float2 rd = rd2[r];
        m0 = fmaxf(m0, s * rd.x);
        m1 = fmaxf(m1, s * rd.y);
    }

    float4 a0 = make_float4(0.f, 0.f, 0.f, 0.f);
    float4 a1 = make_float4(0.f, 0.f, 0.f, 0.f);
    float s0 = 0.f, s1 = 0.f;
    #pragma unroll 2
    for (int e = e0; e < e1; e++) {
        int   col = adj[2 * e + 1];
        int   r   = si[2 * e + 1];
        float s   = sv[e];
        float2 rd = rd2[r];
        float f = s / sqrtf(fmaxf(s * s * g_relnsq[r], 1e-12f));

        float4 u = reinterpret_cast<const float4*>(rel_emb + (size_t)r * FF)[lane];
        u.x *= f; u.y *= f; u.z *= f; u.w *= f;
        float4 x = __ldg(reinterpret_cast<const float4*>(feats + (size_t)col * FF) + lane);

        float d = x.x * u.x + x.y * u.y + x.z * u.z + x.w * u.w;
        d = warp_sum(d);
        float t2 = 2.f * d;
        float4 y;
        y.x = x.x - t2 * u.x; y.y = x.y - t2 * u.y;
        y.z = x.z - t2 * u.z; y.w = x.w - t2 * u.w;

        float w0 = expf(s * rd.x - m0);
        float w1 = expf(s * rd.y - m1);
        s0 += w0; s1 += w1;
        a0.x += w0 * y.x; a0.y += w0 * y.y; a0.z += w0 * y.z; a0.w += w0 * y.w;
        a1.x += w1 * y.x; a1.y += w1 * y.y; a1.z += w1 * y.z; a1.w += w1 * y.w;
    }
    float i0 = 1.f / s0, i1 = 1.f / s1;
    a0.x *= i0; a0.y *= i0; a0.z *= i0; a0.w *= i0;
    a1.x *= i1; a1.y *= i1; a1.z *= i1; a1.w *= i1;
    o0[lane] = a0;
    o1[lane] = a1;
}

// ---------------- Kernel E: fused tail; gate GEMM on tensor cores ----------------
#define TILE 64
#define NTHR 512
#define PP 257
// smem word offsets (floats)
#define OFF_REG0   0                       // proxy (64x257) / Wt chunk (18432 words)
#define OFF_OSH    18432                   // 64 x 256 fp32
#define OFF_PFHI   (OFF_OSH + 16384)       // 64 x 132 words (bf16x2, pitch 264)
#define OFF_PFLO   (OFF_PFHI + 8448)
#define OFF_ATT    (OFF_PFLO + 8448)       // 64 x 64
#define OFF_INVN   (OFF_ATT + 4096)        // 64
#define SMEM_FLOATS (OFF_INVN + 64)        // 55872 floats = 223,488 B

__global__ __launch_bounds__(NTHR) void final_kernel(const float* __restrict__ feats,
                                                     const float* __restrict__ proxy,
                                                     const int* __restrict__ neigh,
                                                     float* __restrict__ out) {
    extern __shared__ float sm[];
    float* Psh  = sm + OFF_REG0;            // proxy during logits/PF; Wt chunk later
    float* Osh  = sm + OFF_OSH;
    unsigned int* PFhiW = reinterpret_cast<unsigned int*>(sm + OFF_PFHI);
    unsigned int* PFloW = reinterpret_cast<unsigned int*>(sm + OFF_PFLO);
    __nv_bfloat16* PFhi16 = reinterpret_cast<__nv_bfloat16*>(PFhiW);
    __nv_bfloat16* PFlo16 = reinterpret_cast<__nv_bfloat16*>(PFloW);
    float* ATT  = sm + OFF_ATT;
    float* INVN = sm + OFF_INVN;

    int tid = threadIdx.x;
    int lane = tid & 31, w = tid >> 5;       // 16 warps
    int r0 = w * 4;
    int base = blockIdx.x * TILE;

    // load proxy (raw) into padded shared
    #pragma unroll
    for (int idx = tid; idx < PX * CC; idx += NTHR) {
        Psh[(idx >> 8) * PP + (idx & 255)] = proxy[idx];
    }
    // build O tile: concat(features, 0.5*(nf0 + nf1-swapped)); 2 rows per pass
    {
        int col = tid & 255;
        for (int rr = tid >> 8; rr < TILE; rr += 2) {
            int n = base + rr;
            float v = 0.f;
            if (n < NN) {
                if (col < 128) {
                    v = feats[(size_t)n * FF + col];
                } else {
                    int m = (n < K1) ? neigh[n] : n;
                    int jj = col - 128;
                    v = 0.5f * (g_nf0[(size_t)n * FF + jj] + g_nf1[(size_t)m * FF + jj]);
                }
            }
            Osh[rr * CC + col] = v;
        }
    }
    __syncthreads();

    // row inverse norms
    #pragma unroll
    for (int q = 0; q < 4; q++) {
        int r = r0 + q;
        float s = 0.f;
        #pragma unroll
        for (int m = 0; m < 8; m++) {
            float v = Osh[r * CC + lane + 32 * m];
            s += v * v;
        }
        s = warp_sum(s);
        if (lane == 0) INVN[r] = 1.f / sqrtf(fmaxf(s, 1e-12f));
    }
    __syncthreads();

    // ---- logits GEMM (SIMT): 4 rows x 2 proxy cols per thread ----
    {
        float acc0[4], acc1[4];
        #pragma unroll
        for (int q = 0; q < 4; q++) { acc0[q] = 0.f; acc1[q] = 0.f; }
        const float* p0 = Psh + lane * PP;
        const float* p1 = Psh + (lane + 32) * PP;
        #pragma unroll 2
        for (int j = 0; j < CC; j += 4) {
            float4 ov[4];
            #pragma unroll
            for (int q = 0; q < 4; q++)
                ov[q] = *reinterpret_cast<const float4*>(Osh + (r0 + q) * CC + j);
            float a0 = p0[j], a1 = p0[j+1], a2 = p0[j+2], a3 = p0[j+3];
            float b0 = p1[j], b1 = p1[j+1], b2 = p1[j+2], b3 = p1[j+3];
            #pragma unroll
            for (int q = 0; q < 4; q++) {
                acc0[q] += ov[q].x * a0 + ov[q].y * a1 + ov[q].z * a2 + ov[q].w * a3;
                acc1[q] += ov[q].x * b0 + ov[q].y * b1 + ov[q].z * b2 + ov[q].w * b3;
            }
        }
        float ipa = g_invp[lane];
        float ipb = g_invp[lane + 32];
        #pragma unroll
        for (int q = 0; q < 4; q++) {
            int r = r0 + q;
            float invn = INVN[r];
            float l0 = acc0[q] * invn * ipa;
            float l1 = acc1[q] * invn * ipb;
            float mx = warp_max(fmaxf(l0, l1));
            float e0v = expf(l0 - mx);
            float e1v = expf(l1 - mx);
            float s = warp_sum(e0v + e1v);
            float inv = 1.f / s;
            ATT[r * PX + lane]      = e0v * inv;
            ATT[r * PX + lane + 32] = e1v * inv;
        }
    }
    __syncthreads();

    // ---- PF GEMM (SIMT): proxy_feature = O - ATT @ proxy -> split bf16 ----
    {
        float acc[4][8];
        #pragma unroll
        for (int q = 0; q < 4; q++)
            #pragma unroll
            for (int c = 0; c < 8; c++) acc[q][c] = 0.f;

        #pragma unroll 2
        for (int k = 0; k < PX; k++) {
            float a[4];
            #pragma unroll
            for (int q = 0; q < 4; q++) a[q] = ATT[(r0 + q) * PX + k];
            float pv[8];
            #pragma unroll
            for (int c = 0; c < 8; c++) pv[c] = Psh[k * PP + lane + 32 * c];
            #pragma unroll
            for (int q = 0; q < 4; q++)
                #pragma unroll
                for (int c = 0; c < 8; c++) acc[q][c] += a[q] * pv[c];
        }
        #pragma unroll
        for (int q = 0; q < 4; q++) {
            int r = r0 + q;
            #pragma unroll
            for (int c = 0; c < 8; c++) {
                int col = lane + 32 * c;
                float v = Osh[r * CC + col] - acc[q][c];
                __nv_bfloat16 h = __float2bfloat16(v);
                __nv_bfloat16 l = __float2bfloat16(v - __bfloat162float(h));
                PFhi16[r * 264 + col] = h;
                PFlo16[r * 264 + col] = l;
            }
        }
    }

    // ---- gate GEMM on tensor cores: Z = PF @ W (split bf16, 3 MMAs) ----
    {
        int g   = lane >> 2;     // 0..7
        int tig = lane & 3;      // 0..3
        int wm  = w & 1;         // row supergroup (32 rows)
        int wn  = w >> 1;        // col group (32 cols)

        float acc[2][4][4];
        #pragma unroll
        for (int mt = 0; mt < 2; mt++)
            #pragma unroll
            for (int nt = 0; nt < 4; nt++)
                #pragma unroll
                for (int i = 0; i < 4; i++) acc[mt][nt][i] = 0.f;

        unsigned int* WtSh = reinterpret_cast<unsigned int*>(sm + OFF_REG0);

        #pragma unroll
        for (int c = 0; c < 4; c++) {
            __syncthreads();   // prior consumers of region0 done
            // contiguous copy of chunk c (hi+lo = 18432 words = 4608 uint4)
            {
                const uint4* src = reinterpret_cast<const uint4*>(g_Wt + c * WT_CHUNK_WORDS);
                uint4* dst = reinterpret_cast<uint4*>(WtSh);
                #pragma unroll
                for (int i = tid; i < 4608; i += NTHR) dst[i] = src[i];
            }
            __syncthreads();

            #pragma unroll
            for (int ks = 0; ks < 4; ks++) {
                int kw  = c * 32 + ks * 8;   // PF word base (global k / 2)
                int lkw = ks * 8;            // Wt chunk word base

                unsigned int ah[2][4], al[2][4];
                #pragma unroll
                for (int mt = 0; mt < 2; mt++) {
                    int rb  = (wm * 32 + mt * 16 + g) * 132;
                    int rb8 = rb + 8 * 132;
                    ah[mt][0] = PFhiW[rb  + kw + tig];
                    ah[mt][1] = PFhiW[rb8 + kw + tig];
                    ah[mt][2] = PFhiW[rb  + kw + 4 + tig];
                    ah[mt][3] = PFhiW[rb8 + kw + 4 + tig];
                    al[mt][0] = PFloW[rb  + kw + tig];
                    al[mt][1] = PFloW[rb8 + kw + tig];
                    al[mt][2] = PFloW[rb  + kw + 4 + tig];
                    al[mt][3] = PFloW[rb8 + kw + 4 + tig];
                }
                #pragma unroll
                for (int nt = 0; nt < 4; nt++) {
                    int n = wn * 32 + nt * 8 + g;
                    unsigned int bh0 = WtSh[n * 36 + lkw + tig];
                    unsigned int bh1 = WtSh[n * 36 + lkw + 4 + tig];
                    unsigned int bl0 = WtSh[9216 + n * 36 + lkw + tig];
                    unsigned int bl1 = WtSh[9216 + n * 36 + lkw + 4 + tig];
                    #pragma unroll
                    for (int mt = 0; mt < 2; mt++) {
                        mma_bf16(acc[mt][nt], ah[mt], bh0, bh1);
                        mma_bf16(acc[mt][nt], ah[mt], bl0, bl1);
                        mma_bf16(acc[mt][nt], al[mt], bh0, bh1);
                    }
                }
            }
        }

        // epilogue: gate + blend + store
        #pragma unroll
        for (int mt = 0; mt < 2; mt++) {
            #pragma unroll
            for (int nt = 0; nt < 4; nt++) {
                int ncol = wn * 32 + nt * 8 + 2 * tig;
                #pragma unroll
                for (int half = 0; half < 2; half++) {
                    int r = wm * 32 + mt * 16 + g + 8 * half;
                    int n = base + r;
                    if (n >= NN) continue;
                    float z0 = acc[mt][nt][2 * half];
                    float z1 = acc[mt][nt][2 * half + 1];
                    float2 o = *reinterpret_cast<const float2*>(Osh + r * CC + ncol);
                    __nv_bfloat162 ph = *reinterpret_cast<__nv_bfloat162*>(&PFhiW[r * 132 + ncol / 2]);
                    __nv_bfloat162 pl = *reinterpret_cast<__nv_bfloat162*>(&PFloW[r * 132 + ncol / 2]);
                    float pf0 = __bfloat162float(ph.x) + __bfloat162float(pl.x);
                    float pf1 = __bfloat162float(ph.y) + __bfloat162float(pl.y);
                    float g0 = 1.f / (1.f + expf(-z0));
                    float g1 = 1.f / (1.f + expf(-z1));
                    float2 res;
                    res.x = g0 * o.x + (1.f - g0) * pf0;
                    res.y = g1 * o.y + (1.f - g1) * pf1;
                    *reinterpret_cast<float2*>(out + (size_t)n * CC + ncol) = res;
                }
            }
        }
    }
}

// ---------------- launch ----------------
extern "C" void kernel_launch(void* const* d_in, const int* in_sizes, int n_in,
                              void* d_out, int out_size) {
    const float* features  = (const float*)d_in[0];
    const float* rel_emb   = (const float*)d_in[1];
    const float* sparse_v  = (const float*)d_in[2];
    const float* attn_k    = (const float*)d_in[3];
    const float* proxy     = (const float*)d_in[4];
    const float* gate_k    = (const float*)d_in[5];
    const int*   adj       = (const int*)d_in[6];
    const int*   sparse_i  = (const int*)d_in[7];
    const int*   neigh     = (const int*)d_in[9];
    float* out = (float*)d_out;

    prep_kernel<<<RR + PX, 128>>>(rel_emb, attn_k, proxy);
    wconv_kernel<<<128, 256>>>(gate_k);
    zero_bounds_kernel<<<(NN + 255) / 256, 256>>>();
    detect_bounds_kernel<<<(EE + 255) / 256, 256>>>(adj);
    agg_kernel<<<(NN * 32 + 255) / 256, 256>>>(features, rel_emb, sparse_v, adj, sparse_i);

    size_t smem = (size_t)SMEM_FLOATS * sizeof(float);
    cudaFuncSetAttribute(final_kernel, cudaFuncAttributeMaxDynamicSharedMemorySize, (int)smem);
    final_kernel<<<(NN + TILE - 1) / TILE, NTHR, smem>>>(features, proxy, neigh, out);
}

// round 5
// speedup vs baseline: 3.3705x; 1.1916x over previous
#include <cuda_runtime.h>
#include <cuda_bf16.h>
#include <math.h>

// Problem constants (fixed by setup_inputs)
#define NN 50000
#define EE 400000
#define RR 1000
#define FF 128
#define K1 1000
#define PX 64      // proxy rows
#define CC 256     // concat dim

// ---------------- scratch (device globals) ----------------
__device__ float g_nf0[(size_t)NN * FF];
__device__ float g_nf1[(size_t)NN * FF];
__device__ float g_relnsq[RR];
__device__ float g_reldot[RR * 2];
__device__ float g_invp[PX];
__device__ int   g_rb[NN];
__device__ int   g_re[NN];

// W^T split bf16 per 64-k chunk: [chunk][hi(9216)|lo(9216)], word = n*36 + k_local/2
#define WT_CHUNK_WORDS 18432
__device__ __align__(16) unsigned int g_Wt[4 * WT_CHUNK_WORDS];
// proxy split bf16, k-major: [hi(64*132)|lo], word = n*132 + k/2
__device__ __align__(16) unsigned int g_Pb[16896];
// proxy^T split bf16, n-major: [hi(256*36)|lo], word = n*36 + k/2
__device__ __align__(16) unsigned int g_PTb[18432];

__inline__ __device__ float warp_sum(float v) {
    #pragma unroll
    for (int o = 16; o; o >>= 1) v += __shfl_xor_sync(0xffffffffu, v, o);
    return v;
}
__inline__ __device__ float warp_max(float v) {
    #pragma unroll
    for (int o = 16; o; o >>= 1) v = fmaxf(v, __shfl_xor_sync(0xffffffffu, v, o));
    return v;
}
__inline__ __device__ unsigned int pack_bf16x2(__nv_bfloat16 lo, __nv_bfloat16 hi) {
    __nv_bfloat162 v(lo, hi);
    return *reinterpret_cast<unsigned int*>(&v);
}
__inline__ __device__ void mma_bf16(float* d, const unsigned int* a,
                                    unsigned int b0, unsigned int b1) {
    asm volatile(
        "mma.sync.aligned.m16n8k16.row.col.f32.bf16.bf16.f32 "
        "{%0,%1,%2,%3}, {%4,%5,%6,%7}, {%8,%9}, {%0,%1,%2,%3};"
        : "+f"(d[0]), "+f"(d[1]), "+f"(d[2]), "+f"(d[3])
        : "r"(a[0]), "r"(a[1]), "r"(a[2]), "r"(a[3]), "r"(b0), "r"(b1));
}

// ---------------- Kernel A: per-relation norms & attn dots, proxy inv-norms ----------------
__global__ void prep_kernel(const float* __restrict__ rel_emb,
                            const float* __restrict__ attn,
                            const float* __restrict__ proxy) {
    int b = blockIdx.x;
    int t = threadIdx.x;
    int lane = t & 31, w = t >> 5;
    __shared__ float sh[3][4];

    if (b < RR) {
        float v  = rel_emb[b * FF + t];
        float a0 = attn[t];
        float a1 = attn[FF + t];
        float nsq = warp_sum(v * v);
        float d0  = warp_sum(v * a0);
        float d1  = warp_sum(v * a1);
        if (lane == 0) { sh[0][w] = nsq; sh[1][w] = d0; sh[2][w] = d1; }
        __syncthreads();
        if (t == 0) {
            g_relnsq[b]       = sh[0][0] + sh[0][1] + sh[0][2] + sh[0][3];
            g_reldot[2*b]     = sh[1][0] + sh[1][1] + sh[1][2] + sh[1][3];
            g_reldot[2*b + 1] = sh[2][0] + sh[2][1] + sh[2][2] + sh[2][3];
        }
    } else {
        int k = b - RR;
        float p0 = proxy[k * CC + t];
        float p1 = proxy[k * CC + 128 + t];
        float s = warp_sum(p0 * p0 + p1 * p1);
        if (lane == 0) sh[0][w] = s;
        __syncthreads();
        if (t == 0) {
            float tot = sh[0][0] + sh[0][1] + sh[0][2] + sh[0][3];
            g_invp[k] = 1.0f / sqrtf(fmaxf(tot, 1e-12f));
        }
    }
}

// ---------------- Kernel A2: W & proxy -> split bf16 packed layouts ----------------
__global__ void wconv_kernel(const float* __restrict__ W, const float* __restrict__ proxy) {
    int tid = blockIdx.x * blockDim.x + threadIdx.x;
    // task 1: W^T chunks (256 n * 128 kpairs)
    if (tid < 256 * 128) {
        int n  = tid >> 7;
        int kp = tid & 127;
        int k  = kp * 2;
        float w0 = W[(size_t)k * CC + n];
        float w1 = W[(size_t)(k + 1) * CC + n];
        __nv_bfloat16 h0 = __float2bfloat16(w0);
        __nv_bfloat16 h1 = __float2bfloat16(w1);
        __nv_bfloat16 l0 = __float2bfloat16(w0 - __bfloat162float(h0));
        __nv_bfloat16 l1 = __float2bfloat16(w1 - __bfloat162float(h1));
        int c  = k >> 6;
        int lw = (k & 63) >> 1;
        int idx = c * WT_CHUNK_WORDS + n * 36 + lw;
        g_Wt[idx]        = pack_bf16x2(h0, h1);
        g_Wt[idx + 9216] = pack_bf16x2(l0, l1);
    } else if (tid < 256 * 128 + 64 * 128) {
        // task 2: P k-major (64 n * 128 kpairs)
        int t2 = tid - 256 * 128;
        int n  = t2 >> 7;
        int kp = t2 & 127;
        int k  = kp * 2;
        float w0 = proxy[(size_t)n * CC + k];
        float w1 = proxy[(size_t)n * CC + k + 1];
        __nv_bfloat16 h0 = __float2bfloat16(w0);
        __nv_bfloat16 h1 = __float2bfloat16(w1);
        __nv_bfloat16 l0 = __float2bfloat16(w0 - __bfloat162float(h0));
        __nv_bfloat16 l1 = __float2bfloat16(w1 - __bfloat162float(h1));
        g_Pb[n * 132 + kp]        = pack_bf16x2(h0, h1);
        g_Pb[n * 132 + kp + 8448] = pack_bf16x2(l0, l1);
    } else if (tid < 256 * 128 + 64 * 128 + 256 * 32) {
        // task 3: P^T n-major (256 n * 32 kpairs), k over proxy rows
        int t3 = tid - 256 * 128 - 64 * 128;
        int n  = t3 >> 5;
        int kw = t3 & 31;
        int k  = kw * 2;
        float w0 = proxy[(size_t)k * CC + n];
        float w1 = proxy[(size_t)(k + 1) * CC + n];
        __nv_bfloat16 h0 = __float2bfloat16(w0);
        __nv_bfloat16 h1 = __float2bfloat16(w1);
        __nv_bfloat16 l0 = __float2bfloat16(w0 - __bfloat162float(h0));
        __nv_bfloat16 l1 = __float2bfloat16(w1 - __bfloat162float(h1));
        g_PTb[n * 36 + kw]        = pack_bf16x2(h0, h1);
        g_PTb[n * 36 + kw + 9216] = pack_bf16x2(l0, l1);
    }
}

// ---------------- Kernel B: row segment bounds ----------------
__global__ void zero_bounds_kernel() {
    int i = blockIdx.x * blockDim.x + threadIdx.x;
    if (i < NN) { g_rb[i] = 0; g_re[i] = 0; }
}
__global__ void detect_bounds_kernel(const int* __restrict__ adj) {
    int e = blockIdx.x * blockDim.x + threadIdx.x;
    if (e >= EE) return;
    int r = adj[2 * e];
    if (e == 0 || adj[2 * (e - 1)] != r) g_rb[r] = e;
    if (e == EE - 1 || adj[2 * (e + 1)] != r) g_re[r] = e + 1;
}

// ---------------- Kernel C: per-row softmax + reflected-neighbor aggregation ----------------
__global__ void agg_kernel(const float* __restrict__ feats,
                           const float* __restrict__ rel_emb,
                           const float* __restrict__ sv,
                           const int* __restrict__ adj,
                           const int* __restrict__ si) {
    int gw = (blockIdx.x * blockDim.x + threadIdx.x) >> 5;
    int lane = threadIdx.x & 31;
    if (gw >= NN) return;

    int e0 = g_rb[gw], e1 = g_re[gw];
    float4* o0 = reinterpret_cast<float4*>(g_nf0 + (size_t)gw * FF);
    float4* o1 = reinterpret_cast<float4*>(g_nf1 + (size_t)gw * FF);

    if (e0 >= e1) {
        float4 z = make_float4(0.f, 0.f, 0.f, 0.f);
        o0[lane] = z; o1[lane] = z;
        return;
    }

    const float2* rd2 = reinterpret_cast<const float2*>(g_reldot);

    float m0 = -1e30f, m1 = -1e30f;
    #pragma unroll 4
    for (int e = e0; e < e1; e++) {
        float s = sv[e];
        int r = si[2 * e + 1];
        float2 rd = rd2[r];
        m0 = fmaxf(m0, s * rd.x);
        m1 = fmaxf(m1, s * rd.y);
    }

    float4 a0 = make_float4(0.f, 0.f, 0.f, 0.f);
    float4 a1 = make_float4(0.f, 0.f, 0.f, 0.f);
    float s0 = 0.f, s1 = 0.f;
    #pragma unroll 2
    for (int e = e0; e < e1; e++) {
        int   col = adj[2 * e + 1];
        int   r   = si[2 * e + 1];
        float s   = sv[e];
        float2 rd = rd2[r];
        float f = s / sqrtf(fmaxf(s * s * g_relnsq[r], 1e-12f));

        float4 u = reinterpret_cast<const float4*>(rel_emb + (size_t)r * FF)[lane];
        u.x *= f; u.y *= f; u.z *= f; u.w *= f;
        float4 x = __ldg(reinterpret_cast<const float4*>(feats + (size_t)col * FF) + lane);

        float d = x.x * u.x + x.y * u.y + x.z * u.z + x.w * u.w;
        d = warp_sum(d);
        float t2 = 2.f * d;
        float4 y;
        y.x = x.x - t2 * u.x; y.y = x.y - t2 * u.y;
        y.z = x.z - t2 * u.z; y.w = x.w - t2 * u.w;

        float w0 = expf(s * rd.x - m0);
        float w1 = expf(s * rd.y - m1);
        s0 += w0; s1 += w1;
        a0.x += w0 * y.x; a0.y += w0 * y.y; a0.z += w0 * y.z; a0.w += w0 * y.w;
        a1.x += w1 * y.x; a1.y += w1 * y.y; a1.z += w1 * y.z; a1.w += w1 * y.w;
    }
    float i0 = 1.f / s0, i1 = 1.f / s1;
    a0.x *= i0; a0.y *= i0; a0.z *= i0; a0.w *= i0;
    a1.x *= i1; a1.y *= i1; a1.z *= i1; a1.w *= i1;
    o0[lane] = a0;
    o1[lane] = a1;
}

// ---------------- Kernel E: fused tail; all three GEMMs on tensor cores ----------------
#define TILE 64
#define NTHR 512
// smem word offsets
#define OFF_REG0   0            // P stage (16896) / PT stage (18432) / Wt chunk (18432)
#define OFF_OHI    18432        // 64 x 132 words (bf16x2)
#define OFF_OLO    26880
#define OFF_SCR    35328        // logits fp32 (64x65) -> PFhi (64x132 words)
#define OFF_PFLO   43776
#define OFF_ATTHI  52224        // 64 x 36 words
#define OFF_ATTLO  54528
#define OFF_INVN   56832
#define OFF_INVP   56896
#define SMEM_WORDS 56960        // 227,840 B

__global__ __launch_bounds__(NTHR) void final_kernel(const float* __restrict__ feats,
                                                     const int* __restrict__ neigh,
                                                     float* __restrict__ out) {
    extern __shared__ float sm[];
    unsigned int* REG0W  = reinterpret_cast<unsigned int*>(sm + OFF_REG0);
    unsigned int* OhiW   = reinterpret_cast<unsigned int*>(sm + OFF_OHI);
    unsigned int* OloW   = reinterpret_cast<unsigned int*>(sm + OFF_OLO);
    __nv_bfloat16* Ohi16 = reinterpret_cast<__nv_bfloat16*>(OhiW);
    __nv_bfloat16* Olo16 = reinterpret_cast<__nv_bfloat16*>(OloW);
    float* LG            = sm + OFF_SCR;   // logits scratch, pitch 65
    unsigned int* PFhiW  = reinterpret_cast<unsigned int*>(sm + OFF_SCR);
    unsigned int* PFloW  = reinterpret_cast<unsigned int*>(sm + OFF_PFLO);
    unsigned int* ATThiW = reinterpret_cast<unsigned int*>(sm + OFF_ATTHI);
    unsigned int* ATTloW = reinterpret_cast<unsigned int*>(sm + OFF_ATTLO);
    __nv_bfloat16* ATThi16 = reinterpret_cast<__nv_bfloat16*>(ATThiW);
    __nv_bfloat16* ATTlo16 = reinterpret_cast<__nv_bfloat16*>(ATTloW);
    float* INVN = sm + OFF_INVN;
    float* INVP = sm + OFF_INVP;

    int tid = threadIdx.x;
    int lane = tid & 31, w = tid >> 5;       // 16 warps
    int g   = lane >> 2;                     // 0..7
    int tig = lane & 3;                      // 0..3
    int base = blockIdx.x * TILE;

    if (tid < PX) INVP[tid] = g_invp[tid];

    // stage P hi/lo (16896 words = 4224 uint4)
    {
        const uint4* src = reinterpret_cast<const uint4*>(g_Pb);
        uint4* dst = reinterpret_cast<uint4*>(REG0W);
        #pragma unroll
        for (int i = tid; i < 4224; i += NTHR) dst[i] = src[i];
    }
    // build O tile as split bf16: concat(features, 0.5*(nf0 + nf1-swapped))
    {
        int col = tid & 255;
        for (int rr = tid >> 8; rr < TILE; rr += 2) {
            int n = base + rr;
            float v = 0.f;
            if (n < NN) {
                if (col < 128) {
                    v = feats[(size_t)n * FF + col];
                } else {
                    int m = (n < K1) ? neigh[n] : n;
                    int jj = col - 128;
                    v = 0.5f * (g_nf0[(size_t)n * FF + jj] + g_nf1[(size_t)m * FF + jj]);
                }
            }
            __nv_bfloat16 h = __float2bfloat16(v);
            __nv_bfloat16 l = __float2bfloat16(v - __bfloat162float(h));
            Ohi16[rr * 264 + col] = h;
            Olo16[rr * 264 + col] = l;
        }
    }
    __syncthreads();

    // row inverse norms from reconstructed O (warp w owns rows 4w..4w+3)
    #pragma unroll
    for (int q = 0; q < 4; q++) {
        int r = w * 4 + q;
        float s = 0.f;
        #pragma unroll
        for (int m = 0; m < 4; m++) {
            int j = r * 132 + lane + 32 * m;
            __nv_bfloat162 h = *reinterpret_cast<__nv_bfloat162*>(&OhiW[j]);
            __nv_bfloat162 l = *reinterpret_cast<__nv_bfloat162*>(&OloW[j]);
            float v0 = __bfloat162float(h.x) + __bfloat162float(l.x);
            float v1 = __bfloat162float(h.y) + __bfloat162float(l.y);
            s += v0 * v0 + v1 * v1;
        }
        s = warp_sum(s);
        if (lane == 0) INVN[r] = 1.f / sqrtf(fmaxf(s, 1e-12f));
    }
    __syncthreads();

    // ---- logits MMA: L = O @ P^T (64x64, K=256), split bf16 (3 products) ----
    {
        int mt  = w & 3;          // m tile (16 rows)
        int nt2 = w >> 2;         // 16-col group (two n8 tiles)
        float acc[2][4];
        #pragma unroll
        for (int nt = 0; nt < 2; nt++)
            #pragma unroll
            for (int i = 0; i < 4; i++) acc[nt][i] = 0.f;

        #pragma unroll 4
        for (int ks = 0; ks < 16; ks++) {
            int kw = ks * 8;
            int rb  = (mt * 16 + g) * 132;
            int rb8 = rb + 8 * 132;
            unsigned int ah[4], al[4];
            ah[0] = OhiW[rb  + kw + tig];     ah[1] = OhiW[rb8 + kw + tig];
            ah[2] = OhiW[rb  + kw + 4 + tig]; ah[3] = OhiW[rb8 + kw + 4 + tig];
            al[0] = OloW[rb  + kw + tig];     al[1] = OloW[rb8 + kw + tig];
            al[2] = OloW[rb  + kw + 4 + tig]; al[3] = OloW[rb8 + kw + 4 + tig];
            #pragma unroll
            for (int nt = 0; nt < 2; nt++) {
                int n = nt2 * 16 + nt * 8 + g;
                unsigned int bh0 = REG0W[n * 132 + kw + tig];
                unsigned int bh1 = REG0W[n * 132 + kw + 4 + tig];
                unsigned int bl0 = REG0W[8448 + n * 132 + kw + tig];
                unsigned int bl1 = REG0W[8448 + n * 132 + kw + 4 + tig];
                mma_bf16(acc[nt], ah, bh0, bh1);
                mma_bf16(acc[nt], ah, bl0, bl1);
                mma_bf16(acc[nt], al, bh0, bh1);
            }
        }
        // scaled epilogue -> LG (pitch 65)
        #pragma unroll
        for (int nt = 0; nt < 2; nt++) {
            int ncol = nt2 * 16 + nt * 8 + 2 * tig;
            float ip0 = INVP[ncol], ip1 = INVP[ncol + 1];
            #pragma unroll
            for (int half = 0; half < 2; half++) {
                int r = mt * 16 + g + 8 * half;
                float invn = INVN[r];
                LG[r * 65 + ncol]     = acc[nt][2 * half]     * invn * ip0;
                LG[r * 65 + ncol + 1] = acc[nt][2 * half + 1] * invn * ip1;
            }
        }
    }
    __syncthreads();

    // ---- softmax over 64 proxies (warp w owns rows 4w..4w+3) -> split bf16 ATT ----
    #pragma unroll
    for (int q = 0; q < 4; q++) {
        int r = w * 4 + q;
        float l0 = LG[r * 65 + lane];
        float l1 = LG[r * 65 + lane + 32];
        float mx = warp_max(fmaxf(l0, l1));
        float e0v = expf(l0 - mx);
        float e1v = expf(l1 - mx);
        float s = warp_sum(e0v + e1v);
        float inv = 1.f / s;
        float a0 = e0v * inv, a1 = e1v * inv;
        __nv_bfloat16 h0 = __float2bfloat16(a0);
        __nv_bfloat16 h1 = __float2bfloat16(a1);
        ATThi16[r * 72 + lane]      = h0;
        ATThi16[r * 72 + lane + 32] = h1;
        ATTlo16[r * 72 + lane]      = __float2bfloat16(a0 - __bfloat162float(h0));
        ATTlo16[r * 72 + lane + 32] = __float2bfloat16(a1 - __bfloat162float(h1));
    }
    // stage PT hi/lo into REG0 (P no longer needed): 18432 words = 4608 uint4
    {
        const uint4* src = reinterpret_cast<const uint4*>(g_PTb);
        uint4* dst = reinterpret_cast<uint4*>(REG0W);
        #pragma unroll
        for (int i = tid; i < 4608; i += NTHR) dst[i] = src[i];
    }
    __syncthreads();

    // ---- PF MMA: delta = ATT @ P (64x256, K=64); PF = O - delta -> split bf16 ----
    {
        int wm = w & 3;           // m tile (16 rows)
        int wn = w >> 2;          // 64-col group (8 n8 tiles)
        float acc[8][4];
        #pragma unroll
        for (int nt = 0; nt < 8; nt++)
            #pragma unroll
            for (int i = 0; i < 4; i++) acc[nt][i] = 0.f;

        #pragma unroll
        for (int ks = 0; ks < 4; ks++) {
            int kw = ks * 8;
            int rb  = (wm * 16 + g) * 36;
            int rb8 = rb + 8 * 36;
            unsigned int ah[4], al[4];
            ah[0] = ATThiW[rb  + kw + tig];     ah[1] = ATThiW[rb8 + kw + tig];
            ah[2] = ATThiW[rb  + kw + 4 + tig]; ah[3] = ATThiW[rb8 + kw + 4 + tig];
            al[0] = ATTloW[rb  + kw + tig];     al[1] = ATTloW[rb8 + kw + tig];
            al[2] = ATTloW[rb  + kw + 4 + tig]; al[3] = ATTloW[rb8 + kw + 4 + tig];
            #pragma unroll
            for (int nt = 0; nt < 8; nt++) {
                int n = wn * 64 + nt * 8 + g;
                unsigned int bh0 = REG0W[n * 36 + kw + tig];
                unsigned int bh1 = REG0W[n * 36 + kw + 4 + tig];
                unsigned int bl0 = REG0W[9216 + n * 36 + kw + tig];
                unsigned int bl1 = REG0W[9216 + n * 36 + kw + 4 + tig];
                mma_bf16(acc[nt], ah, bh0, bh1);
                mma_bf16(acc[nt], ah, bl0, bl1);
                mma_bf16(acc[nt], al, bh0, bh1);
            }
        }
        __syncthreads();   // LG scratch fully consumed before PF overwrite
        #pragma unroll
        for (int nt = 0; nt < 8; nt++) {
            int wcol = wn * 32 + nt * 4 + tig;      // word col (= ncol/2)
            #pragma unroll
            for (int half = 0; half < 2; half++) {
                int r = wm * 16 + g + 8 * half;
                int widx = r * 132 + wcol;
                __nv_bfloat162 h = *reinterpret_cast<__nv_bfloat162*>(&OhiW[widx]);
                __nv_bfloat162 l = *reinterpret_cast<__nv_bfloat162*>(&OloW[widx]);
                float o0 = __bfloat162float(h.x) + __bfloat162float(l.x);
                float o1 = __bfloat162float(h.y) + __bfloat162float(l.y);
                float p0 = o0 - acc[nt][2 * half];
                float p1 = o1 - acc[nt][2 * half + 1];
                __nv_bfloat16 ph0 = __float2bfloat16(p0);
                __nv_bfloat16 ph1 = __float2bfloat16(p1);
                __nv_bfloat16 pl0 = __float2bfloat16(p0 - __bfloat162float(ph0));
                __nv_bfloat16 pl1 = __float2bfloat16(p1 - __bfloat162float(ph1));
                PFhiW[widx] = pack_bf16x2(ph0, ph1);
                PFloW[widx] = pack_bf16x2(pl0, pl1);
            }
        }
    }

    // ---- gate MMA: Z = PF @ W (split bf16, 3 products), W staged in 4 chunks ----
    {
        int wm = w & 1;          // 32-row supergroup
        int wn = w >> 1;         // 32-col group

        float acc[2][4][4];
        #pragma unroll
        for (int mt = 0; mt < 2; mt++)
            #pragma unroll
            for (int nt = 0; nt < 4; nt++)
                #pragma unroll
                for (int i = 0; i < 4; i++) acc[mt][nt][i] = 0.f;

        #pragma unroll
        for (int c = 0; c < 4; c++) {
            __syncthreads();
            {
                const uint4* src = reinterpret_cast<const uint4*>(g_Wt + c * WT_CHUNK_WORDS);
                uint4* dst = reinterpret_cast<uint4*>(REG0W);
                #pragma unroll
                for (int i = tid; i < 4608; i += NTHR) dst[i] = src[i];
            }
            __syncthreads();

            #pragma unroll
            for (int ks = 0; ks < 4; ks++) {
                int kw  = c * 32 + ks * 8;
                int lkw = ks * 8;
                unsigned int ah[2][4], al[2][4];
                #pragma unroll
                for (int mt = 0; mt < 2; mt++) {
                    int rb  = (wm * 32 + mt * 16 + g) * 132;
                    int rb8 = rb + 8 * 132;
                    ah[mt][0] = PFhiW[rb  + kw + tig];     ah[mt][1] = PFhiW[rb8 + kw + tig];
                    ah[mt][2] = PFhiW[rb  + kw + 4 + tig]; ah[mt][3] = PFhiW[rb8 + kw + 4 + tig];
                    al[mt][0] = PFloW[rb  + kw + tig];     al[mt][1] = PFloW[rb8 + kw + tig];
                    al[mt][2] = PFloW[rb  + kw + 4 + tig]; al[mt][3] = PFloW[rb8 + kw + 4 + tig];
                }
                #pragma unroll
                for (int nt = 0; nt < 4; nt++) {
                    int n = wn * 32 + nt * 8 + g;
                    unsigned int bh0 = REG0W[n * 36 + lkw + tig];
                    unsigned int bh1 = REG0W[n * 36 + lkw + 4 + tig];
                    unsigned int bl0 = REG0W[9216 + n * 36 + lkw + tig];
                    unsigned int bl1 = REG0W[9216 + n * 36 + lkw + 4 + tig];
                    #pragma unroll
                    for (int mt = 0; mt < 2; mt++) {
                        mma_bf16(acc[mt][nt], ah[mt], bh0, bh1);
                        mma_bf16(acc[mt][nt], ah[mt], bl0, bl1);
                        mma_bf16(acc[mt][nt], al[mt], bh0, bh1);
                    }
                }
            }
        }

        // epilogue: gate + blend + store
        #pragma unroll
        for (int mt = 0; mt < 2; mt++) {
            #pragma unroll
            for (int nt = 0; nt < 4; nt++) {
                int ncol = wn * 32 + nt * 8 + 2 * tig;
                int wcol = ncol >> 1;
                #pragma unroll
                for (int half = 0; half < 2; half++) {
                    int r = wm * 32 + mt * 16 + g + 8 * half;
                    int n = base + r;
                    if (n >= NN) continue;
                    int widx = r * 132 + wcol;
                    __nv_bfloat162 oh = *reinterpret_cast<__nv_bfloat162*>(&OhiW[widx]);
                    __nv_bfloat162 ol = *reinterpret_cast<__nv_bfloat162*>(&OloW[widx]);
                    __nv_bfloat162 ph = *reinterpret_cast<__nv_bfloat162*>(&PFhiW[widx]);
                    __nv_bfloat162 pl = *reinterpret_cast<__nv_bfloat162*>(&PFloW[widx]);
                    float o0  = __bfloat162float(oh.x) + __bfloat162float(ol.x);
                    float o1  = __bfloat162float(oh.y) + __bfloat162float(ol.y);
                    float pf0 = __bfloat162float(ph.x) + __bfloat162float(pl.x);
                    float pf1 = __bfloat162float(ph.y) + __bfloat162float(pl.y);
                    float z0 = acc[mt][nt][2 * half];
                    float z1 = acc[mt][nt][2 * half + 1];
                    float g0 = 1.f / (1.f + expf(-z0));
                    float g1 = 1.f / (1.f + expf(-z1));
                    float2 res;
                    res.x = g0 * o0 + (1.f - g0) * pf0;
                    res.y = g1 * o1 + (1.f - g1) * pf1;
                    *reinterpret_cast<float2*>(out + (size_t)n * CC + ncol) = res;
                }
            }
        }
    }
}

// ---------------- launch ----------------
extern "C" void kernel_launch(void* const* d_in, const int* in_sizes, int n_in,
                              void* d_out, int out_size) {
    const float* features  = (const float*)d_in[0];
    const float* rel_emb   = (const float*)d_in[1];
    const float* sparse_v  = (const float*)d_in[2];
    const float* attn_k    = (const float*)d_in[3];
    const float* proxy     = (const float*)d_in[4];
    const float* gate_k    = (const float*)d_in[5];
    const int*   adj       = (const int*)d_in[6];
    const int*   sparse_i  = (const int*)d_in[7];
    const int*   neigh     = (const int*)d_in[9];
    float* out = (float*)d_out;

    prep_kernel<<<RR + PX, 128>>>(rel_emb, attn_k, proxy);
    wconv_kernel<<<192, 256>>>(gate_k, proxy);
    zero_bounds_kernel<<<(NN + 255) / 256, 256>>>();
    detect_bounds_kernel<<<(EE + 255) / 256, 256>>>(adj);
    agg_kernel<<<(NN * 32 + 255) / 256, 256>>>(features, rel_emb, sparse_v, adj, sparse_i);

    size_t smem = (size_t)SMEM_WORDS * sizeof(float);
    cudaFuncSetAttribute(final_kernel, cudaFuncAttributeMaxDynamicSharedMemorySize, (int)smem);
    final_kernel<<<(NN + TILE - 1) / TILE, NTHR, smem>>>(features, neigh, out);
}

// round 6
// speedup vs baseline: 3.7854x; 1.1231x over previous
#include <cuda_runtime.h>
#include <cuda_bf16.h>
#include <math.h>

// Problem constants (fixed by setup_inputs)
#define NN 50000
#define EE 400000
#define RR 1000
#define FF 128
#define K1 1000
#define PX 64      // proxy rows
#define CC 256     // concat dim

// ---------------- scratch (device globals) ----------------
__device__ float g_nf0[(size_t)NN * FF];
__device__ float g_nf1[(size_t)NN * FF];
__device__ float g_relnsq[RR];
__device__ float g_reldot[RR * 2];
__device__ float g_invp[PX];
__device__ int   g_rb[NN];
__device__ int   g_re[NN];

// W^T split bf16 per 64-k chunk: [chunk][hi(9216)|lo(9216)], word = n*36 + k_local/2
#define WT_CHUNK_WORDS 18432
__device__ __align__(16) unsigned int g_Wt[4 * WT_CHUNK_WORDS];
// proxy split bf16, k-major: [hi(64*132)|lo], word = n*132 + k/2
__device__ __align__(16) unsigned int g_Pb[16896];
// proxy^T split bf16, n-major: [hi(256*36)|lo], word = n*36 + k/2
__device__ __align__(16) unsigned int g_PTb[18432];

__inline__ __device__ float warp_sum(float v) {
    #pragma unroll
    for (int o = 16; o; o >>= 1) v += __shfl_xor_sync(0xffffffffu, v, o);
    return v;
}
__inline__ __device__ unsigned int pack_bf16x2(__nv_bfloat16 lo, __nv_bfloat16 hi) {
    __nv_bfloat162 v(lo, hi);
    return *reinterpret_cast<unsigned int*>(&v);
}
__inline__ __device__ void mma_bf16(float* d, const unsigned int* a,
                                    unsigned int b0, unsigned int b1) {
    asm volatile(
        "mma.sync.aligned.m16n8k16.row.col.f32.bf16.bf16.f32 "
        "{%0,%1,%2,%3}, {%4,%5,%6,%7}, {%8,%9}, {%0,%1,%2,%3};"
        : "+f"(d[0]), "+f"(d[1]), "+f"(d[2]), "+f"(d[3])
        : "r"(a[0]), "r"(a[1]), "r"(a[2]), "r"(a[3]), "r"(b0), "r"(b1));
}

// ---------------- Kernel A: per-relation norms & attn dots, proxy inv-norms ----------------
__global__ void prep_kernel(const float* __restrict__ rel_emb,
                            const float* __restrict__ attn,
                            const float* __restrict__ proxy) {
    int b = blockIdx.x;
    int t = threadIdx.x;
    int lane = t & 31, w = t >> 5;
    __shared__ float sh[3][4];

    if (b < RR) {
        float v  = rel_emb[b * FF + t];
        float a0 = attn[t];
        float a1 = attn[FF + t];
        float nsq = warp_sum(v * v);
        float d0  = warp_sum(v * a0);
        float d1  = warp_sum(v * a1);
        if (lane == 0) { sh[0][w] = nsq; sh[1][w] = d0; sh[2][w] = d1; }
        __syncthreads();
        if (t == 0) {
            g_relnsq[b]       = sh[0][0] + sh[0][1] + sh[0][2] + sh[0][3];
            g_reldot[2*b]     = sh[1][0] + sh[1][1] + sh[1][2] + sh[1][3];
            g_reldot[2*b + 1] = sh[2][0] + sh[2][1] + sh[2][2] + sh[2][3];
        }
    } else {
        int k = b - RR;
        float p0 = proxy[k * CC + t];
        float p1 = proxy[k * CC + 128 + t];
        float s = warp_sum(p0 * p0 + p1 * p1);
        if (lane == 0) sh[0][w] = s;
        __syncthreads();
        if (t == 0) {
            float tot = sh[0][0] + sh[0][1] + sh[0][2] + sh[0][3];
            g_invp[k] = 1.0f / sqrtf(fmaxf(tot, 1e-12f));
        }
    }
}

// ---------------- Kernel A2: W & proxy -> split bf16; also zero bounds ----------------
__global__ void wconv_kernel(const float* __restrict__ W, const float* __restrict__ proxy) {
    int tid = blockIdx.x * blockDim.x + threadIdx.x;
    if (tid < 256 * 128) {
        int n  = tid >> 7;
        int kp = tid & 127;
        int k  = kp * 2;
        float w0 = W[(size_t)k * CC + n];
        float w1 = W[(size_t)(k + 1) * CC + n];
        __nv_bfloat16 h0 = __float2bfloat16(w0);
        __nv_bfloat16 h1 = __float2bfloat16(w1);
        __nv_bfloat16 l0 = __float2bfloat16(w0 - __bfloat162float(h0));
        __nv_bfloat16 l1 = __float2bfloat16(w1 - __bfloat162float(h1));
        int c  = k >> 6;
        int lw = (k & 63) >> 1;
        int idx = c * WT_CHUNK_WORDS + n * 36 + lw;
        g_Wt[idx]        = pack_bf16x2(h0, h1);
        g_Wt[idx + 9216] = pack_bf16x2(l0, l1);
    } else if (tid < 256 * 128 + 64 * 128) {
        int t2 = tid - 256 * 128;
        int n  = t2 >> 7;
        int kp = t2 & 127;
        int k  = kp * 2;
        float w0 = proxy[(size_t)n * CC + k];
        float w1 = proxy[(size_t)n * CC + k + 1];
        __nv_bfloat16 h0 = __float2bfloat16(w0);
        __nv_bfloat16 h1 = __float2bfloat16(w1);
        __nv_bfloat16 l0 = __float2bfloat16(w0 - __bfloat162float(h0));
        __nv_bfloat16 l1 = __float2bfloat16(w1 - __bfloat162float(h1));
        g_Pb[n * 132 + kp]        = pack_bf16x2(h0, h1);
        g_Pb[n * 132 + kp + 8448] = pack_bf16x2(l0, l1);
    } else if (tid < 256 * 128 + 64 * 128 + 256 * 32) {
        int t3 = tid - 256 * 128 - 64 * 128;
        int n  = t3 >> 5;
        int kw = t3 & 31;
        int k  = kw * 2;
        float w0 = proxy[(size_t)k * CC + n];
        float w1 = proxy[(size_t)(k + 1) * CC + n];
        __nv_bfloat16 h0 = __float2bfloat16(w0);
        __nv_bfloat16 h1 = __float2bfloat16(w1);
        __nv_bfloat16 l0 = __float2bfloat16(w0 - __bfloat162float(h0));
        __nv_bfloat16 l1 = __float2bfloat16(w1 - __bfloat162float(h1));
        g_PTb[n * 36 + kw]        = pack_bf16x2(h0, h1);
        g_PTb[n * 36 + kw + 9216] = pack_bf16x2(l0, l1);
    } else {
        int z = tid - (256 * 128 + 64 * 128 + 256 * 32);
        if (z < NN) { g_rb[z] = 0; g_re[z] = 0; }
    }
}

// ---------------- Kernel B: row segment bounds ----------------
__global__ void detect_bounds_kernel(const int* __restrict__ adj) {
    int e = blockIdx.x * blockDim.x + threadIdx.x;
    if (e >= EE) return;
    int r = adj[2 * e];
    if (e == 0 || adj[2 * (e - 1)] != r) g_rb[r] = e;
    if (e == EE - 1 || adj[2 * (e + 1)] != r) g_re[r] = e + 1;
}

// ---------------- Kernel C: single-pass softmax + reflected-neighbor aggregation --------
// one warp per row; per-edge scalars precomputed lane-parallel, broadcast via shfl.idx
__global__ __launch_bounds__(256) void agg_kernel(const float* __restrict__ feats,
                                                  const float* __restrict__ rel_emb,
                                                  const float* __restrict__ sv,
                                                  const int* __restrict__ adj,
                                                  const int* __restrict__ si) {
    int gw = (blockIdx.x * blockDim.x + threadIdx.x) >> 5;
    int lane = threadIdx.x & 31;
    if (gw >= NN) return;

    int e0 = g_rb[gw], e1 = g_re[gw];
    float4* o0 = reinterpret_cast<float4*>(g_nf0 + (size_t)gw * FF);
    float4* o1 = reinterpret_cast<float4*>(g_nf1 + (size_t)gw * FF);

    if (e0 >= e1) {
        float4 z = make_float4(0.f, 0.f, 0.f, 0.f);
        o0[lane] = z; o1[lane] = z;
        return;
    }

    const float2* rd2 = reinterpret_cast<const float2*>(g_reldot);

    float4 a0 = make_float4(0.f, 0.f, 0.f, 0.f);
    float4 a1 = make_float4(0.f, 0.f, 0.f, 0.f);
    float s0 = 0.f, s1 = 0.f;

    for (int c0 = e0; c0 < e1; c0 += 32) {
        int e = c0 + lane;
        int   pk  = 0;
        float w0p = 0.f, w1p = 0.f, fp = 0.f;
        if (e < e1) {
            float s = sv[e];
            int col = adj[2 * e + 1];
            int r   = si[2 * e + 1];
            float2 rd = rd2[r];
            w0p = __expf(s * rd.x);             // no max shift: |s*rd| small by construction
            w1p = __expf(s * rd.y);
            fp  = s * rsqrtf(fmaxf(s * s * g_relnsq[r], 1e-12f));
            pk  = col | (r << 17);              // col < 2^17, r < 1000
        }
        int cnt = min(32, e1 - c0);
        for (int j = 0; j < cnt; j++) {
            int   pkj = __shfl_sync(0xffffffffu, pk,  j);
            float f   = __shfl_sync(0xffffffffu, fp,  j);
            float w0  = __shfl_sync(0xffffffffu, w0p, j);
            float w1  = __shfl_sync(0xffffffffu, w1p, j);
            int col = pkj & 0x1ffff;
            int r   = pkj >> 17;

            float4 u = reinterpret_cast<const float4*>(rel_emb + (size_t)r * FF)[lane];
            u.x *= f; u.y *= f; u.z *= f; u.w *= f;
            float4 x = __ldg(reinterpret_cast<const float4*>(feats + (size_t)col * FF) + lane);

            float d = x.x * u.x + x.y * u.y + x.z * u.z + x.w * u.w;
            d = warp_sum(d);
            float t2 = 2.f * d;
            float4 y;
            y.x = x.x - t2 * u.x; y.y = x.y - t2 * u.y;
            y.z = x.z - t2 * u.z; y.w = x.w - t2 * u.w;

            s0 += w0; s1 += w1;
            a0.x += w0 * y.x; a0.y += w0 * y.y; a0.z += w0 * y.z; a0.w += w0 * y.w;
            a1.x += w1 * y.x; a1.y += w1 * y.y; a1.z += w1 * y.z; a1.w += w1 * y.w;
        }
    }
    float i0 = 1.f / s0, i1 = 1.f / s1;
    a0.x *= i0; a0.y *= i0; a0.z *= i0; a0.w *= i0;
    a1.x *= i1; a1.y *= i1; a1.z *= i1; a1.w *= i1;
    o0[lane] = a0;
    o1[lane] = a1;
}

// ---------------- Kernel E: fused tail; all three GEMMs on tensor cores ----------------
#define TILE 64
#define NTHR 512
// smem word offsets
#define OFF_REG0   0            // P stage (16896) / PT stage (18432) / Wt chunk (18432)
#define OFF_OHI    18432        // 64 x 132 words (bf16x2)
#define OFF_OLO    26880
#define OFF_SCR    35328        // logits fp32 (64x65) -> PFhi (64x132 words)
#define OFF_PFLO   43776
#define OFF_ATTHI  52224        // 64 x 36 words
#define OFF_ATTLO  54528
#define OFF_INVN   56832
#define OFF_INVP   56896
#define SMEM_WORDS 56960        // 227,840 B

__global__ __launch_bounds__(NTHR) void final_kernel(const float* __restrict__ feats,
                                                     const int* __restrict__ neigh,
                                                     float* __restrict__ out) {
    extern __shared__ float sm[];
    unsigned int* REG0W  = reinterpret_cast<unsigned int*>(sm + OFF_REG0);
    unsigned int* OhiW   = reinterpret_cast<unsigned int*>(sm + OFF_OHI);
    unsigned int* OloW   = reinterpret_cast<unsigned int*>(sm + OFF_OLO);
    __nv_bfloat16* Ohi16 = reinterpret_cast<__nv_bfloat16*>(OhiW);
    __nv_bfloat16* Olo16 = reinterpret_cast<__nv_bfloat16*>(OloW);
    float* LG            = sm + OFF_SCR;   // logits scratch, pitch 65
    unsigned int* PFhiW  = reinterpret_cast<unsigned int*>(sm + OFF_SCR);
    unsigned int* PFloW  = reinterpret_cast<unsigned int*>(sm + OFF_PFLO);
    unsigned int* ATThiW = reinterpret_cast<unsigned int*>(sm + OFF_ATTHI);
    unsigned int* ATTloW = reinterpret_cast<unsigned int*>(sm + OFF_ATTLO);
    __nv_bfloat16* ATThi16 = reinterpret_cast<__nv_bfloat16*>(ATThiW);
    __nv_bfloat16* ATTlo16 = reinterpret_cast<__nv_bfloat16*>(ATTloW);
    float* INVN = sm + OFF_INVN;
    float* INVP = sm + OFF_INVP;

    int tid = threadIdx.x;
    int lane = tid & 31, w = tid >> 5;       // 16 warps
    int g   = lane >> 2;
    int tig = lane & 3;
    int base = blockIdx.x * TILE;

    if (tid < PX) INVP[tid] = g_invp[tid];

    // stage P hi/lo (16896 words = 4224 uint4)
    {
        const uint4* src = reinterpret_cast<const uint4*>(g_Pb);
        uint4* dst = reinterpret_cast<uint4*>(REG0W);
        #pragma unroll
        for (int i = tid; i < 4224; i += NTHR) dst[i] = src[i];
    }
    // build O tile as split bf16: concat(features, 0.5*(nf0 + nf1-swapped))
    {
        int col = tid & 255;
        for (int rr = tid >> 8; rr < TILE; rr += 2) {
            int n = base + rr;
            float v = 0.f;
            if (n < NN) {
                if (col < 128) {
                    v = feats[(size_t)n * FF + col];
                } else {
                    int m = (n < K1) ? neigh[n] : n;
                    int jj = col - 128;
                    v = 0.5f * (g_nf0[(size_t)n * FF + jj] + g_nf1[(size_t)m * FF + jj]);
                }
            }
            __nv_bfloat16 h = __float2bfloat16(v);
            __nv_bfloat16 l = __float2bfloat16(v - __bfloat162float(h));
            Ohi16[rr * 264 + col] = h;
            Olo16[rr * 264 + col] = l;
        }
    }
    __syncthreads();

    // row inverse norms
    #pragma unroll
    for (int q = 0; q < 4; q++) {
        int r = w * 4 + q;
        float s = 0.f;
        #pragma unroll
        for (int m = 0; m < 4; m++) {
            int j = r * 132 + lane + 32 * m;
            __nv_bfloat162 h = *reinterpret_cast<__nv_bfloat162*>(&OhiW[j]);
            __nv_bfloat162 l = *reinterpret_cast<__nv_bfloat162*>(&OloW[j]);
            float v0 = __bfloat162float(h.x) + __bfloat162float(l.x);
            float v1 = __bfloat162float(h.y) + __bfloat162float(l.y);
            s += v0 * v0 + v1 * v1;
        }
        s = warp_sum(s);
        if (lane == 0) INVN[r] = rsqrtf(fmaxf(s, 1e-12f));
    }
    __syncthreads();

    // ---- logits MMA: L = O @ P^T (64x64, K=256), split bf16 ----
    {
        int mt  = w & 3;
        int nt2 = w >> 2;
        float acc[2][4];
        #pragma unroll
        for (int nt = 0; nt < 2; nt++)
            #pragma unroll
            for (int i = 0; i < 4; i++) acc[nt][i] = 0.f;

        #pragma unroll 4
        for (int ks = 0; ks < 16; ks++) {
            int kw = ks * 8;
            int rb  = (mt * 16 + g) * 132;
            int rb8 = rb + 8 * 132;
            unsigned int ah[4], al[4];
            ah[0] = OhiW[rb  + kw + tig];     ah[1] = OhiW[rb8 + kw + tig];
            ah[2] = OhiW[rb  + kw + 4 + tig]; ah[3] = OhiW[rb8 + kw + 4 + tig];
            al[0] = OloW[rb  + kw + tig];     al[1] = OloW[rb8 + kw + tig];
            al[2] = OloW[rb  + kw + 4 + tig]; al[3] = OloW[rb8 + kw + 4 + tig];
            #pragma unroll
            for (int nt = 0; nt < 2; nt++) {
                int n = nt2 * 16 + nt * 8 + g;
                unsigned int bh0 = REG0W[n * 132 + kw + tig];
                unsigned int bh1 = REG0W[n * 132 + kw + 4 + tig];
                unsigned int bl0 = REG0W[8448 + n * 132 + kw + tig];
                unsigned int bl1 = REG0W[8448 + n * 132 + kw + 4 + tig];
                mma_bf16(acc[nt], ah, bh0, bh1);
                mma_bf16(acc[nt], ah, bl0, bl1);
                mma_bf16(acc[nt], al, bh0, bh1);
            }
        }
        #pragma unroll
        for (int nt = 0; nt < 2; nt++) {
            int ncol = nt2 * 16 + nt * 8 + 2 * tig;
            float ip0 = INVP[ncol], ip1 = INVP[ncol + 1];
            #pragma unroll
            for (int half = 0; half < 2; half++) {
                int r = mt * 16 + g + 8 * half;
                float invn = INVN[r];
                LG[r * 65 + ncol]     = acc[nt][2 * half]     * invn * ip0;
                LG[r * 65 + ncol + 1] = acc[nt][2 * half + 1] * invn * ip1;
            }
        }
    }
    __syncthreads();

    // ---- softmax (|logit| <= 1: no max shift) -> split bf16 ATT ----
    #pragma unroll
    for (int q = 0; q < 4; q++) {
        int r = w * 4 + q;
        float l0 = LG[r * 65 + lane];
        float l1 = LG[r * 65 + lane + 32];
        float e0v = __expf(l0);
        float e1v = __expf(l1);
        float s = warp_sum(e0v + e1v);
        float inv = 1.f / s;
        float a0 = e0v * inv, a1 = e1v * inv;
        __nv_bfloat16 h0 = __float2bfloat16(a0);
        __nv_bfloat16 h1 = __float2bfloat16(a1);
        ATThi16[r * 72 + lane]      = h0;
        ATThi16[r * 72 + lane + 32] = h1;
        ATTlo16[r * 72 + lane]      = __float2bfloat16(a0 - __bfloat162float(h0));
        ATTlo16[r * 72 + lane + 32] = __float2bfloat16(a1 - __bfloat162float(h1));
    }
    // stage PT hi/lo into REG0
    {
        const uint4* src = reinterpret_cast<const uint4*>(g_PTb);
        uint4* dst = reinterpret_cast<uint4*>(REG0W);
        #pragma unroll
        for (int i = tid; i < 4608; i += NTHR) dst[i] = src[i];
    }
    __syncthreads();

    // ---- PF MMA: delta = ATT @ P (64x256, K=64); PF = O - delta -> split bf16 ----
    {
        int wm = w & 3;
        int wn = w >> 2;
        float acc[8][4];
        #pragma unroll
        for (int nt = 0; nt < 8; nt++)
            #pragma unroll
            for (int i = 0; i < 4; i++) acc[nt][i] = 0.f;

        #pragma unroll
        for (int ks = 0; ks < 4; ks++) {
            int kw = ks * 8;
            int rb  = (wm * 16 + g) * 36;
            int rb8 = rb + 8 * 36;
            unsigned int ah[4], al[4];
            ah[0] = ATThiW[rb  + kw + tig];     ah[1] = ATThiW[rb8 + kw + tig];
            ah[2] = ATThiW[rb  + kw + 4 + tig]; ah[3] = ATThiW[rb8 + kw + 4 + tig];
            al[0] = ATTloW[rb  + kw + tig];     al[1] = ATTloW[rb8 + kw + tig];
            al[2] = ATTloW[rb  + kw + 4 + tig]; al[3] = ATTloW[rb8 + kw + 4 + tig];
            #pragma unroll
            for (int nt = 0; nt < 8; nt++) {
                int n = wn * 64 + nt * 8 + g;
                unsigned int bh0 = REG0W[n * 36 + kw + tig];
                unsigned int bh1 = REG0W[n * 36 + kw + 4 + tig];
                unsigned int bl0 = REG0W[9216 + n * 36 + kw + tig];
                unsigned int bl1 = REG0W[9216 + n * 36 + kw + 4 + tig];
                mma_bf16(acc[nt], ah, bh0, bh1);
                mma_bf16(acc[nt], ah, bl0, bl1);
                mma_bf16(acc[nt], al, bh0, bh1);
            }
        }
        __syncthreads();   // LG scratch consumed before PF overwrite
        #pragma unroll
        for (int nt = 0; nt < 8; nt++) {
            int wcol = wn * 32 + nt * 4 + tig;
            #pragma unroll
            for (int half = 0; half < 2; half++) {
                int r = wm * 16 + g + 8 * half;
                int widx = r * 132 + wcol;
                __nv_bfloat162 h = *reinterpret_cast<__nv_bfloat162*>(&OhiW[widx]);
                __nv_bfloat162 l = *reinterpret_cast<__nv_bfloat162*>(&OloW[widx]);
                float o0 = __bfloat162float(h.x) + __bfloat162float(l.x);
                float o1 = __bfloat162float(h.y) + __bfloat162float(l.y);
                float p0 = o0 - acc[nt][2 * half];
                float p1 = o1 - acc[nt][2 * half + 1];
                __nv_bfloat16 ph0 = __float2bfloat16(p0);
                __nv_bfloat16 ph1 = __float2bfloat16(p1);
                __nv_bfloat16 pl0 = __float2bfloat16(p0 - __bfloat162float(ph0));
                __nv_bfloat16 pl1 = __float2bfloat16(p1 - __bfloat162float(ph1));
                PFhiW[widx] = pack_bf16x2(ph0, ph1);
                PFloW[widx] = pack_bf16x2(pl0, pl1);
            }
        }
    }

    // ---- gate MMA: Z = PF @ W, W staged in 4 chunks ----
    {
        int wm = w & 1;
        int wn = w >> 1;

        float acc[2][4][4];
        #pragma unroll
        for (int mt = 0; mt < 2; mt++)
            #pragma unroll
            for (int nt = 0; nt < 4; nt++)
                #pragma unroll
                for (int i = 0; i < 4; i++) acc[mt][nt][i] = 0.f;

        #pragma unroll
        for (int c = 0; c < 4; c++) {
            __syncthreads();
            {
                const uint4* src = reinterpret_cast<const uint4*>(g_Wt + c * WT_CHUNK_WORDS);
                uint4* dst = reinterpret_cast<uint4*>(REG0W);
                #pragma unroll
                for (int i = tid; i < 4608; i += NTHR) dst[i] = src[i];
            }
            __syncthreads();

            #pragma unroll
            for (int ks = 0; ks < 4; ks++) {
                int kw  = c * 32 + ks * 8;
                int lkw = ks * 8;
                unsigned int ah[2][4], al[2][4];
                #pragma unroll
                for (int mt = 0; mt < 2; mt++) {
                    int rb  = (wm * 32 + mt * 16 + g) * 132;
                    int rb8 = rb + 8 * 132;
                    ah[mt][0] = PFhiW[rb  + kw + tig];     ah[mt][1] = PFhiW[rb8 + kw + tig];
                    ah[mt][2] = PFhiW[rb  + kw + 4 + tig]; ah[mt][3] = PFhiW[rb8 + kw + 4 + tig];
                    al[mt][0] = PFloW[rb  + kw + tig];     al[mt][1] = PFloW[rb8 + kw + tig];
                    al[mt][2] = PFloW[rb  + kw + 4 + tig]; al[mt][3] = PFloW[rb8 + kw + 4 + tig];
                }
                #pragma unroll
                for (int nt = 0; nt < 4; nt++) {
                    int n = wn * 32 + nt * 8 + g;
                    unsigned int bh0 = REG0W[n * 36 + lkw + tig];
                    unsigned int bh1 = REG0W[n * 36 + lkw + 4 + tig];
                    unsigned int bl0 = REG0W[9216 + n * 36 + lkw + tig];
                    unsigned int bl1 = REG0W[9216 + n * 36 + lkw + 4 + tig];
                    #pragma unroll
                    for (int mt = 0; mt < 2; mt++) {
                        mma_bf16(acc[mt][nt], ah[mt], bh0, bh1);
                        mma_bf16(acc[mt][nt], ah[mt], bl0, bl1);
                        mma_bf16(acc[mt][nt], al[mt], bh0, bh1);
                    }
                }
            }
        }

        // epilogue: gate + blend + store
        #pragma unroll
        for (int mt = 0; mt < 2; mt++) {
            #pragma unroll
            for (int nt = 0; nt < 4; nt++) {
                int ncol = wn * 32 + nt * 8 + 2 * tig;
                int wcol = ncol >> 1;
                #pragma unroll
                for (int half = 0; half < 2; half++) {
                    int r = wm * 32 + mt * 16 + g + 8 * half;
                    int n = base + r;
                    if (n >= NN) continue;
                    int widx = r * 132 + wcol;
                    __nv_bfloat162 oh = *reinterpret_cast<__nv_bfloat162*>(&OhiW[widx]);
                    __nv_bfloat162 ol = *reinterpret_cast<__nv_bfloat162*>(&OloW[widx]);
                    __nv_bfloat162 ph = *reinterpret_cast<__nv_bfloat162*>(&PFhiW[widx]);
                    __nv_bfloat162 pl = *reinterpret_cast<__nv_bfloat162*>(&PFloW[widx]);
                    float o0  = __bfloat162float(oh.x) + __bfloat162float(ol.x);
                    float o1  = __bfloat162float(oh.y) + __bfloat162float(ol.y);
                    float pf0 = __bfloat162float(ph.x) + __bfloat162float(pl.x);
                    float pf1 = __bfloat162float(ph.y) + __bfloat162float(pl.y);
                    float z0 = acc[mt][nt][2 * half];
                    float z1 = acc[mt][nt][2 * half + 1];
                    float g0 = 1.f / (1.f + __expf(-z0));
                    float g1 = 1.f / (1.f + __expf(-z1));
                    float2 res;
                    res.x = g0 * o0 + (1.f - g0) * pf0;
                    res.y = g1 * o1 + (1.f - g1) * pf1;
                    *reinterpret_cast<float2*>(out + (size_t)n * CC + ncol) = res;
                }
            }
        }
    }
}

// ---------------- launch ----------------
extern "C" void kernel_launch(void* const* d_in, const int* in_sizes, int n_in,
                              void* d_out, int out_size) {
    const float* features  = (const float*)d_in[0];
    const float* rel_emb   = (const float*)d_in[1];
    const float* sparse_v  = (const float*)d_in[2];
    const float* attn_k    = (const float*)d_in[3];
    const float* proxy     = (const float*)d_in[4];
    const float* gate_k    = (const float*)d_in[5];
    const int*   adj       = (const int*)d_in[6];
    const int*   sparse_i  = (const int*)d_in[7];
    const int*   neigh     = (const int*)d_in[9];
    float* out = (float*)d_out;

    prep_kernel<<<RR + PX, 128>>>(rel_emb, attn_k, proxy);
    // conversions + zero-bounds fused: 49152 conversion threads + 50000 zero threads
    wconv_kernel<<<(49152 + NN + 255) / 256, 256>>>(gate_k, proxy);
    detect_bounds_kernel<<<(EE + 255) / 256, 256>>>(adj);
    agg_kernel<<<(NN * 32 + 255) / 256, 256>>>(features, rel_emb, sparse_v, adj, sparse_i);

    size_t smem = (size_t)SMEM_WORDS * sizeof(float);
    cudaFuncSetAttribute(final_kernel, cudaFuncAttributeMaxDynamicSharedMemorySize, (int)smem);
    final_kernel<<<(NN + TILE - 1) / TILE, NTHR, smem>>>(features, neigh, out);
}

// round 8
// speedup vs baseline: 3.8880x; 1.0271x over previous
#include <cuda_runtime.h>
#include <cuda_bf16.h>
#include <math.h>
#include <cstdint>

// Problem constants (fixed by setup_inputs)
#define NN 50000
#define EE 400000
#define RR 1000
#define FF 128
#define K1 1000
#define PX 64      // proxy rows
#define CC 256     // concat dim

// ---------------- scratch (device globals) ----------------
__device__ float g_nf0[(size_t)NN * FF];
__device__ float g_nf1[(size_t)NN * FF];
__device__ float g_relnsq[RR];
__device__ float g_reldot[RR * 2];
__device__ float g_invp[PX];
__device__ int   g_rb[NN];
__device__ int   g_re[NN];

// W^T split bf16 in 8 K=32 sub-chunks: [chunk][hi(4608)|lo(4608)], word = n*18 + klocal/2
#define WT_CHUNK_WORDS 9216
__device__ __align__(16) unsigned int g_Wt[8 * WT_CHUNK_WORDS];
// proxy split bf16, k-major: [hi(64*132)|lo], word = n*132 + k/2
__device__ __align__(16) unsigned int g_Pb[16896];
// proxy^T split bf16, n-major: [hi(256*36)|lo], word = n*36 + k/2
__device__ __align__(16) unsigned int g_PTb[18432];

__inline__ __device__ float warp_sum(float v) {
    #pragma unroll
    for (int o = 16; o; o >>= 1) v += __shfl_xor_sync(0xffffffffu, v, o);
    return v;
}
__inline__ __device__ unsigned int pack_bf16x2(__nv_bfloat16 lo, __nv_bfloat16 hi) {
    __nv_bfloat162 v(lo, hi);
    return *reinterpret_cast<unsigned int*>(&v);
}
__inline__ __device__ void mma_bf16(float* d, const unsigned int* a,
                                    unsigned int b0, unsigned int b1) {
    asm volatile(
        "mma.sync.aligned.m16n8k16.row.col.f32.bf16.bf16.f32 "
        "{%0,%1,%2,%3}, {%4,%5,%6,%7}, {%8,%9}, {%0,%1,%2,%3};"
        : "+f"(d[0]), "+f"(d[1]), "+f"(d[2]), "+f"(d[3])
        : "r"(a[0]), "r"(a[1]), "r"(a[2]), "r"(a[3]), "r"(b0), "r"(b1));
}
__device__ __forceinline__ unsigned int smem_u32(const void* p) {
    unsigned int a;
    asm volatile("{ .reg .u64 t; cvta.to.shared.u64 t, %1; cvt.u32.u64 %0, t; }"
                 : "=r"(a) : "l"(p));
    return a;
}
__device__ __forceinline__ void cp_async16(unsigned int dst, const void* src) {
    asm volatile("cp.async.cg.shared.global [%0], [%1], 16;" :: "r"(dst), "l"(src));
}
__device__ __forceinline__ void cp_commit() {
    asm volatile("cp.async.commit_group;" ::: "memory");
}
__device__ __forceinline__ void cp_wait0() {
    asm volatile("cp.async.wait_group 0;" ::: "memory");
}

// ---------------- Kernel A: per-relation norms & attn dots, proxy inv-norms ----------------
__global__ void prep_kernel(const float* __restrict__ rel_emb,
                            const float* __restrict__ attn,
                            const float* __restrict__ proxy) {
    int b = blockIdx.x;
    int t = threadIdx.x;
    int lane = t & 31, w = t >> 5;
    __shared__ float sh[3][4];

    if (b < RR) {
        float v  = rel_emb[b * FF + t];
        float a0 = attn[t];
        float a1 = attn[FF + t];
        float nsq = warp_sum(v * v);
        float d0  = warp_sum(v * a0);
        float d1  = warp_sum(v * a1);
        if (lane == 0) { sh[0][w] = nsq; sh[1][w] = d0; sh[2][w] = d1; }
        __syncthreads();
        if (t == 0) {
            g_relnsq[b]       = sh[0][0] + sh[0][1] + sh[0][2] + sh[0][3];
            g_reldot[2*b]     = sh[1][0] + sh[1][1] + sh[1][2] + sh[1][3];
            g_reldot[2*b + 1] = sh[2][0] + sh[2][1] + sh[2][2] + sh[2][3];
        }
    } else {
        int k = b - RR;
        float p0 = proxy[k * CC + t];
        float p1 = proxy[k * CC + 128 + t];
        float s = warp_sum(p0 * p0 + p1 * p1);
        if (lane == 0) sh[0][w] = s;
        __syncthreads();
        if (t == 0) {
            float tot = sh[0][0] + sh[0][1] + sh[0][2] + sh[0][3];
            g_invp[k] = 1.0f / sqrtf(fmaxf(tot, 1e-12f));
        }
    }
}

// ---------------- Kernel A2: W & proxy -> split bf16; also zero bounds ----------------
__global__ void wconv_kernel(const float* __restrict__ W, const float* __restrict__ proxy) {
    int tid = blockIdx.x * blockDim.x + threadIdx.x;
    if (tid < 256 * 128) {
        int n  = tid >> 7;
        int kp = tid & 127;
        int k  = kp * 2;
        float w0 = W[(size_t)k * CC + n];
        float w1 = W[(size_t)(k + 1) * CC + n];
        __nv_bfloat16 h0 = __float2bfloat16(w0);
        __nv_bfloat16 h1 = __float2bfloat16(w1);
        __nv_bfloat16 l0 = __float2bfloat16(w0 - __bfloat162float(h0));
        __nv_bfloat16 l1 = __float2bfloat16(w1 - __bfloat162float(h1));
        int c  = k >> 5;            // 8 chunks of K=32
        int lw = (k & 31) >> 1;     // 0..15
        int idx = c * WT_CHUNK_WORDS + n * 18 + lw;
        g_Wt[idx]        = pack_bf16x2(h0, h1);
        g_Wt[idx + 4608] = pack_bf16x2(l0, l1);
    } else if (tid < 256 * 128 + 64 * 128) {
        int t2 = tid - 256 * 128;
        int n  = t2 >> 7;
        int kp = t2 & 127;
        int k  = kp * 2;
        float w0 = proxy[(size_t)n * CC + k];
        float w1 = proxy[(size_t)n * CC + k + 1];
        __nv_bfloat16 h0 = __float2bfloat16(w0);
        __nv_bfloat16 h1 = __float2bfloat16(w1);
        __nv_bfloat16 l0 = __float2bfloat16(w0 - __bfloat162float(h0));
        __nv_bfloat16 l1 = __float2bfloat16(w1 - __bfloat162float(h1));
        g_Pb[n * 132 + kp]        = pack_bf16x2(h0, h1);
        g_Pb[n * 132 + kp + 8448] = pack_bf16x2(l0, l1);
    } else if (tid < 256 * 128 + 64 * 128 + 256 * 32) {
        int t3 = tid - 256 * 128 - 64 * 128;
        int n  = t3 >> 5;
        int kw = t3 & 31;
        int k  = kw * 2;
        float w0 = proxy[(size_t)k * CC + n];
        float w1 = proxy[(size_t)(k + 1) * CC + n];
        __nv_bfloat16 h0 = __float2bfloat16(w0);
        __nv_bfloat16 h1 = __float2bfloat16(w1);
        __nv_bfloat16 l0 = __float2bfloat16(w0 - __bfloat162float(h0));
        __nv_bfloat16 l1 = __float2bfloat16(w1 - __bfloat162float(h1));
        g_PTb[n * 36 + kw]        = pack_bf16x2(h0, h1);
        g_PTb[n * 36 + kw + 9216] = pack_bf16x2(l0, l1);
    } else {
        int z = tid - (256 * 128 + 64 * 128 + 256 * 32);
        if (z < NN) { g_rb[z] = 0; g_re[z] = 0; }
    }
}

// ---------------- Kernel B: row segment bounds ----------------
__global__ void detect_bounds_kernel(const int* __restrict__ adj) {
    int e = blockIdx.x * blockDim.x + threadIdx.x;
    if (e >= EE) return;
    int r = adj[2 * e];
    if (e == 0 || adj[2 * (e - 1)] != r) g_rb[r] = e;
    if (e == EE - 1 || adj[2 * (e + 1)] != r) g_re[r] = e + 1;
}

// ---------------- Kernel C: single-pass softmax + reflected-neighbor aggregation --------
// one warp per row; per-edge scalars precomputed lane-parallel, pipelined vector loads
__global__ __launch_bounds__(256) void agg_kernel(const float* __restrict__ feats,
                                                  const float* __restrict__ rel_emb,
                                                  const float* __restrict__ sv,
                                                  const int* __restrict__ adj,
                                                  const int* __restrict__ si) {
    int gw = (blockIdx.x * blockDim.x + threadIdx.x) >> 5;
    int lane = threadIdx.x & 31;
    if (gw >= NN) return;

    int e0 = g_rb[gw], e1 = g_re[gw];
    float4* o0 = reinterpret_cast<float4*>(g_nf0 + (size_t)gw * FF);
    float4* o1 = reinterpret_cast<float4*>(g_nf1 + (size_t)gw * FF);

    if (e0 >= e1) {
        float4 z = make_float4(0.f, 0.f, 0.f, 0.f);
        o0[lane] = z; o1[lane] = z;
        return;
    }

    const float2* rd2 = reinterpret_cast<const float2*>(g_reldot);

    float4 a0 = make_float4(0.f, 0.f, 0.f, 0.f);
    float4 a1 = make_float4(0.f, 0.f, 0.f, 0.f);
    float s0 = 0.f, s1 = 0.f;

    for (int c0 = e0; c0 < e1; c0 += 32) {
        int e = c0 + lane;
        int   pk  = 0;
        float w0p = 0.f, w1p = 0.f, f2p = 0.f;
        if (e < e1) {
            float s = sv[e];
            int col = adj[2 * e + 1];
            int r   = si[2 * e + 1];
            float2 rd = rd2[r];
            w0p = __expf(s * rd.x);             // no max shift: |s*rd| small by construction
            w1p = __expf(s * rd.y);
            float f = s * rsqrtf(fmaxf(s * s * g_relnsq[r], 1e-12f));
            f2p = f * f;
            pk  = col | (r << 17);              // col < 2^17, r < 1000
        }
        int cnt = min(32, e1 - c0);

        // prefetch edge 0 of this chunk
        int pk0 = __shfl_sync(0xffffffffu, pk, 0);
        float4 u = reinterpret_cast<const float4*>(rel_emb + (size_t)(pk0 >> 17) * FF)[lane];
        float4 x = __ldg(reinterpret_cast<const float4*>(feats + (size_t)(pk0 & 0x1ffff) * FF) + lane);

        for (int j = 0; j < cnt; j++) {
            float f2 = __shfl_sync(0xffffffffu, f2p, j);
            float w0 = __shfl_sync(0xffffffffu, w0p, j);
            float w1 = __shfl_sync(0xffffffffu, w1p, j);
            float4 uc = u, xc = x;
            if (j + 1 < cnt) {
                int pn = __shfl_sync(0xffffffffu, pk, j + 1);
                u = reinterpret_cast<const float4*>(rel_emb + (size_t)(pn >> 17) * FF)[lane];
                x = __ldg(reinterpret_cast<const float4*>(feats + (size_t)(pn & 0x1ffff) * FF) + lane);
            }
            float dr = xc.x * uc.x + xc.y * uc.y + xc.z * uc.z + xc.w * uc.w;
            dr = warp_sum(dr);
            float t2 = 2.f * f2 * dr;
            float4 y;
            y.x = xc.x - t2 * uc.x; y.y = xc.y - t2 * uc.y;
            y.z = xc.z - t2 * uc.z; y.w = xc.w - t2 * uc.w;

            s0 += w0; s1 += w1;
            a0.x += w0 * y.x; a0.y += w0 * y.y; a0.z += w0 * y.z; a0.w += w0 * y.w;
            a1.x += w1 * y.x; a1.y += w1 * y.y; a1.z += w1 * y.z; a1.w += w1 * y.w;
        }
    }
    float i0 = 1.f / s0, i1 = 1.f / s1;
    a0.x *= i0; a0.y *= i0; a0.z *= i0; a0.w *= i0;
    a1.x *= i1; a1.y *= i1; a1.z *= i1; a1.w *= i1;
    o0[lane] = a0;
    o1[lane] = a1;
}

// ---------------- Kernel E: fused tail; tensor-core GEMMs + cp.async pipelines ----------
#define TILE 64
#define NTHR 512
// smem word offsets
#define OFF_REG0   0            // P stage (16896) / PT stage (18432) / 2x Wt sub-chunk (2x9216)
#define OFF_OHI    18432        // 64 x 132 words (bf16x2)
#define OFF_OLO    26880
#define OFF_SCR    35328        // logits fp32 (64x65) -> PFhi (64x132 words)
#define OFF_PFLO   43776
#define OFF_ATTHI  52224        // 64 x 36 words
#define OFF_ATTLO  54528
#define OFF_INVN   56832
#define OFF_INVP   56896
#define SMEM_WORDS 56960        // 227,840 B

__global__ __launch_bounds__(NTHR) void final_kernel(const float* __restrict__ feats,
                                                     const int* __restrict__ neigh,
                                                     float* __restrict__ out) {
    extern __shared__ float sm[];
    unsigned int* REG0W  = reinterpret_cast<unsigned int*>(sm + OFF_REG0);
    unsigned int* OhiW   = reinterpret_cast<unsigned int*>(sm + OFF_OHI);
    unsigned int* OloW   = reinterpret_cast<unsigned int*>(sm + OFF_OLO);
    __nv_bfloat16* Ohi16 = reinterpret_cast<__nv_bfloat16*>(OhiW);
    __nv_bfloat16* Olo16 = reinterpret_cast<__nv_bfloat16*>(OloW);
    float* LG            = sm + OFF_SCR;   // logits scratch, pitch 65
    unsigned int* PFhiW  = reinterpret_cast<unsigned int*>(sm + OFF_SCR);
    unsigned int* PFloW  = reinterpret_cast<unsigned int*>(sm + OFF_PFLO);
    unsigned int* ATThiW = reinterpret_cast<unsigned int*>(sm + OFF_ATTHI);
    unsigned int* ATTloW = reinterpret_cast<unsigned int*>(sm + OFF_ATTLO);
    __nv_bfloat16* ATThi16 = reinterpret_cast<__nv_bfloat16*>(ATThiW);
    __nv_bfloat16* ATTlo16 = reinterpret_cast<__nv_bfloat16*>(ATTloW);
    float* INVN = sm + OFF_INVN;
    float* INVP = sm + OFF_INVP;

    int tid = threadIdx.x;
    int lane = tid & 31, w = tid >> 5;       // 16 warps
    int g   = lane >> 2;
    int tig = lane & 3;
    int base = blockIdx.x * TILE;

    unsigned int reg0a = smem_u32(REG0W);

    if (tid < PX) INVP[tid] = g_invp[tid];

    // stage P hi/lo via cp.async (overlaps with O-build gathers below)
    {
        const uint4* src = reinterpret_cast<const uint4*>(g_Pb);
        #pragma unroll
        for (int i = tid; i < 4224; i += NTHR) cp_async16(reg0a + i * 16, src + i);
        cp_commit();
    }
    // build O tile as split bf16: concat(features, 0.5*(nf0 + nf1-swapped))
    {
        int col = tid & 255;
        for (int rr = tid >> 8; rr < TILE; rr += 2) {
            int n = base + rr;
            float v = 0.f;
            if (n < NN) {
                if (col < 128) {
                    v = feats[(size_t)n * FF + col];
                } else {
                    int m = (n < K1) ? neigh[n] : n;
                    int jj = col - 128;
                    v = 0.5f * (g_nf0[(size_t)n * FF + jj] + g_nf1[(size_t)m * FF + jj]);
                }
            }
            __nv_bfloat16 h = __float2bfloat16(v);
            __nv_bfloat16 l = __float2bfloat16(v - __bfloat162float(h));
            Ohi16[rr * 264 + col] = h;
            Olo16[rr * 264 + col] = l;
        }
    }
    cp_wait0();
    __syncthreads();

    // row inverse norms
    #pragma unroll
    for (int q = 0; q < 4; q++) {
        int r = w * 4 + q;
        float s = 0.f;
        #pragma unroll
        for (int m = 0; m < 4; m++) {
            int j = r * 132 + lane + 32 * m;
            __nv_bfloat162 h = *reinterpret_cast<__nv_bfloat162*>(&OhiW[j]);
            __nv_bfloat162 l = *reinterpret_cast<__nv_bfloat162*>(&OloW[j]);
            float v0 = __bfloat162float(h.x) + __bfloat162float(l.x);
            float v1 = __bfloat162float(h.y) + __bfloat162float(l.y);
            s += v0 * v0 + v1 * v1;
        }
        s = warp_sum(s);
        if (lane == 0) INVN[r] = rsqrtf(fmaxf(s, 1e-12f));
    }
    __syncthreads();

    // ---- logits MMA: L = O @ P^T (64x64, K=256), split bf16 ----
    {
        int mt  = w & 3;
        int nt2 = w >> 2;
        float acc[2][4];
        #pragma unroll
        for (int nt = 0; nt < 2; nt++)
            #pragma unroll
            for (int i = 0; i < 4; i++) acc[nt][i] = 0.f;

        #pragma unroll 4
        for (int ks = 0; ks < 16; ks++) {
            int kw = ks * 8;
            int rb  = (mt * 16 + g) * 132;
            int rb8 = rb + 8 * 132;
            unsigned int ah[4], al[4];
            ah[0] = OhiW[rb  + kw + tig];     ah[1] = OhiW[rb8 + kw + tig];
            ah[2] = OhiW[rb  + kw + 4 + tig]; ah[3] = OhiW[rb8 + kw + 4 + tig];
            al[0] = OloW[rb  + kw + tig];     al[1] = OloW[rb8 + kw + tig];
            al[2] = OloW[rb  + kw + 4 + tig]; al[3] = OloW[rb8 + kw + 4 + tig];
            #pragma unroll
            for (int nt = 0; nt < 2; nt++) {
                int n = nt2 * 16 + nt * 8 + g;
                unsigned int bh0 = REG0W[n * 132 + kw + tig];
                unsigned int bh1 = REG0W[n * 132 + kw + 4 + tig];
                unsigned int bl0 = REG0W[8448 + n * 132 + kw + tig];
                unsigned int bl1 = REG0W[8448 + n * 132 + kw + 4 + tig];
                mma_bf16(acc[nt], ah, bh0, bh1);
                mma_bf16(acc[nt], ah, bl0, bl1);
                mma_bf16(acc[nt], al, bh0, bh1);
            }
        }
        #pragma unroll
        for (int nt = 0; nt < 2; nt++) {
            int ncol = nt2 * 16 + nt * 8 + 2 * tig;
            float ip0 = INVP[ncol], ip1 = INVP[ncol + 1];
            #pragma unroll
            for (int half = 0; half < 2; half++) {
                int r = mt * 16 + g + 8 * half;
                float invn = INVN[r];
                LG[r * 65 + ncol]     = acc[nt][2 * half]     * invn * ip0;
                LG[r * 65 + ncol + 1] = acc[nt][2 * half + 1] * invn * ip1;
            }
        }
    }
    __syncthreads();

    // ---- softmax (|logit| <= 1: no max shift) -> split bf16 ATT ----
    #pragma unroll
    for (int q = 0; q < 4; q++) {
        int r = w * 4 + q;
        float l0 = LG[r * 65 + lane];
        float l1 = LG[r * 65 + lane + 32];
        float e0v = __expf(l0);
        float e1v = __expf(l1);
        float s = warp_sum(e0v + e1v);
        float inv = 1.f / s;
        float a0 = e0v * inv, a1 = e1v * inv;
        __nv_bfloat16 h0 = __float2bfloat16(a0);
        __nv_bfloat16 h1 = __float2bfloat16(a1);
        ATThi16[r * 72 + lane]      = h0;
        ATThi16[r * 72 + lane + 32] = h1;
        ATTlo16[r * 72 + lane]      = __float2bfloat16(a0 - __bfloat162float(h0));
        ATTlo16[r * 72 + lane + 32] = __float2bfloat16(a1 - __bfloat162float(h1));
    }
    // stage PT hi/lo into REG0 via cp.async (all P reads completed at prior barrier)
    {
        const uint4* src = reinterpret_cast<const uint4*>(g_PTb);
        #pragma unroll
        for (int i = tid; i < 4608; i += NTHR) cp_async16(reg0a + i * 16, src + i);
        cp_commit();
    }
    cp_wait0();
    __syncthreads();

    // ---- PF MMA: delta = ATT @ P (64x256, K=64); PF = O - delta -> split bf16 ----
    {
        int wm = w & 3;
        int wn = w >> 2;
        float acc[8][4];
        #pragma unroll
        for (int nt = 0; nt < 8; nt++)
            #pragma unroll
            for (int i = 0; i < 4; i++) acc[nt][i] = 0.f;

        #pragma unroll
        for (int ks = 0; ks < 4; ks++) {
            int kw = ks * 8;
            int rb  = (wm * 16 + g) * 36;
            int rb8 = rb + 8 * 36;
            unsigned int ah[4], al[4];
            ah[0] = ATThiW[rb  + kw + tig];     ah[1] = ATThiW[rb8 + kw + tig];
            ah[2] = ATThiW[rb  + kw + 4 + tig]; ah[3] = ATThiW[rb8 + kw + 4 + tig];
            al[0] = ATTloW[rb  + kw + tig];     al[1] = ATTloW[rb8 + kw + tig];
            al[2] = ATTloW[rb  + kw + 4 + tig]; al[3] = ATTloW[rb8 + kw + 4 + tig];
            #pragma unroll
            for (int nt = 0; nt < 8; nt++) {
                int n = wn * 64 + nt * 8 + g;
                unsigned int bh0 = REG0W[n * 36 + kw + tig];
                unsigned int bh1 = REG0W[n * 36 + kw + 4 + tig];
                unsigned int bl0 = REG0W[9216 + n * 36 + kw + tig];
                unsigned int bl1 = REG0W[9216 + n * 36 + kw + 4 + tig];
                mma_bf16(acc[nt], ah, bh0, bh1);
                mma_bf16(acc[nt], ah, bl0, bl1);
                mma_bf16(acc[nt], al, bh0, bh1);
            }
        }
        __syncthreads();   // all PT reads done; LG consumed long before

        // prefetch gate W sub-chunk 0 into buf0 (overlaps with PF epilogue)
        {
            const uint4* src = reinterpret_cast<const uint4*>(g_Wt);
            #pragma unroll
            for (int i = tid; i < 2304; i += NTHR) cp_async16(reg0a + i * 16, src + i);
            cp_commit();
        }

        #pragma unroll
        for (int nt = 0; nt < 8; nt++) {
            int wcol = wn * 32 + nt * 4 + tig;
            #pragma unroll
            for (int half = 0; half < 2; half++) {
                int r = wm * 16 + g + 8 * half;
                int widx = r * 132 + wcol;
                __nv_bfloat162 h = *reinterpret_cast<__nv_bfloat162*>(&OhiW[widx]);
                __nv_bfloat162 l = *reinterpret_cast<__nv_bfloat162*>(&OloW[widx]);
                float o0 = __bfloat162float(h.x) + __bfloat162float(l.x);
                float o1 = __bfloat162float(h.y) + __bfloat162float(l.y);
                float p0 = o0 - acc[nt][2 * half];
                float p1 = o1 - acc[nt][2 * half + 1];
                __nv_bfloat16 ph0 = __float2bfloat16(p0);
                __nv_bfloat16 ph1 = __float2bfloat16(p1);
                __nv_bfloat16 pl0 = __float2bfloat16(p0 - __bfloat162float(ph0));
                __nv_bfloat16 pl1 = __float2bfloat16(p1 - __bfloat162float(ph1));
                PFhiW[widx] = pack_bf16x2(ph0, ph1);
                PFloW[widx] = pack_bf16x2(pl0, pl1);
            }
        }
    }

    // ---- gate MMA: Z = PF @ W, 8 K=32 sub-chunks, double-buffered cp.async ----
    {
        int wm = w & 1;
        int wn = w >> 1;

        float acc[2][4][4];
        #pragma unroll
        for (int mt = 0; mt < 2; mt++)
            #pragma unroll
            for (int nt = 0; nt < 4; nt++)
                #pragma unroll
                for (int i = 0; i < 4; i++) acc[mt][nt][i] = 0.f;

        #pragma unroll
        for (int c = 0; c < 8; c++) {
            cp_wait0();        // sub-chunk c landed (issued previous iteration / preloop)
            __syncthreads();   // all warps done with sub-chunk c-1 compute; data visible
            if (c < 7) {
                const uint4* src = reinterpret_cast<const uint4*>(g_Wt) + (c + 1) * 2304;
                unsigned int dsta = reg0a + (((c + 1) & 1) * WT_CHUNK_WORDS) * 4;
                #pragma unroll
                for (int i = tid; i < 2304; i += NTHR) cp_async16(dsta + i * 16, src + i);
                cp_commit();
            }
            const unsigned int* B = REG0W + (c & 1) * WT_CHUNK_WORDS;

            #pragma unroll
            for (int ks = 0; ks < 2; ks++) {
                int kw  = c * 16 + ks * 8;
                int lkw = ks * 8;
                unsigned int ah[2][4], al[2][4];
                #pragma unroll
                for (int mt = 0; mt < 2; mt++) {
                    int rb  = (wm * 32 + mt * 16 + g) * 132;
                    int rb8 = rb + 8 * 132;
                    ah[mt][0] = PFhiW[rb  + kw + tig];     ah[mt][1] = PFhiW[rb8 + kw + tig];
                    ah[mt][2] = PFhiW[rb  + kw + 4 + tig]; ah[mt][3] = PFhiW[rb8 + kw + 4 + tig];
                    al[mt][0] = PFloW[rb  + kw + tig];     al[mt][1] = PFloW[rb8 + kw + tig];
                    al[mt][2] = PFloW[rb  + kw + 4 + tig]; al[mt][3] = PFloW[rb8 + kw + 4 + tig];
                }
                #pragma unroll
                for (int nt = 0; nt < 4; nt++) {
                    int n = wn * 32 + nt * 8 + g;
                    unsigned int bh0 = B[n * 18 + lkw + tig];
                    unsigned int bh1 = B[n * 18 + lkw + 4 + tig];
                    unsigned int bl0 = B[4608 + n * 18 + lkw + tig];
                    unsigned int bl1 = B[4608 + n * 18 + lkw + 4 + tig];
                    #pragma unroll
                    for (int mt = 0; mt < 2; mt++) {
                        mma_bf16(acc[mt][nt], ah[mt], bh0, bh1);
                        mma_bf16(acc[mt][nt], ah[mt], bl0, bl1);
                        mma_bf16(acc[mt][nt], al[mt], bh0, bh1);
                    }
                }
            }
        }

        // epilogue: gate + blend + store
        #pragma unroll
        for (int mt = 0; mt < 2; mt++) {
            #pragma unroll
            for (int nt = 0; nt < 4; nt++) {
                int ncol = wn * 32 + nt * 8 + 2 * tig;
                int wcol = ncol >> 1;
                #pragma unroll
                for (int half = 0; half < 2; half++) {
                    int r = wm * 32 + mt * 16 + g + 8 * half;
                    int n = base + r;
                    if (n >= NN) continue;
                    int widx = r * 132 + wcol;
                    __nv_bfloat162 oh = *reinterpret_cast<__nv_bfloat162*>(&OhiW[widx]);
                    __nv_bfloat162 ol = *reinterpret_cast<__nv_bfloat162*>(&OloW[widx]);
                    __nv_bfloat162 ph = *reinterpret_cast<__nv_bfloat162*>(&PFhiW[widx]);
                    __nv_bfloat162 pl = *reinterpret_cast<__nv_bfloat162*>(&PFloW[widx]);
                    float o0  = __bfloat162float(oh.x) + __bfloat162float(ol.x);
                    float o1  = __bfloat162float(oh.y) + __bfloat162float(ol.y);
                    float pf0 = __bfloat162float(ph.x) + __bfloat162float(pl.x);
                    float pf1 = __bfloat162float(ph.y) + __bfloat162float(pl.y);
                    float z0 = acc[mt][nt][2 * half];
                    float z1 = acc[mt][nt][2 * half + 1];
                    float g0 = 1.f / (1.f + __expf(-z0));
                    float g1 = 1.f / (1.f + __expf(-z1));
                    float2 res;
                    res.x = g0 * o0 + (1.f - g0) * pf0;
                    res.y = g1 * o1 + (1.f - g1) * pf1;
                    *reinterpret_cast<float2*>(out + (size_t)n * CC + ncol) = res;
                }
            }
        }
    }
}

// ---------------- launch ----------------
extern "C" void kernel_launch(void* const* d_in, const int* in_sizes, int n_in,
                              void* d_out, int out_size) {
    const float* features  = (const float*)d_in[0];
    const float* rel_emb   = (const float*)d_in[1];
    const float* sparse_v  = (const float*)d_in[2];
    const float* attn_k    = (const float*)d_in[3];
    const float* proxy     = (const float*)d_in[4];
    const float* gate_k    = (const float*)d_in[5];
    const int*   adj       = (const int*)d_in[6];
    const int*   sparse_i  = (const int*)d_in[7];
    const int*   neigh     = (const int*)d_in[9];
    float* out = (float*)d_out;

    prep_kernel<<<RR + PX, 128>>>(rel_emb, attn_k, proxy);
    wconv_kernel<<<(49152 + NN + 255) / 256, 256>>>(gate_k, proxy);
    detect_bounds_kernel<<<(EE + 255) / 256, 256>>>(adj);
    agg_kernel<<<(NN * 32 + 255) / 256, 256>>>(features, rel_emb, sparse_v, adj, sparse_i);

    size_t smem = (size_t)SMEM_WORDS * sizeof(float);
    cudaFuncSetAttribute(final_kernel, cudaFuncAttributeMaxDynamicSharedMemorySize, (int)smem);
    final_kernel<<<(NN + TILE - 1) / TILE, NTHR, smem>>>(features, neigh, out);
}

// round 9
// speedup vs baseline: 4.3122x; 1.1091x over previous
#include <cuda_runtime.h>
#include <cuda_bf16.h>
#include <math.h>
#include <cstdint>

// Problem constants (fixed by setup_inputs)
#define NN 50000
#define EE 400000
#define RR 1000
#define FF 128
#define K1 1000
#define PX 64      // proxy rows
#define CC 256     // concat dim

// ---------------- scratch (device globals) ----------------
__device__ float g_nf0[(size_t)NN * FF];
__device__ float g_nf1[(size_t)NN * FF];
__device__ float g_relnsq[RR];
__device__ float g_reldot[RR * 2];
__device__ float g_invp[PX];
__device__ int   g_rb[NN];
__device__ int   g_re[NN];

// W^T split bf16 in 8 K=32 sub-chunks: [chunk][hi(4608)|lo(4608)], word = n*18 + klocal/2
#define WT_CHUNK_WORDS 9216
__device__ __align__(16) unsigned int g_Wt[8 * WT_CHUNK_WORDS];
// proxy split bf16, k-major: [hi(64*132)|lo], word = n*132 + k/2
__device__ __align__(16) unsigned int g_Pb[16896];
// proxy^T split bf16, n-major: [hi(256*36)|lo], word = n*36 + k/2
__device__ __align__(16) unsigned int g_PTb[18432];

__inline__ __device__ float warp_sum(float v) {
    #pragma unroll
    for (int o = 16; o; o >>= 1) v += __shfl_xor_sync(0xffffffffu, v, o);
    return v;
}
__inline__ __device__ unsigned int pack_bf16x2(__nv_bfloat16 lo, __nv_bfloat16 hi) {
    __nv_bfloat162 v(lo, hi);
    return *reinterpret_cast<unsigned int*>(&v);
}
__inline__ __device__ void mma_bf16(float* d, const unsigned int* a,
                                    unsigned int b0, unsigned int b1) {
    asm volatile(
        "mma.sync.aligned.m16n8k16.row.col.f32.bf16.bf16.f32 "
        "{%0,%1,%2,%3}, {%4,%5,%6,%7}, {%8,%9}, {%0,%1,%2,%3};"
        : "+f"(d[0]), "+f"(d[1]), "+f"(d[2]), "+f"(d[3])
        : "r"(a[0]), "r"(a[1]), "r"(a[2]), "r"(a[3]), "r"(b0), "r"(b1));
}
__device__ __forceinline__ unsigned int smem_u32(const void* p) {
    unsigned int a;
    asm volatile("{ .reg .u64 t; cvta.to.shared.u64 t, %1; cvt.u32.u64 %0, t; }"
                 : "=r"(a) : "l"(p));
    return a;
}
__device__ __forceinline__ void cp_async16(unsigned int dst, const void* src) {
    asm volatile("cp.async.cg.shared.global [%0], [%1], 16;" :: "r"(dst), "l"(src));
}
__device__ __forceinline__ void cp_commit() {
    asm volatile("cp.async.commit_group;" ::: "memory");
}
__device__ __forceinline__ void cp_wait0() {
    asm volatile("cp.async.wait_group 0;" ::: "memory");
}

// ---------------- Kernel A: per-relation norms & attn dots, proxy inv-norms ----------------
__global__ void prep_kernel(const float* __restrict__ rel_emb,
                            const float* __restrict__ attn,
                            const float* __restrict__ proxy) {
    int b = blockIdx.x;
    int t = threadIdx.x;
    int lane = t & 31, w = t >> 5;
    __shared__ float sh[3][4];

    if (b < RR) {
        float v  = rel_emb[b * FF + t];
        float a0 = attn[t];
        float a1 = attn[FF + t];
        float nsq = warp_sum(v * v);
        float d0  = warp_sum(v * a0);
        float d1  = warp_sum(v * a1);
        if (lane == 0) { sh[0][w] = nsq; sh[1][w] = d0; sh[2][w] = d1; }
        __syncthreads();
        if (t == 0) {
            g_relnsq[b]       = sh[0][0] + sh[0][1] + sh[0][2] + sh[0][3];
            g_reldot[2*b]     = sh[1][0] + sh[1][1] + sh[1][2] + sh[1][3];
            g_reldot[2*b + 1] = sh[2][0] + sh[2][1] + sh[2][2] + sh[2][3];
        }
    } else {
        int k = b - RR;
        float p0 = proxy[k * CC + t];
        float p1 = proxy[k * CC + 128 + t];
        float s = warp_sum(p0 * p0 + p1 * p1);
        if (lane == 0) sh[0][w] = s;
        __syncthreads();
        if (t == 0) {
            float tot = sh[0][0] + sh[0][1] + sh[0][2] + sh[0][3];
            g_invp[k] = 1.0f / sqrtf(fmaxf(tot, 1e-12f));
        }
    }
}

// ---------------- Kernel A2: W & proxy -> split bf16; also zero bounds ----------------
__global__ void wconv_kernel(const float* __restrict__ W, const float* __restrict__ proxy) {
    int tid = blockIdx.x * blockDim.x + threadIdx.x;
    if (tid < 256 * 128) {
        int n  = tid >> 7;
        int kp = tid & 127;
        int k  = kp * 2;
        float w0 = W[(size_t)k * CC + n];
        float w1 = W[(size_t)(k + 1) * CC + n];
        __nv_bfloat16 h0 = __float2bfloat16(w0);
        __nv_bfloat16 h1 = __float2bfloat16(w1);
        __nv_bfloat16 l0 = __float2bfloat16(w0 - __bfloat162float(h0));
        __nv_bfloat16 l1 = __float2bfloat16(w1 - __bfloat162float(h1));
        int c  = k >> 5;            // 8 chunks of K=32
        int lw = (k & 31) >> 1;     // 0..15
        int idx = c * WT_CHUNK_WORDS + n * 18 + lw;
        g_Wt[idx]        = pack_bf16x2(h0, h1);
        g_Wt[idx + 4608] = pack_bf16x2(l0, l1);
    } else if (tid < 256 * 128 + 64 * 128) {
        int t2 = tid - 256 * 128;
        int n  = t2 >> 7;
        int kp = t2 & 127;
        int k  = kp * 2;
        float w0 = proxy[(size_t)n * CC + k];
        float w1 = proxy[(size_t)n * CC + k + 1];
        __nv_bfloat16 h0 = __float2bfloat16(w0);
        __nv_bfloat16 h1 = __float2bfloat16(w1);
        __nv_bfloat16 l0 = __float2bfloat16(w0 - __bfloat162float(h0));
        __nv_bfloat16 l1 = __float2bfloat16(w1 - __bfloat162float(h1));
        g_Pb[n * 132 + kp]        = pack_bf16x2(h0, h1);
        g_Pb[n * 132 + kp + 8448] = pack_bf16x2(l0, l1);
    } else if (tid < 256 * 128 + 64 * 128 + 256 * 32) {
        int t3 = tid - 256 * 128 - 64 * 128;
        int n  = t3 >> 5;
        int kw = t3 & 31;
        int k  = kw * 2;
        float w0 = proxy[(size_t)k * CC + n];
        float w1 = proxy[(size_t)(k + 1) * CC + n];
        __nv_bfloat16 h0 = __float2bfloat16(w0);
        __nv_bfloat16 h1 = __float2bfloat16(w1);
        __nv_bfloat16 l0 = __float2bfloat16(w0 - __bfloat162float(h0));
        __nv_bfloat16 l1 = __float2bfloat16(w1 - __bfloat162float(h1));
        g_PTb[n * 36 + kw]        = pack_bf16x2(h0, h1);
        g_PTb[n * 36 + kw + 9216] = pack_bf16x2(l0, l1);
    } else {
        int z = tid - (256 * 128 + 64 * 128 + 256 * 32);
        if (z < NN) { g_rb[z] = 0; g_re[z] = 0; }
    }
}

// ---------------- Kernel B: row segment bounds ----------------
__global__ void detect_bounds_kernel(const int* __restrict__ adj) {
    int e = blockIdx.x * blockDim.x + threadIdx.x;
    if (e >= EE) return;
    int r = adj[2 * e];
    if (e == 0 || adj[2 * (e - 1)] != r) g_rb[r] = e;
    if (e == EE - 1 || adj[2 * (e + 1)] != r) g_re[r] = e + 1;
}

// ---------------- Kernel C: single-pass softmax + reflected-neighbor aggregation --------
__global__ __launch_bounds__(256) void agg_kernel(const float* __restrict__ feats,
                                                  const float* __restrict__ rel_emb,
                                                  const float* __restrict__ sv,
                                                  const int* __restrict__ adj,
                                                  const int* __restrict__ si) {
    int gw = (blockIdx.x * blockDim.x + threadIdx.x) >> 5;
    int lane = threadIdx.x & 31;
    if (gw >= NN) return;

    int e0 = g_rb[gw], e1 = g_re[gw];
    float4* o0 = reinterpret_cast<float4*>(g_nf0 + (size_t)gw * FF);
    float4* o1 = reinterpret_cast<float4*>(g_nf1 + (size_t)gw * FF);

    if (e0 >= e1) {
        float4 z = make_float4(0.f, 0.f, 0.f, 0.f);
        o0[lane] = z; o1[lane] = z;
        return;
    }

    const float2* rd2 = reinterpret_cast<const float2*>(g_reldot);

    float4 a0 = make_float4(0.f, 0.f, 0.f, 0.f);
    float4 a1 = make_float4(0.f, 0.f, 0.f, 0.f);
    float s0 = 0.f, s1 = 0.f;

    for (int c0 = e0; c0 < e1; c0 += 32) {
        int e = c0 + lane;
        int   pk  = 0;
        float w0p = 0.f, w1p = 0.f, fp = 0.f;
        if (e < e1) {
            float s = sv[e];
            int col = adj[2 * e + 1];
            int r   = si[2 * e + 1];
            float2 rd = rd2[r];
            w0p = __expf(s * rd.x);             // no max shift: |s*rd| small by construction
            w1p = __expf(s * rd.y);
            fp  = s * rsqrtf(fmaxf(s * s * g_relnsq[r], 1e-12f));
            pk  = col | (r << 17);              // col < 2^17, r < 1000
        }
        int cnt = min(32, e1 - c0);
        for (int j = 0; j < cnt; j++) {
            int   pkj = __shfl_sync(0xffffffffu, pk,  j);
            float f   = __shfl_sync(0xffffffffu, fp,  j);
            float w0  = __shfl_sync(0xffffffffu, w0p, j);
            float w1  = __shfl_sync(0xffffffffu, w1p, j);
            int col = pkj & 0x1ffff;
            int r   = pkj >> 17;

            float4 u = reinterpret_cast<const float4*>(rel_emb + (size_t)r * FF)[lane];
            u.x *= f; u.y *= f; u.z *= f; u.w *= f;
            float4 x = __ldg(reinterpret_cast<const float4*>(feats + (size_t)col * FF) + lane);

            float d = x.x * u.x + x.y * u.y + x.z * u.z + x.w * u.w;
            d = warp_sum(d);
            float t2 = 2.f * d;
            float4 y;
            y.x = x.x - t2 * u.x; y.y = x.y - t2 * u.y;
            y.z = x.z - t2 * u.z; y.w = x.w - t2 * u.w;

            s0 += w0; s1 += w1;
            a0.x += w0 * y.x; a0.y += w0 * y.y; a0.z += w0 * y.z; a0.w += w0 * y.w;
            a1.x += w1 * y.x; a1.y += w1 * y.y; a1.z += w1 * y.z; a1.w += w1 * y.w;
        }
    }
    float i0 = 1.f / s0, i1 = 1.f / s1;
    a0.x *= i0; a0.y *= i0; a0.z *= i0; a0.w *= i0;
    a1.x *= i1; a1.y *= i1; a1.z *= i1; a1.w *= i1;
    o0[lane] = a0;
    o1[lane] = a1;
}

// ---------------- Kernel E: fused tail; 32 warps, tensor-core GEMMs + cp.async ----------
#define TILE 64
#define NTHR 1024
// smem word offsets
#define OFF_REG0   0            // P stage (16896) / PT stage (18432) / 2x Wt sub-chunk (2x9216)
#define OFF_OHI    18432        // 64 x 132 words (bf16x2)
#define OFF_OLO    26880
#define OFF_SCR    35328        // logits fp32 (64x65) -> PFhi (64x132 words)
#define OFF_PFLO   43776
#define OFF_ATTHI  52224        // 64 x 36 words
#define OFF_ATTLO  54528
#define OFF_INVN   56832
#define OFF_INVP   56896
#define SMEM_WORDS 56960        // 227,840 B

__global__ __launch_bounds__(NTHR) void final_kernel(const float* __restrict__ feats,
                                                     const int* __restrict__ neigh,
                                                     float* __restrict__ out) {
    extern __shared__ float sm[];
    unsigned int* REG0W  = reinterpret_cast<unsigned int*>(sm + OFF_REG0);
    unsigned int* OhiW   = reinterpret_cast<unsigned int*>(sm + OFF_OHI);
    unsigned int* OloW   = reinterpret_cast<unsigned int*>(sm + OFF_OLO);
    __nv_bfloat16* Ohi16 = reinterpret_cast<__nv_bfloat16*>(OhiW);
    __nv_bfloat16* Olo16 = reinterpret_cast<__nv_bfloat16*>(OloW);
    float* LG            = sm + OFF_SCR;   // logits scratch, pitch 65
    unsigned int* PFhiW  = reinterpret_cast<unsigned int*>(sm + OFF_SCR);
    unsigned int* PFloW  = reinterpret_cast<unsigned int*>(sm + OFF_PFLO);
    unsigned int* ATThiW = reinterpret_cast<unsigned int*>(sm + OFF_ATTHI);
    unsigned int* ATTloW = reinterpret_cast<unsigned int*>(sm + OFF_ATTLO);
    __nv_bfloat16* ATThi16 = reinterpret_cast<__nv_bfloat16*>(ATThiW);
    __nv_bfloat16* ATTlo16 = reinterpret_cast<__nv_bfloat16*>(ATTloW);
    float* INVN = sm + OFF_INVN;
    float* INVP = sm + OFF_INVP;

    int tid = threadIdx.x;
    int lane = tid & 31, w = tid >> 5;       // 32 warps
    int g   = lane >> 2;
    int tig = lane & 3;
    int base = blockIdx.x * TILE;

    unsigned int reg0a = smem_u32(REG0W);

    if (tid < PX) INVP[tid] = g_invp[tid];

    // stage P hi/lo via cp.async (overlaps with O-build gathers below)
    {
        const uint4* src = reinterpret_cast<const uint4*>(g_Pb);
        #pragma unroll
        for (int i = tid; i < 4224; i += NTHR) cp_async16(reg0a + i * 16, src + i);
        cp_commit();
    }
    // build O tile as split bf16: concat(features, 0.5*(nf0 + nf1-swapped))
    {
        int col = tid & 255;
        for (int rr = tid >> 8; rr < TILE; rr += 4) {
            int n = base + rr;
            float v = 0.f;
            if (n < NN) {
                if (col < 128) {
                    v = feats[(size_t)n * FF + col];
                } else {
                    int m = (n < K1) ? neigh[n] : n;
                    int jj = col - 128;
                    v = 0.5f * (g_nf0[(size_t)n * FF + jj] + g_nf1[(size_t)m * FF + jj]);
                }
            }
            __nv_bfloat16 h = __float2bfloat16(v);
            __nv_bfloat16 l = __float2bfloat16(v - __bfloat162float(h));
            Ohi16[rr * 264 + col] = h;
            Olo16[rr * 264 + col] = l;
        }
    }
    cp_wait0();
    __syncthreads();

    // row inverse norms: warp w owns rows 2w, 2w+1
    #pragma unroll
    for (int q = 0; q < 2; q++) {
        int r = w * 2 + q;
        float s = 0.f;
        #pragma unroll
        for (int m = 0; m < 4; m++) {
            int j = r * 132 + lane + 32 * m;
            __nv_bfloat162 h = *reinterpret_cast<__nv_bfloat162*>(&OhiW[j]);
            __nv_bfloat162 l = *reinterpret_cast<__nv_bfloat162*>(&OloW[j]);
            float v0 = __bfloat162float(h.x) + __bfloat162float(l.x);
            float v1 = __bfloat162float(h.y) + __bfloat162float(l.y);
            s += v0 * v0 + v1 * v1;
        }
        s = warp_sum(s);
        if (lane == 0) INVN[r] = rsqrtf(fmaxf(s, 1e-12f));
    }
    __syncthreads();

    // ---- logits MMA: L = O @ P^T (64x64, K=256); warp = (mt: m16) x (nt8: n8) ----
    {
        int mt  = w & 3;
        int nt8 = w >> 2;        // 0..7
        float acc[4];
        #pragma unroll
        for (int i = 0; i < 4; i++) acc[i] = 0.f;

        int n = nt8 * 8 + g;
        #pragma unroll 4
        for (int ks = 0; ks < 16; ks++) {
            int kw = ks * 8;
            int rb  = (mt * 16 + g) * 132;
            int rb8 = rb + 8 * 132;
            unsigned int ah[4], al[4];
            ah[0] = OhiW[rb  + kw + tig];     ah[1] = OhiW[rb8 + kw + tig];
            ah[2] = OhiW[rb  + kw + 4 + tig]; ah[3] = OhiW[rb8 + kw + 4 + tig];
            al[0] = OloW[rb  + kw + tig];     al[1] = OloW[rb8 + kw + tig];
            al[2] = OloW[rb  + kw + 4 + tig]; al[3] = OloW[rb8 + kw + 4 + tig];
            unsigned int bh0 = REG0W[n * 132 + kw + tig];
            unsigned int bh1 = REG0W[n * 132 + kw + 4 + tig];
            unsigned int bl0 = REG0W[8448 + n * 132 + kw + tig];
            unsigned int bl1 = REG0W[8448 + n * 132 + kw + 4 + tig];
            mma_bf16(acc, ah, bh0, bh1);
            mma_bf16(acc, ah, bl0, bl1);
            mma_bf16(acc, al, bh0, bh1);
        }
        {
            int ncol = nt8 * 8 + 2 * tig;
            float ip0 = INVP[ncol], ip1 = INVP[ncol + 1];
            #pragma unroll
            for (int half = 0; half < 2; half++) {
                int r = mt * 16 + g + 8 * half;
                float invn = INVN[r];
                LG[r * 65 + ncol]     = acc[2 * half]     * invn * ip0;
                LG[r * 65 + ncol + 1] = acc[2 * half + 1] * invn * ip1;
            }
        }
    }
    __syncthreads();

    // ---- softmax (|logit| <= 1: no max shift) -> split bf16 ATT; warp w: rows 2w,2w+1 ----
    #pragma unroll
    for (int q = 0; q < 2; q++) {
        int r = w * 2 + q;
        float l0 = LG[r * 65 + lane];
        float l1 = LG[r * 65 + lane + 32];
        float e0v = __expf(l0);
        float e1v = __expf(l1);
        float s = warp_sum(e0v + e1v);
        float inv = 1.f / s;
        float a0 = e0v * inv, a1 = e1v * inv;
        __nv_bfloat16 h0 = __float2bfloat16(a0);
        __nv_bfloat16 h1 = __float2bfloat16(a1);
        ATThi16[r * 72 + lane]      = h0;
        ATThi16[r * 72 + lane + 32] = h1;
        ATTlo16[r * 72 + lane]      = __float2bfloat16(a0 - __bfloat162float(h0));
        ATTlo16[r * 72 + lane + 32] = __float2bfloat16(a1 - __bfloat162float(h1));
    }
    // stage PT hi/lo into REG0 via cp.async (all P reads completed at prior barrier)
    {
        const uint4* src = reinterpret_cast<const uint4*>(g_PTb);
        #pragma unroll
        for (int i = tid; i < 4608; i += NTHR) cp_async16(reg0a + i * 16, src + i);
        cp_commit();
    }
    cp_wait0();
    __syncthreads();

    // ---- PF MMA: delta = ATT @ P (64x256, K=64); warp = (wm: m16) x (wn: n32, nt4) ----
    {
        int wm = w & 3;
        int wn = w >> 2;         // 0..7, 32-col groups
        float acc[4][4];
        #pragma unroll
        for (int nt = 0; nt < 4; nt++)
            #pragma unroll
            for (int i = 0; i < 4; i++) acc[nt][i] = 0.f;

        #pragma unroll
        for (int ks = 0; ks < 4; ks++) {
            int kw = ks * 8;
            int rb  = (wm * 16 + g) * 36;
            int rb8 = rb + 8 * 36;
            unsigned int ah[4], al[4];
            ah[0] = ATThiW[rb  + kw + tig];     ah[1] = ATThiW[rb8 + kw + tig];
            ah[2] = ATThiW[rb  + kw + 4 + tig]; ah[3] = ATThiW[rb8 + kw + 4 + tig];
            al[0] = ATTloW[rb  + kw + tig];     al[1] = ATTloW[rb8 + kw + tig];
            al[2] = ATTloW[rb  + kw + 4 + tig]; al[3] = ATTloW[rb8 + kw + 4 + tig];
            #pragma unroll
            for (int nt = 0; nt < 4; nt++) {
                int n = wn * 32 + nt * 8 + g;
                unsigned int bh0 = REG0W[n * 36 + kw + tig];
                unsigned int bh1 = REG0W[n * 36 + kw + 4 + tig];
                unsigned int bl0 = REG0W[9216 + n * 36 + kw + tig];
                unsigned int bl1 = REG0W[9216 + n * 36 + kw + 4 + tig];
                mma_bf16(acc[nt], ah, bh0, bh1);
                mma_bf16(acc[nt], ah, bl0, bl1);
                mma_bf16(acc[nt], al, bh0, bh1);
            }
        }
        __syncthreads();   // all PT reads done; LG consumed long before

        // prefetch gate W sub-chunk 0 into buf0 (overlaps with PF epilogue)
        {
            const uint4* src = reinterpret_cast<const uint4*>(g_Wt);
            #pragma unroll
            for (int i = tid; i < 2304; i += NTHR) cp_async16(reg0a + i * 16, src + i);
            cp_commit();
        }

        #pragma unroll
        for (int nt = 0; nt < 4; nt++) {
            int wcol = wn * 16 + nt * 4 + tig;
            #pragma unroll
            for (int half = 0; half < 2; half++) {
                int r = wm * 16 + g + 8 * half;
                int widx = r * 132 + wcol;
                __nv_bfloat162 h = *reinterpret_cast<__nv_bfloat162*>(&OhiW[widx]);
                __nv_bfloat162 l = *reinterpret_cast<__nv_bfloat162*>(&OloW[widx]);
                float o0 = __bfloat162float(h.x) + __bfloat162float(l.x);
                float o1 = __bfloat162float(h.y) + __bfloat162float(l.y);
                float p0 = o0 - acc[nt][2 * half];
                float p1 = o1 - acc[nt][2 * half + 1];
                __nv_bfloat16 ph0 = __float2bfloat16(p0);
                __nv_bfloat16 ph1 = __float2bfloat16(p1);
                __nv_bfloat16 pl0 = __float2bfloat16(p0 - __bfloat162float(ph0));
                __nv_bfloat16 pl1 = __float2bfloat16(p1 - __bfloat162float(ph1));
                PFhiW[widx] = pack_bf16x2(ph0, ph1);
                PFloW[widx] = pack_bf16x2(pl0, pl1);
            }
        }
    }

    // ---- gate MMA: Z = PF @ W; warp = (wm: m16) x (wn: n32, nt4); 8 K=32 chunks ----
    {
        int wm = w & 3;
        int wn = w >> 2;

        float acc[4][4];
        #pragma unroll
        for (int nt = 0; nt < 4; nt++)
            #pragma unroll
            for (int i = 0; i < 4; i++) acc[nt][i] = 0.f;

        #pragma unroll
        for (int c = 0; c < 8; c++) {
            cp_wait0();        // sub-chunk c landed
            __syncthreads();   // all warps done with sub-chunk c-1 compute; data visible
            if (c < 7) {
                const uint4* src = reinterpret_cast<const uint4*>(g_Wt) + (c + 1) * 2304;
                unsigned int dsta = reg0a + (((c + 1) & 1) * WT_CHUNK_WORDS) * 4;
                #pragma unroll
                for (int i = tid; i < 2304; i += NTHR) cp_async16(dsta + i * 16, src + i);
                cp_commit();
            }
            const unsigned int* B = REG0W + (c & 1) * WT_CHUNK_WORDS;

            #pragma unroll
            for (int ks = 0; ks < 2; ks++) {
                int kw  = c * 16 + ks * 8;
                int lkw = ks * 8;
                int rb  = (wm * 16 + g) * 132;
                int rb8 = rb + 8 * 132;
                unsigned int ah[4], al[4];
                ah[0] = PFhiW[rb  + kw + tig];     ah[1] = PFhiW[rb8 + kw + tig];
                ah[2] = PFhiW[rb  + kw + 4 + tig]; ah[3] = PFhiW[rb8 + kw + 4 + tig];
                al[0] = PFloW[rb  + kw + tig];     al[1] = PFloW[rb8 + kw + tig];
                al[2] = PFloW[rb  + kw + 4 + tig]; al[3] = PFloW[rb8 + kw + 4 + tig];
                #pragma unroll
                for (int nt = 0; nt < 4; nt++) {
                    int n = wn * 32 + nt * 8 + g;
                    unsigned int bh0 = B[n * 18 + lkw + tig];
                    unsigned int bh1 = B[n * 18 + lkw + 4 + tig];
                    unsigned int bl0 = B[4608 + n * 18 + lkw + tig];
                    unsigned int bl1 = B[4608 + n * 18 + lkw + 4 + tig];
                    mma_bf16(acc[nt], ah, bh0, bh1);
                    mma_bf16(acc[nt], ah, bl0, bl1);
                    mma_bf16(acc[nt], al, bh0, bh1);
                }
            }
        }

        // epilogue: gate + blend + store
        #pragma unroll
        for (int nt = 0; nt < 4; nt++) {
            int ncol = wn * 32 + nt * 8 + 2 * tig;
            int wcol = ncol >> 1;
            #pragma unroll
            for (int half = 0; half < 2; half++) {
                int r = wm * 16 + g + 8 * half;
                int n = base + r;
                if (n >= NN) continue;
                int widx = r * 132 + wcol;
                __nv_bfloat162 oh = *reinterpret_cast<__nv_bfloat162*>(&OhiW[widx]);
                __nv_bfloat162 ol = *reinterpret_cast<__nv_bfloat162*>(&OloW[widx]);
                __nv_bfloat162 ph = *reinterpret_cast<__nv_bfloat162*>(&PFhiW[widx]);
                __nv_bfloat162 pl = *reinterpret_cast<__nv_bfloat162*>(&PFloW[widx]);
                float o0  = __bfloat162float(oh.x) + __bfloat162float(ol.x);
                float o1  = __bfloat162float(oh.y) + __bfloat162float(ol.y);
                float pf0 = __bfloat162float(ph.x) + __bfloat162float(pl.x);
                float pf1 = __bfloat162float(ph.y) + __bfloat162float(pl.y);
                float z0 = acc[nt][2 * half];
                float z1 = acc[nt][2 * half + 1];
                float g0 = 1.f / (1.f + __expf(-z0));
                float g1 = 1.f / (1.f + __expf(-z1));
                float2 res;
                res.x = g0 * o0 + (1.f - g0) * pf0;
                res.y = g1 * o1 + (1.f - g1) * pf1;
                *reinterpret_cast<float2*>(out + (size_t)n * CC + ncol) = res;
            }
        }
    }
}

// ---------------- launch ----------------
extern "C" void kernel_launch(void* const* d_in, const int* in_sizes, int n_in,
                              void* d_out, int out_size) {
    const float* features  = (const float*)d_in[0];
    const float* rel_emb   = (const float*)d_in[1];
    const float* sparse_v  = (const float*)d_in[2];
    const float* attn_k    = (const float*)d_in[3];
    const float* proxy     = (const float*)d_in[4];
    const float* gate_k    = (const float*)d_in[5];
    const int*   adj       = (const int*)d_in[6];
    const int*   sparse_i  = (const int*)d_in[7];
    const int*   neigh     = (const int*)d_in[9];
    float* out = (float*)d_out;

    prep_kernel<<<RR + PX, 128>>>(rel_emb, attn_k, proxy);
    wconv_kernel<<<(49152 + NN + 255) / 256, 256>>>(gate_k, proxy);
    detect_bounds_kernel<<<(EE + 255) / 256, 256>>>(adj);
    agg_kernel<<<(NN * 32 + 255) / 256, 256>>>(features, rel_emb, sparse_v, adj, sparse_i);

    size_t smem = (size_t)SMEM_WORDS * sizeof(float);
    cudaFuncSetAttribute(final_kernel, cudaFuncAttributeMaxDynamicSharedMemorySize, (int)smem);
    final_kernel<<<(NN + TILE - 1) / TILE, NTHR, smem>>>(features, neigh, out);
}

// round 10
// speedup vs baseline: 5.3372x; 1.2377x over previous
#include <cuda_runtime.h>
#include <cuda_bf16.h>
#include <math.h>
#include <cstdint>

// Problem constants (fixed by setup_inputs)
#define NN 50000
#define EE 400000
#define RR 1000
#define FF 128
#define K1 1000
#define PX 64      // proxy rows
#define CC 256     // concat dim

// ---------------- scratch (device globals) ----------------
__device__ float g_nf0[(size_t)NN * FF];
__device__ float g_nf1[(size_t)NN * FF];
__device__ float g_relnsq[RR];
__device__ float g_reldot[RR * 2];
__device__ float g_invp[PX];
__device__ int   g_rb[NN];
__device__ int   g_re[NN];

// W^T hi-only bf16 in 4 K=64 chunks: [chunk][9216 words], word = n*36 + klocal/2
#define WT64_WORDS 9216
__device__ __align__(16) unsigned int g_Wt[4 * WT64_WORDS];
// proxy split bf16, k-major: [hi(64*132)|lo], word = n*132 + k/2
__device__ __align__(16) unsigned int g_Pb[16896];
// proxy^T split bf16, n-major: [hi(256*36)|lo], word = n*36 + k/2
__device__ __align__(16) unsigned int g_PTb[18432];

__inline__ __device__ float warp_sum(float v) {
    #pragma unroll
    for (int o = 16; o; o >>= 1) v += __shfl_xor_sync(0xffffffffu, v, o);
    return v;
}
// two independent interleaved reductions (overlapped shfl chains)
__inline__ __device__ void warp_sum2(float& a, float& b) {
    #pragma unroll
    for (int o = 16; o; o >>= 1) {
        float ta = __shfl_xor_sync(0xffffffffu, a, o);
        float tb = __shfl_xor_sync(0xffffffffu, b, o);
        a += ta; b += tb;
    }
}
__inline__ __device__ unsigned int pack_bf16x2(__nv_bfloat16 lo, __nv_bfloat16 hi) {
    __nv_bfloat162 v(lo, hi);
    return *reinterpret_cast<unsigned int*>(&v);
}
__inline__ __device__ void mma_bf16(float* d, const unsigned int* a,
                                    unsigned int b0, unsigned int b1) {
    asm volatile(
        "mma.sync.aligned.m16n8k16.row.col.f32.bf16.bf16.f32 "
        "{%0,%1,%2,%3}, {%4,%5,%6,%7}, {%8,%9}, {%0,%1,%2,%3};"
        : "+f"(d[0]), "+f"(d[1]), "+f"(d[2]), "+f"(d[3])
        : "r"(a[0]), "r"(a[1]), "r"(a[2]), "r"(a[3]), "r"(b0), "r"(b1));
}
__device__ __forceinline__ unsigned int smem_u32(const void* p) {
    unsigned int a;
    asm volatile("{ .reg .u64 t; cvta.to.shared.u64 t, %1; cvt.u32.u64 %0, t; }"
                 : "=r"(a) : "l"(p));
    return a;
}
__device__ __forceinline__ void cp_async16(unsigned int dst, const void* src) {
    asm volatile("cp.async.cg.shared.global [%0], [%1], 16;" :: "r"(dst), "l"(src));
}
__device__ __forceinline__ void cp_commit() {
    asm volatile("cp.async.commit_group;" ::: "memory");
}
__device__ __forceinline__ void cp_wait0() {
    asm volatile("cp.async.wait_group 0;" ::: "memory");
}

// ---------------- Kernel A: per-relation norms & attn dots, proxy inv-norms ----------------
__global__ void prep_kernel(const float* __restrict__ rel_emb,
                            const float* __restrict__ attn,
                            const float* __restrict__ proxy) {
    int b = blockIdx.x;
    int t = threadIdx.x;
    int lane = t & 31, w = t >> 5;
    __shared__ float sh[3][4];

    if (b < RR) {
        float v  = rel_emb[b * FF + t];
        float a0 = attn[t];
        float a1 = attn[FF + t];
        float nsq = warp_sum(v * v);
        float d0  = warp_sum(v * a0);
        float d1  = warp_sum(v * a1);
        if (lane == 0) { sh[0][w] = nsq; sh[1][w] = d0; sh[2][w] = d1; }
        __syncthreads();
        if (t == 0) {
            g_relnsq[b]       = sh[0][0] + sh[0][1] + sh[0][2] + sh[0][3];
            g_reldot[2*b]     = sh[1][0] + sh[1][1] + sh[1][2] + sh[1][3];
            g_reldot[2*b + 1] = sh[2][0] + sh[2][1] + sh[2][2] + sh[2][3];
        }
    } else {
        int k = b - RR;
        float p0 = proxy[k * CC + t];
        float p1 = proxy[k * CC + 128 + t];
        float s = warp_sum(p0 * p0 + p1 * p1);
        if (lane == 0) sh[0][w] = s;
        __syncthreads();
        if (t == 0) {
            float tot = sh[0][0] + sh[0][1] + sh[0][2] + sh[0][3];
            g_invp[k] = 1.0f / sqrtf(fmaxf(tot, 1e-12f));
        }
    }
}

// ---------------- Kernel A2: W & proxy -> bf16 layouts; also zero bounds ----------------
__global__ void wconv_kernel(const float* __restrict__ W, const float* __restrict__ proxy) {
    int tid = blockIdx.x * blockDim.x + threadIdx.x;
    if (tid < 256 * 128) {
        int n  = tid >> 7;
        int kp = tid & 127;
        int k  = kp * 2;
        float w0 = W[(size_t)k * CC + n];
        float w1 = W[(size_t)(k + 1) * CC + n];
        __nv_bfloat16 h0 = __float2bfloat16(w0);
        __nv_bfloat16 h1 = __float2bfloat16(w1);
        int c  = k >> 6;            // 4 chunks of K=64
        int lw = (k & 63) >> 1;     // 0..31
        g_Wt[c * WT64_WORDS + n * 36 + lw] = pack_bf16x2(h0, h1);
    } else if (tid < 256 * 128 + 64 * 128) {
        int t2 = tid - 256 * 128;
        int n  = t2 >> 7;
        int kp = t2 & 127;
        int k  = kp * 2;
        float w0 = proxy[(size_t)n * CC + k];
        float w1 = proxy[(size_t)n * CC + k + 1];
        __nv_bfloat16 h0 = __float2bfloat16(w0);
        __nv_bfloat16 h1 = __float2bfloat16(w1);
        __nv_bfloat16 l0 = __float2bfloat16(w0 - __bfloat162float(h0));
        __nv_bfloat16 l1 = __float2bfloat16(w1 - __bfloat162float(h1));
        g_Pb[n * 132 + kp]        = pack_bf16x2(h0, h1);
        g_Pb[n * 132 + kp + 8448] = pack_bf16x2(l0, l1);
    } else if (tid < 256 * 128 + 64 * 128 + 256 * 32) {
        int t3 = tid - 256 * 128 - 64 * 128;
        int n  = t3 >> 5;
        int kw = t3 & 31;
        int k  = kw * 2;
        float w0 = proxy[(size_t)k * CC + n];
        float w1 = proxy[(size_t)(k + 1) * CC + n];
        __nv_bfloat16 h0 = __float2bfloat16(w0);
        __nv_bfloat16 h1 = __float2bfloat16(w1);
        __nv_bfloat16 l0 = __float2bfloat16(w0 - __bfloat162float(h0));
        __nv_bfloat16 l1 = __float2bfloat16(w1 - __bfloat162float(h1));
        g_PTb[n * 36 + kw]        = pack_bf16x2(h0, h1);
        g_PTb[n * 36 + kw + 9216] = pack_bf16x2(l0, l1);
    } else {
        int z = tid - (256 * 128 + 64 * 128 + 256 * 32);
        if (z < NN) { g_rb[z] = 0; g_re[z] = 0; }
    }
}

// ---------------- Kernel B: row segment bounds ----------------
__global__ void detect_bounds_kernel(const int* __restrict__ adj) {
    int e = blockIdx.x * blockDim.x + threadIdx.x;
    if (e >= EE) return;
    int r = adj[2 * e];
    if (e == 0 || adj[2 * (e - 1)] != r) g_rb[r] = e;
    if (e == EE - 1 || adj[2 * (e + 1)] != r) g_re[r] = e + 1;
}

// ---------------- Kernel C: single-pass softmax + reflected-neighbor aggregation --------
// one warp per row; per-edge scalars precomputed lane-parallel; edges processed in pairs
// (lanes >= cnt hold zero weights, so padding edges contribute exactly zero)
__global__ __launch_bounds__(256) void agg_kernel(const float* __restrict__ feats,
                                                  const float* __restrict__ rel_emb,
                                                  const float* __restrict__ sv,
                                                  const int* __restrict__ adj,
                                                  const int* __restrict__ si) {
    int gw = (blockIdx.x * blockDim.x + threadIdx.x) >> 5;
    int lane = threadIdx.x & 31;
    if (gw >= NN) return;

    int e0 = g_rb[gw], e1 = g_re[gw];
    float4* o0 = reinterpret_cast<float4*>(g_nf0 + (size_t)gw * FF);
    float4* o1 = reinterpret_cast<float4*>(g_nf1 + (size_t)gw * FF);

    if (e0 >= e1) {
        float4 z = make_float4(0.f, 0.f, 0.f, 0.f);
        o0[lane] = z; o1[lane] = z;
        return;
    }

    const float2* rd2 = reinterpret_cast<const float2*>(g_reldot);

    float4 a0 = make_float4(0.f, 0.f, 0.f, 0.f);
    float4 a1 = make_float4(0.f, 0.f, 0.f, 0.f);
    float s0 = 0.f, s1 = 0.f;

    for (int c0 = e0; c0 < e1; c0 += 32) {
        int e = c0 + lane;
        int   pk  = 0;
        float w0p = 0.f, w1p = 0.f, fp = 0.f;
        if (e < e1) {
            float s = sv[e];
            int col = adj[2 * e + 1];
            int r   = si[2 * e + 1];
            float2 rd = rd2[r];
            w0p = __expf(s * rd.x);             // no max shift: |s*rd| small by construction
            w1p = __expf(s * rd.y);
            fp  = s * rsqrtf(fmaxf(s * s * g_relnsq[r], 1e-12f));
            pk  = col | (r << 17);              // col < 2^17, r < 1000
        }
        int cnt = min(32, e1 - c0);

        for (int j = 0; j < cnt; j += 2) {
            int   pa  = __shfl_sync(0xffffffffu, pk,  j);
            int   pb  = __shfl_sync(0xffffffffu, pk,  j + 1);
            float fa  = __shfl_sync(0xffffffffu, fp,  j);
            float fb  = __shfl_sync(0xffffffffu, fp,  j + 1);
            float w0a = __shfl_sync(0xffffffffu, w0p, j);
            float w0b = __shfl_sync(0xffffffffu, w0p, j + 1);
            float w1a = __shfl_sync(0xffffffffu, w1p, j);
            float w1b = __shfl_sync(0xffffffffu, w1p, j + 1);

            float4 ua = reinterpret_cast<const float4*>(rel_emb + (size_t)(pa >> 17) * FF)[lane];
            float4 xa = __ldg(reinterpret_cast<const float4*>(feats + (size_t)(pa & 0x1ffff) * FF) + lane);
            float4 ub = reinterpret_cast<const float4*>(rel_emb + (size_t)(pb >> 17) * FF)[lane];
            float4 xb = __ldg(reinterpret_cast<const float4*>(feats + (size_t)(pb & 0x1ffff) * FF) + lane);

            float da = xa.x * ua.x + xa.y * ua.y + xa.z * ua.z + xa.w * ua.w;
            float db = xb.x * ub.x + xb.y * ub.y + xb.z * ub.z + xb.w * ub.w;
            warp_sum2(da, db);

            float ta = 2.f * fa * fa * da;
            float tb = 2.f * fb * fb * db;
            float4 ya, yb;
            ya.x = xa.x - ta * ua.x; ya.y = xa.y - ta * ua.y;
            ya.z = xa.z - ta * ua.z; ya.w = xa.w - ta * ua.w;
            yb.x = xb.x - tb * ub.x; yb.y = xb.y - tb * ub.y;
            yb.z = xb.z - tb * ub.z; yb.w = xb.w - tb * ub.w;

            s0 += w0a + w0b; s1 += w1a + w1b;
            a0.x += w0a * ya.x + w0b * yb.x; a0.y += w0a * ya.y + w0b * yb.y;
            a0.z += w0a * ya.z + w0b * yb.z; a0.w += w0a * ya.w + w0b * yb.w;
            a1.x += w1a * ya.x + w1b * yb.x; a1.y += w1a * ya.y + w1b * yb.y;
            a1.z += w1a * ya.z + w1b * yb.z; a1.w += w1a * ya.w + w1b * yb.w;
        }
    }
    float i0 = 1.f / s0, i1 = 1.f / s1;
    a0.x *= i0; a0.y *= i0; a0.z *= i0; a0.w *= i0;
    a1.x *= i1; a1.y *= i1; a1.z *= i1; a1.w *= i1;
    o0[lane] = a0;
    o1[lane] = a1;
}

// ---------------- Kernel E: fused tail; 32 warps, tensor-core GEMMs + cp.async ----------
#define TILE 64
#define NTHR 1024
// smem word offsets
#define OFF_REG0   0            // P stage (16896) / PT stage (18432) / 2x Wt64 chunk (2x9216)
#define OFF_OHI    18432        // 64 x 132 words (bf16x2)
#define OFF_OLO    26880
#define OFF_SCR    35328        // logits fp32 (64x65) -> PFhi (64x132 words)
#define OFF_PFLO   43776
#define OFF_ATTHI  52224        // 64 x 36 words
#define OFF_ATTLO  54528
#define OFF_INVN   56832
#define OFF_INVP   56896
#define SMEM_WORDS 56960        // 227,840 B

__global__ __launch_bounds__(NTHR) void final_kernel(const float* __restrict__ feats,
                                                     const int* __restrict__ neigh,
                                                     float* __restrict__ out) {
    extern __shared__ float sm[];
    unsigned int* REG0W  = reinterpret_cast<unsigned int*>(sm + OFF_REG0);
    unsigned int* OhiW   = reinterpret_cast<unsigned int*>(sm + OFF_OHI);
    unsigned int* OloW   = reinterpret_cast<unsigned int*>(sm + OFF_OLO);
    __nv_bfloat16* Ohi16 = reinterpret_cast<__nv_bfloat16*>(OhiW);
    __nv_bfloat16* Olo16 = reinterpret_cast<__nv_bfloat16*>(OloW);
    float* LG            = sm + OFF_SCR;   // logits scratch, pitch 65
    unsigned int* PFhiW  = reinterpret_cast<unsigned int*>(sm + OFF_SCR);
    unsigned int* PFloW  = reinterpret_cast<unsigned int*>(sm + OFF_PFLO);
    unsigned int* ATThiW = reinterpret_cast<unsigned int*>(sm + OFF_ATTHI);
    unsigned int* ATTloW = reinterpret_cast<unsigned int*>(sm + OFF_ATTLO);
    __nv_bfloat16* ATThi16 = reinterpret_cast<__nv_bfloat16*>(ATThiW);
    __nv_bfloat16* ATTlo16 = reinterpret_cast<__nv_bfloat16*>(ATTloW);
    float* INVN = sm + OFF_INVN;
    float* INVP = sm + OFF_INVP;

    int tid = threadIdx.x;
    int lane = tid & 31, w = tid >> 5;       // 32 warps
    int g   = lane >> 2;
    int tig = lane & 3;
    int base = blockIdx.x * TILE;

    unsigned int reg0a = smem_u32(REG0W);

    if (tid < PX) INVP[tid] = g_invp[tid];

    // stage P hi/lo via cp.async (overlaps with O-build gathers below)
    {
        const uint4* src = reinterpret_cast<const uint4*>(g_Pb);
        #pragma unroll
        for (int i = tid; i < 4224; i += NTHR) cp_async16(reg0a + i * 16, src + i);
        cp_commit();
    }
    // build O tile as split bf16: concat(features, 0.5*(nf0 + nf1-swapped))
    {
        int col = tid & 255;
        for (int rr = tid >> 8; rr < TILE; rr += 4) {
            int n = base + rr;
            float v = 0.f;
            if (n < NN) {
                if (col < 128) {
                    v = feats[(size_t)n * FF + col];
                } else {
                    int m = (n < K1) ? neigh[n] : n;
                    int jj = col - 128;
                    v = 0.5f * (g_nf0[(size_t)n * FF + jj] + g_nf1[(size_t)m * FF + jj]);
                }
            }
            __nv_bfloat16 h = __float2bfloat16(v);
            __nv_bfloat16 l = __float2bfloat16(v - __bfloat162float(h));
            Ohi16[rr * 264 + col] = h;
            Olo16[rr * 264 + col] = l;
        }
    }
    cp_wait0();
    __syncthreads();

    // row inverse norms: warp w owns rows 2w, 2w+1
    #pragma unroll
    for (int q = 0; q < 2; q++) {
        int r = w * 2 + q;
        float s = 0.f;
        #pragma unroll
        for (int m = 0; m < 4; m++) {
            int j = r * 132 + lane + 32 * m;
            __nv_bfloat162 h = *reinterpret_cast<__nv_bfloat162*>(&OhiW[j]);
            __nv_bfloat162 l = *reinterpret_cast<__nv_bfloat162*>(&OloW[j]);
            float v0 = __bfloat162float(h.x) + __bfloat162float(l.x);
            float v1 = __bfloat162float(h.y) + __bfloat162float(l.y);
            s += v0 * v0 + v1 * v1;
        }
        s = warp_sum(s);
        if (lane == 0) INVN[r] = rsqrtf(fmaxf(s, 1e-12f));
    }
    __syncthreads();

    // ---- logits MMA: L = O @ P^T (64x64, K=256); warp = (mt: m16) x (nt8: n8) ----
    {
        int mt  = w & 3;
        int nt8 = w >> 2;        // 0..7
        float acc[4];
        #pragma unroll
        for (int i = 0; i < 4; i++) acc[i] = 0.f;

        int n = nt8 * 8 + g;
        #pragma unroll 4
        for (int ks = 0; ks < 16; ks++) {
            int kw = ks * 8;
            int rb  = (mt * 16 + g) * 132;
            int rb8 = rb + 8 * 132;
            unsigned int ah[4], al[4];
            ah[0] = OhiW[rb  + kw + tig];     ah[1] = OhiW[rb8 + kw + tig];
            ah[2] = OhiW[rb  + kw + 4 + tig]; ah[3] = OhiW[rb8 + kw + 4 + tig];
            al[0] = OloW[rb  + kw + tig];     al[1] = OloW[rb8 + kw + tig];
            al[2] = OloW[rb  + kw + 4 + tig]; al[3] = OloW[rb8 + kw + 4 + tig];
            unsigned int bh0 = REG0W[n * 132 + kw + tig];
            unsigned int bh1 = REG0W[n * 132 + kw + 4 + tig];
            unsigned int bl0 = REG0W[8448 + n * 132 + kw + tig];
            unsigned int bl1 = REG0W[8448 + n * 132 + kw + 4 + tig];
            mma_bf16(acc, ah, bh0, bh1);
            mma_bf16(acc, ah, bl0, bl1);
            mma_bf16(acc, al, bh0, bh1);
        }
        {
            int ncol = nt8 * 8 + 2 * tig;
            float ip0 = INVP[ncol], ip1 = INVP[ncol + 1];
            #pragma unroll
            for (int half = 0; half < 2; half++) {
                int r = mt * 16 + g + 8 * half;
                float invn = INVN[r];
                LG[r * 65 + ncol]     = acc[2 * half]     * invn * ip0;
                LG[r * 65 + ncol + 1] = acc[2 * half + 1] * invn * ip1;
            }
        }
    }
    __syncthreads();

    // ---- softmax (|logit| <= 1: no max shift) -> split bf16 ATT; warp w: rows 2w,2w+1 ----
    #pragma unroll
    for (int q = 0; q < 2; q++) {
        int r = w * 2 + q;
        float l0 = LG[r * 65 + lane];
        float l1 = LG[r * 65 + lane + 32];
        float e0v = __expf(l0);
        float e1v = __expf(l1);
        float s = warp_sum(e0v + e1v);
        float inv = 1.f / s;
        float a0 = e0v * inv, a1 = e1v * inv;
        __nv_bfloat16 h0 = __float2bfloat16(a0);
        __nv_bfloat16 h1 = __float2bfloat16(a1);
        ATThi16[r * 72 + lane]      = h0;
        ATThi16[r * 72 + lane + 32] = h1;
        ATTlo16[r * 72 + lane]      = __float2bfloat16(a0 - __bfloat162float(h0));
        ATTlo16[r * 72 + lane + 32] = __float2bfloat16(a1 - __bfloat162float(h1));
    }
    // stage PT hi/lo into REG0 via cp.async (all P reads completed at prior barrier)
    {
        const uint4* src = reinterpret_cast<const uint4*>(g_PTb);
        #pragma unroll
        for (int i = tid; i < 4608; i += NTHR) cp_async16(reg0a + i * 16, src + i);
        cp_commit();
    }
    cp_wait0();
    __syncthreads();

    // ---- PF MMA: delta = ATT @ P (64x256, K=64); warp = (wm: m16) x (wn: n32, nt4) ----
    {
        int wm = w & 3;
        int wn = w >> 2;         // 0..7, 32-col groups
        float acc[4][4];
        #pragma unroll
        for (int nt = 0; nt < 4; nt++)
            #pragma unroll
            for (int i = 0; i < 4; i++) acc[nt][i] = 0.f;

        #pragma unroll
        for (int ks = 0; ks < 4; ks++) {
            int kw = ks * 8;
            int rb  = (wm * 16 + g) * 36;
            int rb8 = rb + 8 * 36;
            unsigned int ah[4], al[4];
            ah[0] = ATThiW[rb  + kw + tig];     ah[1] = ATThiW[rb8 + kw + tig];
            ah[2] = ATThiW[rb  + kw + 4 + tig]; ah[3] = ATThiW[rb8 + kw + 4 + tig];
            al[0] = ATTloW[rb  + kw + tig];     al[1] = ATTloW[rb8 + kw + tig];
            al[2] = ATTloW[rb  + kw + 4 + tig]; al[3] = ATTloW[rb8 + kw + 4 + tig];
            #pragma unroll
            for (int nt = 0; nt < 4; nt++) {
                int n = wn * 32 + nt * 8 + g;
                unsigned int bh0 = REG0W[n * 36 + kw + tig];
                unsigned int bh1 = REG0W[n * 36 + kw + 4 + tig];
                unsigned int bl0 = REG0W[9216 + n * 36 + kw + tig];
                unsigned int bl1 = REG0W[9216 + n * 36 + kw + 4 + tig];
                mma_bf16(acc[nt], ah, bh0, bh1);
                mma_bf16(acc[nt], ah, bl0, bl1);
                mma_bf16(acc[nt], al, bh0, bh1);
            }
        }
        __syncthreads();   // all PT reads done; LG consumed long before

        // prefetch gate W chunk 0 (hi-only, K=64) into buf0 (overlaps with PF epilogue)
        {
            const uint4* src = reinterpret_cast<const uint4*>(g_Wt);
            #pragma unroll
            for (int i = tid; i < 2304; i += NTHR) cp_async16(reg0a + i * 16, src + i);
            cp_commit();
        }

        #pragma unroll
        for (int nt = 0; nt < 4; nt++) {
            int wcol = wn * 16 + nt * 4 + tig;
            #pragma unroll
            for (int half = 0; half < 2; half++) {
                int r = wm * 16 + g + 8 * half;
                int widx = r * 132 + wcol;
                __nv_bfloat162 h = *reinterpret_cast<__nv_bfloat162*>(&OhiW[widx]);
                __nv_bfloat162 l = *reinterpret_cast<__nv_bfloat162*>(&OloW[widx]);
                float o0 = __bfloat162float(h.x) + __bfloat162float(l.x);
                float o1 = __bfloat162float(h.y) + __bfloat162float(l.y);
                float p0 = o0 - acc[nt][2 * half];
                float p1 = o1 - acc[nt][2 * half + 1];
                __nv_bfloat16 ph0 = __float2bfloat16(p0);
                __nv_bfloat16 ph1 = __float2bfloat16(p1);
                __nv_bfloat16 pl0 = __float2bfloat16(p0 - __bfloat162float(ph0));
                __nv_bfloat16 pl1 = __float2bfloat16(p1 - __bfloat162float(ph1));
                PFhiW[widx] = pack_bf16x2(ph0, ph1);
                PFloW[widx] = pack_bf16x2(pl0, pl1);
            }
        }
    }

    // ---- gate MMA: Z = PFhi @ Whi (single product); 4 K=64 chunks, double-buffered ----
    {
        int wm = w & 3;
        int wn = w >> 2;

        float acc[4][4];
        #pragma unroll
        for (int nt = 0; nt < 4; nt++)
            #pragma unroll
            for (int i = 0; i < 4; i++) acc[nt][i] = 0.f;

        #pragma unroll
        for (int c = 0; c < 4; c++) {
            cp_wait0();        // chunk c landed
            __syncthreads();   // all warps done with chunk c-1 compute; data visible
            if (c < 3) {
                const uint4* src = reinterpret_cast<const uint4*>(g_Wt) + (c + 1) * 2304;
                unsigned int dsta = reg0a + (((c + 1) & 1) * WT64_WORDS) * 4;
                #pragma unroll
                for (int i = tid; i < 2304; i += NTHR) cp_async16(dsta + i * 16, src + i);
                cp_commit();
            }
            const unsigned int* B = REG0W + (c & 1) * WT64_WORDS;

            #pragma unroll
            for (int ks = 0; ks < 4; ks++) {
                int kw  = c * 32 + ks * 8;
                int lkw = ks * 8;
                int rb  = (wm * 16 + g) * 132;
                int rb8 = rb + 8 * 132;
                unsigned int ah[4];
                ah[0] = PFhiW[rb  + kw + tig];     ah[1] = PFhiW[rb8 + kw + tig];
                ah[2] = PFhiW[rb  + kw + 4 + tig]; ah[3] = PFhiW[rb8 + kw + 4 + tig];
                #pragma unroll
                for (int nt = 0; nt < 4; nt++) {
                    int n = wn * 32 + nt * 8 + g;
                    unsigned int bh0 = B[n * 36 + lkw + tig];
                    unsigned int bh1 = B[n * 36 + lkw + 4 + tig];
                    mma_bf16(acc[nt], ah, bh0, bh1);
                }
            }
        }

        // epilogue: gate + blend + store
        #pragma unroll
        for (int nt = 0; nt < 4; nt++) {
            int ncol = wn * 32 + nt * 8 + 2 * tig;
            int wcol = ncol >> 1;
            #pragma unroll
            for (int half = 0; half < 2; half++) {
                int r = wm * 16 + g + 8 * half;
                int n = base + r;
                if (n >= NN) continue;
                int widx = r * 132 + wcol;
                __nv_bfloat162 oh = *reinterpret_cast<__nv_bfloat162*>(&OhiW[widx]);
                __nv_bfloat162 ol = *reinterpret_cast<__nv_bfloat162*>(&OloW[widx]);
                __nv_bfloat162 ph = *reinterpret_cast<__nv_bfloat162*>(&PFhiW[widx]);
                __nv_bfloat162 pl = *reinterpret_cast<__nv_bfloat162*>(&PFloW[widx]);
                float o0  = __bfloat162float(oh.x) + __bfloat162float(ol.x);
                float o1  = __bfloat162float(oh.y) + __bfloat162float(ol.y);
                float pf0 = __bfloat162float(ph.x) + __bfloat162float(pl.x);
                float pf1 = __bfloat162float(ph.y) + __bfloat162float(pl.y);
                float z0 = acc[nt][2 * half];
                float z1 = acc[nt][2 * half + 1];
                float g0 = 1.f / (1.f + __expf(-z0));
                float g1 = 1.f / (1.f + __expf(-z1));
                float2 res;
                res.x = g0 * o0 + (1.f - g0) * pf0;
                res.y = g1 * o1 + (1.f - g1) * pf1;
                *reinterpret_cast<float2*>(out + (size_t)n * CC + ncol) = res;
            }
        }
    }
}

// ---------------- launch ----------------
extern "C" void kernel_launch(void* const* d_in, const int* in_sizes, int n_in,
                              void* d_out, int out_size) {
    const float* features  = (const float*)d_in[0];
    const float* rel_emb   = (const float*)d_in[1];
    const float* sparse_v  = (const float*)d_in[2];
    const float* attn_k    = (const float*)d_in[3];
    const float* proxy     = (const float*)d_in[4];
    const float* gate_k    = (const float*)d_in[5];
    const int*   adj       = (const int*)d_in[6];
    const int*   sparse_i  = (const int*)d_in[7];
    const int*   neigh     = (const int*)d_in[9];
    float* out = (float*)d_out;

    prep_kernel<<<RR + PX, 128>>>(rel_emb, attn_k, proxy);
    wconv_kernel<<<(49152 + NN + 255) / 256, 256>>>(gate_k, proxy);
    detect_bounds_kernel<<<(EE + 255) / 256, 256>>>(adj);
    agg_kernel<<<(NN * 32 + 255) / 256, 256>>>(features, rel_emb, sparse_v, adj, sparse_i);

    size_t smem = (size_t)SMEM_WORDS * sizeof(float);
    cudaFuncSetAttribute(final_kernel, cudaFuncAttributeMaxDynamicSharedMemorySize, (int)smem);
    final_kernel<<<(NN + TILE - 1) / TILE, NTHR, smem>>>(features, neigh, out);
}